// round 9
// baseline (speedup 1.0000x reference)
#include <cuda_runtime.h>
#include <math.h>
#include <stdint.h>

#define HIDDEN 2048
#define NH 16
#define NKV 4
#define HD 128
#define KVD 512
#define BATCH 2
#define SEQ 2048
#define MTOT (BATCH*SEQ)   // 4096

// ---------------- scratch (static device globals; no allocs allowed) -------
__device__ float g_q [(size_t)MTOT * HIDDEN];
__device__ float g_k [(size_t)MTOT * KVD];
__device__ float g_v [(size_t)MTOT * KVD];
__device__ float g_ao[(size_t)MTOT * HIDDEN];

// int8 dual-digit operands + row scales
__device__ int8_t g_hsH[(size_t)MTOT * HIDDEN];
__device__ int8_t g_hsL[(size_t)MTOT * HIDDEN];
__device__ int8_t g_wqH[(size_t)HIDDEN * HIDDEN];
__device__ int8_t g_wqL[(size_t)HIDDEN * HIDDEN];
__device__ int8_t g_wkH[(size_t)KVD * HIDDEN];
__device__ int8_t g_wkL[(size_t)KVD * HIDDEN];
__device__ int8_t g_wvH[(size_t)KVD * HIDDEN];
__device__ int8_t g_wvL[(size_t)KVD * HIDDEN];
__device__ int8_t g_woH[(size_t)HIDDEN * HIDDEN];
__device__ int8_t g_woL[(size_t)HIDDEN * HIDDEN];
__device__ int8_t g_aoH[(size_t)MTOT * HIDDEN];
__device__ int8_t g_aoL[(size_t)MTOT * HIDDEN];

__device__ float g_sHS[MTOT];
__device__ float g_sWQ[HIDDEN];
__device__ float g_sWK[KVD];
__device__ float g_sWV[KVD];
__device__ float g_sWO[HIDDEN];
__device__ float g_sAO[MTOT];

// ---------------- helpers ---------------------------------------------------
__device__ __forceinline__ uint32_t smem_u32(const void* p) {
    return (uint32_t)__cvta_generic_to_shared(p);
}
__device__ __forceinline__ void cpa16(uint32_t smaddr, const void* g) {
    asm volatile("cp.async.cg.shared.global [%0], [%1], 16;" :: "r"(smaddr), "l"(g));
}
__device__ __forceinline__ void cpa_commit() { asm volatile("cp.async.commit_group;"); }
__device__ __forceinline__ void cpa_wait1()  { asm volatile("cp.async.wait_group 1;"); }
__device__ __forceinline__ void cpa_wait0()  { asm volatile("cp.async.wait_group 0;"); }

__device__ __forceinline__ void ldsm_x4(uint32_t* r, uint32_t addr) {
    asm volatile("ldmatrix.sync.aligned.m8n8.x4.shared.b16 {%0,%1,%2,%3}, [%4];"
                 : "=r"(r[0]), "=r"(r[1]), "=r"(r[2]), "=r"(r[3]) : "r"(addr));
}
__device__ __forceinline__ void mma_s8(int* d, const uint32_t* a, const uint32_t* b) {
    asm volatile(
        "mma.sync.aligned.m16n8k32.row.col.s32.s8.s8.s32 "
        "{%0,%1,%2,%3}, {%4,%5,%6,%7}, {%8,%9}, {%0,%1,%2,%3};"
        : "+r"(d[0]), "+r"(d[1]), "+r"(d[2]), "+r"(d[3])
        : "r"(a[0]), "r"(a[1]), "r"(a[2]), "r"(a[3]), "r"(b[0]), "r"(b[1]));
}

// ---------------- row quantization: fp32 -> 2x int8 digits + scale ----------
// x ~= s * (128*hi + lo), s = amax/16256, hi,lo in int8, |lo| <= 64
__global__ __launch_bounds__(256) void rowquant(
    const float* __restrict__ in, int K,
    int8_t* __restrict__ hi, int8_t* __restrict__ lo,
    float* __restrict__ scale)
{
    const int row = blockIdx.x;
    const int tid = threadIdx.x;
    const float* p = in + (size_t)row * K;

    float m = 0.f;
    for (int i = tid * 4; i < K; i += 1024) {
        float4 v = *(const float4*)(p + i);
        m = fmaxf(m, fmaxf(fmaxf(fabsf(v.x), fabsf(v.y)), fmaxf(fabsf(v.z), fabsf(v.w))));
    }
    __shared__ float red[8];
    #pragma unroll
    for (int o = 16; o > 0; o >>= 1) m = fmaxf(m, __shfl_xor_sync(0xffffffffu, m, o));
    if ((tid & 31) == 0) red[tid >> 5] = m;
    __syncthreads();
    if (tid == 0) {
        float mm = red[0];
        #pragma unroll
        for (int i = 1; i < 8; i++) mm = fmaxf(mm, red[i]);
        red[0] = mm;
        scale[row] = mm / 16256.f;
    }
    __syncthreads();
    const float amax = red[0];
    const float inv = (amax > 0.f) ? (16256.f / amax) : 0.f;

    for (int i = tid * 4; i < K; i += 1024) {
        float4 v = *(const float4*)(p + i);
        int q0 = __float2int_rn(v.x * inv);
        int q1 = __float2int_rn(v.y * inv);
        int q2 = __float2int_rn(v.z * inv);
        int q3 = __float2int_rn(v.w * inv);
        int h0 = (q0 + 64) >> 7, h1 = (q1 + 64) >> 7;
        int h2 = (q2 + 64) >> 7, h3 = (q3 + 64) >> 7;
        char4 hv = make_char4((char)h0, (char)h1, (char)h2, (char)h3);
        char4 lv = make_char4((char)(q0 - (h0 << 7)), (char)(q1 - (h1 << 7)),
                              (char)(q2 - (h2 << 7)), (char)(q3 - (h3 << 7)));
        *(char4*)(hi + (size_t)row * K + i) = hv;
        *(char4*)(lo + (size_t)row * K + i) = lv;
    }
}

// ============================================================================
// int8 dual-digit GEMM: C[M,N] = A[M,K] * W[N,K]^T, K = 2048
// 128x128x32 block tile, 512 threads (16 warps, 4x4), warp tile 32x32
// IMMA m16n8k32: hi*hi -> acc1; hi*lo + lo*hi -> acc2; exact int32 accum.
// C = sA[row]*sB[col] * (16384*acc1 + 128*acc2)
// ============================================================================
#define QLD 48                  // bytes per smem row (32 data + 16 pad)
#define QARR (128 * QLD)        // 6144 bytes
#define QBUF (4 * QARR)         // 24576
#define QSM (2 * QBUF)          // 49152

__global__ __launch_bounds__(512) void gemm_i8(
    const int8_t* __restrict__ Ah_, const int8_t* __restrict__ Al_,
    const int8_t* __restrict__ Bh_, const int8_t* __restrict__ Bl_,
    const float* __restrict__ sA, const float* __restrict__ sB,
    float* __restrict__ C, int N)
{
    extern __shared__ char dsm[];
    const uint32_t base = smem_u32(dsm);

    const int tid  = threadIdx.x;
    const int warp = tid >> 5, lane = tid & 31;
    const int wr = warp & 3, wc = warp >> 2;     // 4x4 warp grid
    const int row0 = blockIdx.y * 128;
    const int col0 = blockIdx.x * 128;

    const char* sAh = (const char*)(Ah_ + (size_t)row0 * HIDDEN);
    const char* sAl = (const char*)(Al_ + (size_t)row0 * HIDDEN);
    const char* sBh = (const char*)(Bh_ + (size_t)col0 * HIDDEN);
    const char* sBl = (const char*)(Bl_ + (size_t)col0 * HIDDEN);

    const int nChunk = HIDDEN / 32;   // 64

    // loader: per array 256 x 16B chunks (128 rows x 2); tid<256 -> A, else B
    const int cid = tid & 255;
    const int rr = cid >> 1, cc = cid & 1;
    auto loadTile = [&](int t, int buf) {
        const uint32_t b0 = base + buf * QBUF;
        const size_t go = (size_t)rr * HIDDEN + t * 32 + cc * 16;
        const uint32_t so = (uint32_t)(rr * QLD + cc * 16);
        if (tid < 256) {
            cpa16(b0 + 0 * QARR + so, sAh + go);
            cpa16(b0 + 1 * QARR + so, sAl + go);
        } else {
            cpa16(b0 + 2 * QARR + so, sBh + go);
            cpa16(b0 + 3 * QARR + so, sBl + go);
        }
        cpa_commit();
    };

    int acc1[2][4][4], acc2[2][4][4];
    #pragma unroll
    for (int mi = 0; mi < 2; mi++)
        #pragma unroll
        for (int ni = 0; ni < 4; ni++)
            #pragma unroll
            for (int r = 0; r < 4; r++) { acc1[mi][ni][r] = 0; acc2[mi][ni][r] = 0; }

    // ldmatrix lane addresses
    // A fragment (16x32 int8): tiles {rows0-7,b0-15}{rows8-15,b0-15}{rows0-7,b16-31}{rows8-15,b16-31}
    const uint32_t aoff = (uint32_t)((wr * 32 + (lane & 7) + ((lane >> 3) & 1) * 8) * QLD
                                     + (lane >> 4) * 16);
    // B fragments (two n-groups of 8 per ldsm): tiles {n0-7,b0-15}{n0-7,b16-31}{n8-15,b0-15}{n8-15,b16-31}
    const uint32_t boff = (uint32_t)((wc * 32 + (lane >> 4) * 8 + (lane & 7)) * QLD
                                     + ((lane >> 3) & 1) * 16);

    loadTile(0, 0);

    for (int t = 0; t < nChunk; t++) {
        const int buf = t & 1;
        if (t + 1 < nChunk) { loadTile(t + 1, buf ^ 1); cpa_wait1(); }
        else                { cpa_wait0(); }
        __syncthreads();

        const uint32_t bo = base + buf * QBUF;

        uint32_t ah[2][4], al[2][4];
        ldsm_x4(ah[0], bo + 0 * QARR + aoff);
        ldsm_x4(ah[1], bo + 0 * QARR + aoff + 16 * QLD);
        ldsm_x4(al[0], bo + 1 * QARR + aoff);
        ldsm_x4(al[1], bo + 1 * QARR + aoff + 16 * QLD);

        uint32_t bh[4][2], bl[4][2], tmp[4];
        ldsm_x4(tmp, bo + 2 * QARR + boff);
        bh[0][0] = tmp[0]; bh[0][1] = tmp[1]; bh[1][0] = tmp[2]; bh[1][1] = tmp[3];
        ldsm_x4(tmp, bo + 2 * QARR + boff + 16 * QLD);
        bh[2][0] = tmp[0]; bh[2][1] = tmp[1]; bh[3][0] = tmp[2]; bh[3][1] = tmp[3];
        ldsm_x4(tmp, bo + 3 * QARR + boff);
        bl[0][0] = tmp[0]; bl[0][1] = tmp[1]; bl[1][0] = tmp[2]; bl[1][1] = tmp[3];
        ldsm_x4(tmp, bo + 3 * QARR + boff + 16 * QLD);
        bl[2][0] = tmp[0]; bl[2][1] = tmp[1]; bl[3][0] = tmp[2]; bl[3][1] = tmp[3];

        #pragma unroll
        for (int mi = 0; mi < 2; mi++)
            #pragma unroll
            for (int ni = 0; ni < 4; ni++) {
                mma_s8(acc1[mi][ni], ah[mi], bh[ni]);   // hi*hi
                mma_s8(acc2[mi][ni], ah[mi], bl[ni]);   // hi*lo
                mma_s8(acc2[mi][ni], al[mi], bh[ni]);   // lo*hi
            }
        __syncthreads();
    }

    // epilogue: dequantize
    #pragma unroll
    for (int mi = 0; mi < 2; mi++) {
        const int row = row0 + wr * 32 + mi * 16 + (lane >> 2);
        const float sa0 = sA[row], sa1 = sA[row + 8];
        #pragma unroll
        for (int ni = 0; ni < 4; ni++) {
            const int col = col0 + wc * 32 + ni * 8 + 2 * (lane & 3);
            const float sb0 = sB[col], sb1 = sB[col + 1];
            float v0 = sa0 * sb0 * (16384.f * (float)acc1[mi][ni][0] + 128.f * (float)acc2[mi][ni][0]);
            float v1 = sa0 * sb1 * (16384.f * (float)acc1[mi][ni][1] + 128.f * (float)acc2[mi][ni][1]);
            float v2 = sa1 * sb0 * (16384.f * (float)acc1[mi][ni][2] + 128.f * (float)acc2[mi][ni][2]);
            float v3 = sa1 * sb1 * (16384.f * (float)acc1[mi][ni][3] + 128.f * (float)acc2[mi][ni][3]);
            *(float2*)(C + (size_t)row * N + col)       = make_float2(v0, v1);
            *(float2*)(C + (size_t)(row + 8) * N + col) = make_float2(v2, v3);
        }
    }
}

// ---------------- RoPE (in-place on q [MTOT,2048] and k [MTOT,512]) --------
__global__ void rope_kernel(float* __restrict__ q, float* __restrict__ k)
{
    const int bs  = blockIdx.x;
    const int pos = bs % SEQ;
    const int i   = threadIdx.x;       // 0..63
    float inv = powf(10000.0f, -(float)i / 64.0f);
    float ang = (float)pos * inv;
    float s, c;
    sincosf(ang, &s, &c);

    #pragma unroll
    for (int h = 0; h < NH; h++) {
        float* p = q + (size_t)bs * HIDDEN + h * HD;
        float a = p[i], b2 = p[i + 64];
        p[i]      = a * c - b2 * s;
        p[i + 64] = b2 * c + a * s;
    }
    #pragma unroll
    for (int h = 0; h < NKV; h++) {
        float* p = k + (size_t)bs * KVD + h * HD;
        float a = p[i], b2 = p[i + 64];
        p[i]      = a * c - b2 * s;
        p[i + 64] = b2 * c + a * s;
    }
}

// ---------------- Flash attention (causal, GQA), fp32 ----------------------
#define BQ 64
#define BKV 64

struct AttnSmem {
    float Qt[HD][BQ];
    float Kt[HD][BKV];
    float V [BKV][HD];
    float P [BQ][BKV];
    float Mx[BQ];
    float L [BQ];
    float Alpha[BQ];
    int   Msk[BKV];
};

__global__ __launch_bounds__(256) void attn_kernel(
    const float* __restrict__ q, const float* __restrict__ k,
    const float* __restrict__ v, const int* __restrict__ amask,
    float* __restrict__ ao)
{
    extern __shared__ char smraw[];
    AttnSmem* S = reinterpret_cast<AttnSmem*>(smraw);

    const int qb = blockIdx.x;
    const int h  = blockIdx.y;
    const int b  = blockIdx.z;
    const int kvh = h / (NH / NKV);
    const int tid = threadIdx.x;
    const int tx = tid & 15, ty = tid >> 4;

    for (int idx = tid; idx < BQ * HD / 4; idx += 256) {
        int r = idx >> 5, dq = idx & 31;
        float4 v4 = *(const float4*)(q + (size_t)(b * SEQ + qb * BQ + r) * HIDDEN + h * HD + dq * 4);
        S->Qt[dq*4+0][r] = v4.x; S->Qt[dq*4+1][r] = v4.y;
        S->Qt[dq*4+2][r] = v4.z; S->Qt[dq*4+3][r] = v4.w;
    }
    if (tid < BQ) { S->Mx[tid] = -1e30f; S->L[tid] = 0.f; }
    __syncthreads();

    float accO[4][8];
    #pragma unroll
    for (int i = 0; i < 4; i++)
        #pragma unroll
        for (int j = 0; j < 8; j++) accO[i][j] = 0.f;

    const float scale = 0.08838834764831845f;
    const int nkv = qb + 1;

    for (int kb = 0; kb < nkv; kb++) {
        for (int idx = tid; idx < BKV * HD / 4; idx += 256) {
            int r = idx >> 5, dq = idx & 31;
            size_t basea = (size_t)(b * SEQ + kb * BKV + r) * KVD + kvh * HD + dq * 4;
            float4 k4 = *(const float4*)(k + basea);
            S->Kt[dq*4+0][r] = k4.x; S->Kt[dq*4+1][r] = k4.y;
            S->Kt[dq*4+2][r] = k4.z; S->Kt[dq*4+3][r] = k4.w;
            *(float4*)&S->V[r][dq*4] = *(const float4*)(v + basea);
        }
        if (tid < BKV) S->Msk[tid] = amask[b * SEQ + kb * BKV + tid];
        __syncthreads();

        float sc[4][4];
        #pragma unroll
        for (int i = 0; i < 4; i++)
            #pragma unroll
            for (int j = 0; j < 4; j++) sc[i][j] = 0.f;

        for (int d = 0; d < HD; d++) {
            float4 rq = *(const float4*)&S->Qt[d][ty * 4];
            float4 rk = *(const float4*)&S->Kt[d][tx * 4];
            float ra[4] = {rq.x, rq.y, rq.z, rq.w};
            float rb[4] = {rk.x, rk.y, rk.z, rk.w};
            #pragma unroll
            for (int i = 0; i < 4; i++)
                #pragma unroll
                for (int j = 0; j < 4; j++)
                    sc[i][j] = fmaf(ra[i], rb[j], sc[i][j]);
        }

        #pragma unroll
        for (int i = 0; i < 4; i++) {
            int rg = qb * BQ + ty * 4 + i;
            #pragma unroll
            for (int j = 0; j < 4; j++) {
                int cl = tx * 4 + j;
                int cg = kb * BKV + cl;
                float val = sc[i][j] * scale;
                if (cg > rg || S->Msk[cl] == 0) val = -1e30f;
                S->P[ty*4+i][cl] = val;
            }
        }
        __syncthreads();

        if (tid < BQ) {
            float mo = S->Mx[tid], m = mo;
            #pragma unroll 8
            for (int c = 0; c < BKV; c++) m = fmaxf(m, S->P[tid][c]);
            float ls = 0.f;
            #pragma unroll 8
            for (int c = 0; c < BKV; c++) {
                float p = __expf(S->P[tid][c] - m);
                S->P[tid][c] = p;
                ls += p;
            }
            float al = __expf(mo - m);
            S->Alpha[tid] = al;
            S->L[tid] = S->L[tid] * al + ls;
            S->Mx[tid] = m;
        }
        __syncthreads();

        float al[4];
        #pragma unroll
        for (int i = 0; i < 4; i++) al[i] = S->Alpha[ty * 4 + i];
        #pragma unroll
        for (int i = 0; i < 4; i++)
            #pragma unroll
            for (int j = 0; j < 8; j++) accO[i][j] *= al[i];

        for (int kk = 0; kk < BKV; kk++) {
            float pv[4];
            #pragma unroll
            for (int i = 0; i < 4; i++) pv[i] = S->P[ty*4+i][kk];
            float4 v0 = *(const float4*)&S->V[kk][tx*8];
            float4 v1 = *(const float4*)&S->V[kk][tx*8+4];
            float vv[8] = {v0.x, v0.y, v0.z, v0.w, v1.x, v1.y, v1.z, v1.w};
            #pragma unroll
            for (int i = 0; i < 4; i++)
                #pragma unroll
                for (int j = 0; j < 8; j++)
                    accO[i][j] = fmaf(pv[i], vv[j], accO[i][j]);
        }
        __syncthreads();
    }

    #pragma unroll
    for (int i = 0; i < 4; i++) {
        int r = ty * 4 + i;
        float invl = 1.0f / S->L[r];
        float4 o0 = make_float4(accO[i][0]*invl, accO[i][1]*invl, accO[i][2]*invl, accO[i][3]*invl);
        float4 o1 = make_float4(accO[i][4]*invl, accO[i][5]*invl, accO[i][6]*invl, accO[i][7]*invl);
        float4* op = (float4*)(ao + (size_t)(b * SEQ + qb * BQ + r) * HIDDEN + h * HD + tx * 8);
        op[0] = o0;
        op[1] = o1;
    }
}

// ---------------- launch ----------------------------------------------------
extern "C" void kernel_launch(void* const* d_in, const int* in_sizes, int n_in,
                              void* d_out, int out_size)
{
    const float* hs    = (const float*)d_in[0];
    const int*   amask = (const int*)  d_in[1];
    const float* wq    = (const float*)d_in[2];
    const float* wk    = (const float*)d_in[3];
    const float* wv    = (const float*)d_in[4];
    const float* wo    = (const float*)d_in[5];
    float* out = (float*)d_out;

    float *dq, *dk, *dv, *dao;
    cudaGetSymbolAddress((void**)&dq,  g_q);
    cudaGetSymbolAddress((void**)&dk,  g_k);
    cudaGetSymbolAddress((void**)&dv,  g_v);
    cudaGetSymbolAddress((void**)&dao, g_ao);

    int8_t *hsH, *hsL, *wqH, *wqL, *wkH, *wkL, *wvH, *wvL, *woH, *woL, *aoH, *aoL;
    cudaGetSymbolAddress((void**)&hsH, g_hsH); cudaGetSymbolAddress((void**)&hsL, g_hsL);
    cudaGetSymbolAddress((void**)&wqH, g_wqH); cudaGetSymbolAddress((void**)&wqL, g_wqL);
    cudaGetSymbolAddress((void**)&wkH, g_wkH); cudaGetSymbolAddress((void**)&wkL, g_wkL);
    cudaGetSymbolAddress((void**)&wvH, g_wvH); cudaGetSymbolAddress((void**)&wvL, g_wvL);
    cudaGetSymbolAddress((void**)&woH, g_woH); cudaGetSymbolAddress((void**)&woL, g_woL);
    cudaGetSymbolAddress((void**)&aoH, g_aoH); cudaGetSymbolAddress((void**)&aoL, g_aoL);

    float *sHS, *sWQ, *sWK, *sWV, *sWO, *sAO;
    cudaGetSymbolAddress((void**)&sHS, g_sHS);
    cudaGetSymbolAddress((void**)&sWQ, g_sWQ);
    cudaGetSymbolAddress((void**)&sWK, g_sWK);
    cudaGetSymbolAddress((void**)&sWV, g_sWV);
    cudaGetSymbolAddress((void**)&sWO, g_sWO);
    cudaGetSymbolAddress((void**)&sAO, g_sAO);

    cudaFuncSetAttribute(gemm_i8, cudaFuncAttributeMaxDynamicSharedMemorySize, QSM);

    // quantize inputs to dual int8 digits
    rowquant<<<MTOT,   256>>>(hs, HIDDEN, hsH, hsL, sHS);
    rowquant<<<HIDDEN, 256>>>(wq, HIDDEN, wqH, wqL, sWQ);
    rowquant<<<KVD,    256>>>(wk, HIDDEN, wkH, wkL, sWK);
    rowquant<<<KVD,    256>>>(wv, HIDDEN, wvH, wvL, sWV);
    rowquant<<<HIDDEN, 256>>>(wo, HIDDEN, woH, woL, sWO);

    // projections (int8 IMMA)
    gemm_i8<<<dim3(HIDDEN / 128, MTOT / 128), 512, QSM>>>(hsH, hsL, wqH, wqL, sHS, sWQ, dq, HIDDEN);
    gemm_i8<<<dim3(KVD    / 128, MTOT / 128), 512, QSM>>>(hsH, hsL, wkH, wkL, sHS, sWK, dk, KVD);
    gemm_i8<<<dim3(KVD    / 128, MTOT / 128), 512, QSM>>>(hsH, hsL, wvH, wvL, sHS, sWV, dv, KVD);

    // RoPE on q and k
    rope_kernel<<<MTOT, 64>>>(dq, dk);

    // flash attention (fp32 SIMT — unchanged)
    size_t smb = sizeof(AttnSmem);
    cudaFuncSetAttribute(attn_kernel, cudaFuncAttributeMaxDynamicSharedMemorySize, (int)smb);
    attn_kernel<<<dim3(SEQ / BQ, NH, BATCH), 256, smb>>>(dq, dk, dv, amask, dao);

    // quantize attention output, then O-projection
    rowquant<<<MTOT, 256>>>(dao, HIDDEN, aoH, aoL, sAO);
    gemm_i8<<<dim3(HIDDEN / 128, MTOT / 128), 512, QSM>>>(aoH, aoL, woH, woL, sAO, sWO, out, HIDDEN);
}

// round 10
// speedup vs baseline: 1.4684x; 1.4684x over previous
#include <cuda_runtime.h>
#include <cuda_fp16.h>
#include <math.h>
#include <stdint.h>

#define HIDDEN 2048
#define NH 16
#define NKV 4
#define HD 128
#define KVD 512
#define BATCH 2
#define SEQ 2048
#define MTOT (BATCH*SEQ)   // 4096

// ---------------- scratch (static device globals; no allocs allowed) -------
__device__ float g_q [(size_t)MTOT * HIDDEN];
__device__ float g_k [(size_t)MTOT * KVD];
__device__ float g_v [(size_t)MTOT * KVD];
__device__ float g_ao[(size_t)MTOT * HIDDEN];

// fp16 (hi, sum) operands: hi = fp16(x); sum = fp16(hi + 64*(x - hi))
__device__ __half g_hsh[(size_t)MTOT * HIDDEN];
__device__ __half g_hss[(size_t)MTOT * HIDDEN];
__device__ __half g_wqh[(size_t)HIDDEN * HIDDEN];
__device__ __half g_wqs[(size_t)HIDDEN * HIDDEN];
__device__ __half g_wkh[(size_t)KVD * HIDDEN];
__device__ __half g_wks[(size_t)KVD * HIDDEN];
__device__ __half g_wvh[(size_t)KVD * HIDDEN];
__device__ __half g_wvs[(size_t)KVD * HIDDEN];
__device__ __half g_woh[(size_t)HIDDEN * HIDDEN];
__device__ __half g_wos[(size_t)HIDDEN * HIDDEN];
__device__ __half g_aoh[(size_t)MTOT * HIDDEN];
__device__ __half g_aos[(size_t)MTOT * HIDDEN];

#define SPLIT_S 64.0f
#define SPLIT_SINV (1.0f / 64.0f)

// ---------------- helpers ---------------------------------------------------
__device__ __forceinline__ uint32_t smem_u32(const void* p) {
    return (uint32_t)__cvta_generic_to_shared(p);
}
__device__ __forceinline__ void cpa16(uint32_t smaddr, const void* g) {
    asm volatile("cp.async.cg.shared.global [%0], [%1], 16;" :: "r"(smaddr), "l"(g));
}
__device__ __forceinline__ void cpa_commit() { asm volatile("cp.async.commit_group;"); }
__device__ __forceinline__ void cpa_wait1()  { asm volatile("cp.async.wait_group 1;"); }
__device__ __forceinline__ void cpa_wait0()  { asm volatile("cp.async.wait_group 0;"); }

__device__ __forceinline__ void ldsm_x4(uint32_t* r, uint32_t addr) {
    asm volatile("ldmatrix.sync.aligned.m8n8.x4.shared.b16 {%0,%1,%2,%3}, [%4];"
                 : "=r"(r[0]), "=r"(r[1]), "=r"(r[2]), "=r"(r[3]) : "r"(addr));
}
__device__ __forceinline__ void mma_f16(float* d, const uint32_t* a, const uint32_t* b) {
    asm volatile(
        "mma.sync.aligned.m16n8k16.row.col.f32.f16.f16.f32 "
        "{%0,%1,%2,%3}, {%4,%5,%6,%7}, {%8,%9}, {%0,%1,%2,%3};"
        : "+f"(d[0]), "+f"(d[1]), "+f"(d[2]), "+f"(d[3])
        : "r"(a[0]), "r"(a[1]), "r"(a[2]), "r"(a[3]), "r"(b[0]), "r"(b[1]));
}

// ---------------- split kernel: fp32 -> (hi, hi + 64*resid) fp16 ------------
__global__ void split_fp16(const float* __restrict__ in,
                           __half* __restrict__ hi,
                           __half* __restrict__ su, int n4)
{
    for (int i = blockIdx.x * blockDim.x + threadIdx.x; i < n4; i += gridDim.x * blockDim.x) {
        float4 x = ((const float4*)in)[i];
        __half h0 = __float2half(x.x), h1 = __float2half(x.y);
        __half h2 = __float2half(x.z), h3 = __float2half(x.w);
        float f0 = __half2float(h0), f1 = __half2float(h1);
        float f2 = __half2float(h2), f3 = __half2float(h3);
        __half s0 = __float2half(fmaf(SPLIT_S, x.x - f0, f0));
        __half s1 = __float2half(fmaf(SPLIT_S, x.y - f1, f1));
        __half s2 = __float2half(fmaf(SPLIT_S, x.z - f2, f2));
        __half s3 = __float2half(fmaf(SPLIT_S, x.w - f3, f3));
        ushort4 hv = make_ushort4(__half_as_ushort(h0), __half_as_ushort(h1),
                                  __half_as_ushort(h2), __half_as_ushort(h3));
        ushort4 sv = make_ushort4(__half_as_ushort(s0), __half_as_ushort(s1),
                                  __half_as_ushort(s2), __half_as_ushort(s3));
        ((ushort4*)hi)[i] = hv;
        ((ushort4*)su)[i] = sv;
    }
}

// ============================================================================
// fp16 2-MMA corrected GEMM: C[M,N] = A[M,K] * W[N,K]^T, K = 2048
// 128x128x32 block tile, 512 threads (16 warps, 4x4), warp tile 32x32
// acc_h += Ah*Bh ; acc_s += As*Bs ; C = acc_h + (acc_s - acc_h)/64
// ============================================================================
#define LDH 40                  // halfs per smem row (32 data + 8 pad)
#define LDB (LDH * 2)           // 80 bytes
#define ARR (128 * LDB)         // 10240 bytes per array
#define BUFB (4 * ARR)          // Ah, As, Bh, Bs
#define GSM (2 * BUFB)          // 81920 double-buffered

__global__ __launch_bounds__(512) void gemm_fp16x2(
    const __half* __restrict__ Ah_, const __half* __restrict__ As_,
    const __half* __restrict__ Bh_, const __half* __restrict__ Bs_,
    float* __restrict__ C, int N)
{
    extern __shared__ char dsm[];
    const uint32_t base = smem_u32(dsm);

    const int tid  = threadIdx.x;
    const int warp = tid >> 5, lane = tid & 31;
    const int wr = warp & 3, wc = warp >> 2;     // 4x4 warp grid
    const int row0 = blockIdx.y * 128;
    const int col0 = blockIdx.x * 128;

    const char* src[4] = {
        (const char*)(Ah_ + (size_t)row0 * HIDDEN),
        (const char*)(As_ + (size_t)row0 * HIDDEN),
        (const char*)(Bh_ + (size_t)col0 * HIDDEN),
        (const char*)(Bs_ + (size_t)col0 * HIDDEN)
    };

    const int nChunk = HIDDEN / 32;   // 64

    const int lr = tid >> 2;          // 0..127 row
    const int lc = tid & 3;           // 16B chunk
    auto loadTile = [&](int t, int buf) {
        #pragma unroll
        for (int a = 0; a < 4; a++) {
            cpa16(base + buf * BUFB + a * ARR + lr * LDB + lc * 16,
                  src[a] + ((size_t)lr * HIDDEN + t * 32) * 2 + lc * 16);
        }
        cpa_commit();
    };

    float acch[2][4][4], accs[2][4][4];
    #pragma unroll
    for (int mi = 0; mi < 2; mi++)
        #pragma unroll
        for (int ni = 0; ni < 4; ni++)
            #pragma unroll
            for (int r = 0; r < 4; r++) { acch[mi][ni][r] = 0.f; accs[mi][ni][r] = 0.f; }

    const uint32_t aoffA = (uint32_t)((wr * 32 + (lane & 15)) * LDB + ((lane >> 4) << 3) * 2);
    const uint32_t aoffB = (uint32_t)((wc * 32 + ((lane >> 4) << 3) + (lane & 7)) * LDB
                                      + (((lane >> 3) & 1) << 3) * 2);

    loadTile(0, 0);

    for (int t = 0; t < nChunk; t++) {
        const int buf = t & 1;
        if (t + 1 < nChunk) { loadTile(t + 1, buf ^ 1); cpa_wait1(); }
        else                { cpa_wait0(); }
        __syncthreads();

        const uint32_t bo = base + buf * BUFB;

        #pragma unroll
        for (int ks = 0; ks < 2; ks++) {
            const uint32_t kb = (uint32_t)(ks * 32);

            uint32_t ah[2][4], as_[2][4];
            ldsm_x4(ah[0],  bo + 0 * ARR + aoffA + kb);
            ldsm_x4(ah[1],  bo + 0 * ARR + aoffA + kb + 16 * LDB);
            ldsm_x4(as_[0], bo + 1 * ARR + aoffA + kb);
            ldsm_x4(as_[1], bo + 1 * ARR + aoffA + kb + 16 * LDB);

            uint32_t bh[4][2], bs[4][2], tmp[4];
            ldsm_x4(tmp, bo + 2 * ARR + aoffB + kb);
            bh[0][0] = tmp[0]; bh[0][1] = tmp[1]; bh[1][0] = tmp[2]; bh[1][1] = tmp[3];
            ldsm_x4(tmp, bo + 2 * ARR + aoffB + kb + 16 * LDB);
            bh[2][0] = tmp[0]; bh[2][1] = tmp[1]; bh[3][0] = tmp[2]; bh[3][1] = tmp[3];
            ldsm_x4(tmp, bo + 3 * ARR + aoffB + kb);
            bs[0][0] = tmp[0]; bs[0][1] = tmp[1]; bs[1][0] = tmp[2]; bs[1][1] = tmp[3];
            ldsm_x4(tmp, bo + 3 * ARR + aoffB + kb + 16 * LDB);
            bs[2][0] = tmp[0]; bs[2][1] = tmp[1]; bs[3][0] = tmp[2]; bs[3][1] = tmp[3];

            #pragma unroll
            for (int mi = 0; mi < 2; mi++)
                #pragma unroll
                for (int ni = 0; ni < 4; ni++) {
                    mma_f16(acch[mi][ni], ah[mi],  bh[ni]);   // hi * hi
                    mma_f16(accs[mi][ni], as_[mi], bs[ni]);   // sum * sum
                }
        }
        __syncthreads();
    }

    // epilogue: C = acc_h + (acc_s - acc_h) / 64
    #pragma unroll
    for (int mi = 0; mi < 2; mi++)
        #pragma unroll
        for (int ni = 0; ni < 4; ni++) {
            const int row = row0 + wr * 32 + mi * 16 + (lane >> 2);
            const int col = col0 + wc * 32 + ni * 8 + 2 * (lane & 3);
            float v0 = acch[mi][ni][0] + (accs[mi][ni][0] - acch[mi][ni][0]) * SPLIT_SINV;
            float v1 = acch[mi][ni][1] + (accs[mi][ni][1] - acch[mi][ni][1]) * SPLIT_SINV;
            float v2 = acch[mi][ni][2] + (accs[mi][ni][2] - acch[mi][ni][2]) * SPLIT_SINV;
            float v3 = acch[mi][ni][3] + (accs[mi][ni][3] - acch[mi][ni][3]) * SPLIT_SINV;
            *(float2*)(C + (size_t)row * N + col)       = make_float2(v0, v1);
            *(float2*)(C + (size_t)(row + 8) * N + col) = make_float2(v2, v3);
        }
}

// ---------------- RoPE (in-place on q [MTOT,2048] and k [MTOT,512]) --------
__global__ void rope_kernel(float* __restrict__ q, float* __restrict__ k)
{
    const int bs  = blockIdx.x;
    const int pos = bs % SEQ;
    const int i   = threadIdx.x;       // 0..63
    float inv = powf(10000.0f, -(float)i / 64.0f);
    float ang = (float)pos * inv;
    float s, c;
    sincosf(ang, &s, &c);

    #pragma unroll
    for (int h = 0; h < NH; h++) {
        float* p = q + (size_t)bs * HIDDEN + h * HD;
        float a = p[i], b2 = p[i + 64];
        p[i]      = a * c - b2 * s;
        p[i + 64] = b2 * c + a * s;
    }
    #pragma unroll
    for (int h = 0; h < NKV; h++) {
        float* p = k + (size_t)bs * KVD + h * HD;
        float a = p[i], b2 = p[i + 64];
        p[i]      = a * c - b2 * s;
        p[i + 64] = b2 * c + a * s;
    }
}

// ---------------- Flash attention (causal, GQA), fp32 ----------------------
#define BQ 64
#define BKV 64

struct AttnSmem {
    float Qt[HD][BQ];
    float Kt[HD][BKV];
    float V [BKV][HD];
    float P [BQ][BKV];
    float Mx[BQ];
    float L [BQ];
    float Alpha[BQ];
    int   Msk[BKV];
};

__global__ __launch_bounds__(256) void attn_kernel(
    const float* __restrict__ q, const float* __restrict__ k,
    const float* __restrict__ v, const int* __restrict__ amask,
    float* __restrict__ ao)
{
    extern __shared__ char smraw[];
    AttnSmem* S = reinterpret_cast<AttnSmem*>(smraw);

    const int qb = blockIdx.x;
    const int h  = blockIdx.y;
    const int b  = blockIdx.z;
    const int kvh = h / (NH / NKV);
    const int tid = threadIdx.x;
    const int tx = tid & 15, ty = tid >> 4;

    for (int idx = tid; idx < BQ * HD / 4; idx += 256) {
        int r = idx >> 5, dq = idx & 31;
        float4 v4 = *(const float4*)(q + (size_t)(b * SEQ + qb * BQ + r) * HIDDEN + h * HD + dq * 4);
        S->Qt[dq*4+0][r] = v4.x; S->Qt[dq*4+1][r] = v4.y;
        S->Qt[dq*4+2][r] = v4.z; S->Qt[dq*4+3][r] = v4.w;
    }
    if (tid < BQ) { S->Mx[tid] = -1e30f; S->L[tid] = 0.f; }
    __syncthreads();

    float accO[4][8];
    #pragma unroll
    for (int i = 0; i < 4; i++)
        #pragma unroll
        for (int j = 0; j < 8; j++) accO[i][j] = 0.f;

    const float scale = 0.08838834764831845f;
    const int nkv = qb + 1;

    for (int kb = 0; kb < nkv; kb++) {
        for (int idx = tid; idx < BKV * HD / 4; idx += 256) {
            int r = idx >> 5, dq = idx & 31;
            size_t basea = (size_t)(b * SEQ + kb * BKV + r) * KVD + kvh * HD + dq * 4;
            float4 k4 = *(const float4*)(k + basea);
            S->Kt[dq*4+0][r] = k4.x; S->Kt[dq*4+1][r] = k4.y;
            S->Kt[dq*4+2][r] = k4.z; S->Kt[dq*4+3][r] = k4.w;
            *(float4*)&S->V[r][dq*4] = *(const float4*)(v + basea);
        }
        if (tid < BKV) S->Msk[tid] = amask[b * SEQ + kb * BKV + tid];
        __syncthreads();

        float sc[4][4];
        #pragma unroll
        for (int i = 0; i < 4; i++)
            #pragma unroll
            for (int j = 0; j < 4; j++) sc[i][j] = 0.f;

        for (int d = 0; d < HD; d++) {
            float4 rq = *(const float4*)&S->Qt[d][ty * 4];
            float4 rk = *(const float4*)&S->Kt[d][tx * 4];
            float ra[4] = {rq.x, rq.y, rq.z, rq.w};
            float rb[4] = {rk.x, rk.y, rk.z, rk.w};
            #pragma unroll
            for (int i = 0; i < 4; i++)
                #pragma unroll
                for (int j = 0; j < 4; j++)
                    sc[i][j] = fmaf(ra[i], rb[j], sc[i][j]);
        }

        #pragma unroll
        for (int i = 0; i < 4; i++) {
            int rg = qb * BQ + ty * 4 + i;
            #pragma unroll
            for (int j = 0; j < 4; j++) {
                int cl = tx * 4 + j;
                int cg = kb * BKV + cl;
                float val = sc[i][j] * scale;
                if (cg > rg || S->Msk[cl] == 0) val = -1e30f;
                S->P[ty*4+i][cl] = val;
            }
        }
        __syncthreads();

        if (tid < BQ) {
            float mo = S->Mx[tid], m = mo;
            #pragma unroll 8
            for (int c = 0; c < BKV; c++) m = fmaxf(m, S->P[tid][c]);
            float ls = 0.f;
            #pragma unroll 8
            for (int c = 0; c < BKV; c++) {
                float p = __expf(S->P[tid][c] - m);
                S->P[tid][c] = p;
                ls += p;
            }
            float al = __expf(mo - m);
            S->Alpha[tid] = al;
            S->L[tid] = S->L[tid] * al + ls;
            S->Mx[tid] = m;
        }
        __syncthreads();

        float al[4];
        #pragma unroll
        for (int i = 0; i < 4; i++) al[i] = S->Alpha[ty * 4 + i];
        #pragma unroll
        for (int i = 0; i < 4; i++)
            #pragma unroll
            for (int j = 0; j < 8; j++) accO[i][j] *= al[i];

        for (int kk = 0; kk < BKV; kk++) {
            float pv[4];
            #pragma unroll
            for (int i = 0; i < 4; i++) pv[i] = S->P[ty*4+i][kk];
            float4 v0 = *(const float4*)&S->V[kk][tx*8];
            float4 v1 = *(const float4*)&S->V[kk][tx*8+4];
            float vv[8] = {v0.x, v0.y, v0.z, v0.w, v1.x, v1.y, v1.z, v1.w};
            #pragma unroll
            for (int i = 0; i < 4; i++)
                #pragma unroll
                for (int j = 0; j < 8; j++)
                    accO[i][j] = fmaf(pv[i], vv[j], accO[i][j]);
        }
        __syncthreads();
    }

    #pragma unroll
    for (int i = 0; i < 4; i++) {
        int r = ty * 4 + i;
        float invl = 1.0f / S->L[r];
        float4 o0 = make_float4(accO[i][0]*invl, accO[i][1]*invl, accO[i][2]*invl, accO[i][3]*invl);
        float4 o1 = make_float4(accO[i][4]*invl, accO[i][5]*invl, accO[i][6]*invl, accO[i][7]*invl);
        float4* op = (float4*)(ao + (size_t)(b * SEQ + qb * BQ + r) * HIDDEN + h * HD + tx * 8);
        op[0] = o0;
        op[1] = o1;
    }
}

// ---------------- launch ----------------------------------------------------
extern "C" void kernel_launch(void* const* d_in, const int* in_sizes, int n_in,
                              void* d_out, int out_size)
{
    const float* hs    = (const float*)d_in[0];
    const int*   amask = (const int*)  d_in[1];
    const float* wq    = (const float*)d_in[2];
    const float* wk    = (const float*)d_in[3];
    const float* wv    = (const float*)d_in[4];
    const float* wo    = (const float*)d_in[5];
    float* out = (float*)d_out;

    float *dq, *dk, *dv, *dao;
    cudaGetSymbolAddress((void**)&dq,  g_q);
    cudaGetSymbolAddress((void**)&dk,  g_k);
    cudaGetSymbolAddress((void**)&dv,  g_v);
    cudaGetSymbolAddress((void**)&dao, g_ao);

    __half *hsh, *hss, *wqh, *wqs, *wkh, *wks, *wvh, *wvs, *woh, *wos, *aoh, *aos;
    cudaGetSymbolAddress((void**)&hsh, g_hsh); cudaGetSymbolAddress((void**)&hss, g_hss);
    cudaGetSymbolAddress((void**)&wqh, g_wqh); cudaGetSymbolAddress((void**)&wqs, g_wqs);
    cudaGetSymbolAddress((void**)&wkh, g_wkh); cudaGetSymbolAddress((void**)&wks, g_wks);
    cudaGetSymbolAddress((void**)&wvh, g_wvh); cudaGetSymbolAddress((void**)&wvs, g_wvs);
    cudaGetSymbolAddress((void**)&woh, g_woh); cudaGetSymbolAddress((void**)&wos, g_wos);
    cudaGetSymbolAddress((void**)&aoh, g_aoh); cudaGetSymbolAddress((void**)&aos, g_aos);

    cudaFuncSetAttribute(gemm_fp16x2, cudaFuncAttributeMaxDynamicSharedMemorySize, GSM);

    // split inputs into fp16 (hi, sum)
    split_fp16<<<1024, 256>>>(hs, hsh, hss, MTOT * HIDDEN / 4);
    split_fp16<<<1024, 256>>>(wq, wqh, wqs, HIDDEN * HIDDEN / 4);
    split_fp16<<<512,  256>>>(wk, wkh, wks, KVD * HIDDEN / 4);
    split_fp16<<<512,  256>>>(wv, wvh, wvs, KVD * HIDDEN / 4);
    split_fp16<<<1024, 256>>>(wo, woh, wos, HIDDEN * HIDDEN / 4);

    // projections (2-MMA corrected fp16 tensor cores)
    gemm_fp16x2<<<dim3(HIDDEN / 128, MTOT / 128), 512, GSM>>>(hsh, hss, wqh, wqs, dq, HIDDEN);
    gemm_fp16x2<<<dim3(KVD    / 128, MTOT / 128), 512, GSM>>>(hsh, hss, wkh, wks, dk, KVD);
    gemm_fp16x2<<<dim3(KVD    / 128, MTOT / 128), 512, GSM>>>(hsh, hss, wvh, wvs, dv, KVD);

    // RoPE on q and k
    rope_kernel<<<MTOT, 64>>>(dq, dk);

    // flash attention (fp32 SIMT — unchanged)
    size_t smb = sizeof(AttnSmem);
    cudaFuncSetAttribute(attn_kernel, cudaFuncAttributeMaxDynamicSharedMemorySize, (int)smb);
    attn_kernel<<<dim3(SEQ / BQ, NH, BATCH), 256, smb>>>(dq, dk, dv, amask, dao);

    // split attention output, then O-projection
    split_fp16<<<1024, 256>>>(dao, aoh, aos, MTOT * HIDDEN / 4);
    gemm_fp16x2<<<dim3(HIDDEN / 128, MTOT / 128), 512, GSM>>>(aoh, aos, woh, wos, out, HIDDEN);
}

// round 11
// speedup vs baseline: 3.6142x; 2.4613x over previous
#include <cuda_runtime.h>
#include <cuda_fp16.h>
#include <math.h>
#include <stdint.h>

#define HIDDEN 2048
#define NH 16
#define NKV 4
#define HD 128
#define KVD 512
#define BATCH 2
#define SEQ 2048
#define MTOT (BATCH*SEQ)   // 4096

// ---------------- scratch (static device globals; no allocs allowed) -------
__device__ float g_q [(size_t)MTOT * HIDDEN];
__device__ float g_k [(size_t)MTOT * KVD];
__device__ float g_v [(size_t)MTOT * KVD];
__device__ float g_ao[(size_t)MTOT * HIDDEN];

// fp16 (hi, sum) operands: hi = fp16(x); sum = fp16(hi + 64*(x - hi))
__device__ __half g_hsh[(size_t)MTOT * HIDDEN];
__device__ __half g_hss[(size_t)MTOT * HIDDEN];
__device__ __half g_wqh[(size_t)HIDDEN * HIDDEN];
__device__ __half g_wqs[(size_t)HIDDEN * HIDDEN];
__device__ __half g_wkh[(size_t)KVD * HIDDEN];
__device__ __half g_wks[(size_t)KVD * HIDDEN];
__device__ __half g_wvh[(size_t)KVD * HIDDEN];
__device__ __half g_wvs[(size_t)KVD * HIDDEN];
__device__ __half g_woh[(size_t)HIDDEN * HIDDEN];
__device__ __half g_wos[(size_t)HIDDEN * HIDDEN];
__device__ __half g_aoh[(size_t)MTOT * HIDDEN];
__device__ __half g_aos[(size_t)MTOT * HIDDEN];

// attention fp16 operands
__device__ __half g_qh [(size_t)MTOT * HIDDEN];
__device__ __half g_qs2[(size_t)MTOT * HIDDEN];
__device__ __half g_kh [(size_t)MTOT * KVD];
__device__ __half g_ks2[(size_t)MTOT * KVD];
__device__ __half g_vth[(size_t)BATCH * NKV * HD * SEQ];
__device__ __half g_vts[(size_t)BATCH * NKV * HD * SEQ];

#define SPLIT_S 64.0f
#define SPLIT_SINV (1.0f / 64.0f)

// ---------------- helpers ---------------------------------------------------
__device__ __forceinline__ uint32_t smem_u32(const void* p) {
    return (uint32_t)__cvta_generic_to_shared(p);
}
__device__ __forceinline__ void cpa16(uint32_t smaddr, const void* g) {
    asm volatile("cp.async.cg.shared.global [%0], [%1], 16;" :: "r"(smaddr), "l"(g));
}
__device__ __forceinline__ void cpa_commit() { asm volatile("cp.async.commit_group;"); }
__device__ __forceinline__ void cpa_wait1()  { asm volatile("cp.async.wait_group 1;"); }
__device__ __forceinline__ void cpa_wait0()  { asm volatile("cp.async.wait_group 0;"); }

__device__ __forceinline__ void ldsm_x4(uint32_t* r, uint32_t addr) {
    asm volatile("ldmatrix.sync.aligned.m8n8.x4.shared.b16 {%0,%1,%2,%3}, [%4];"
                 : "=r"(r[0]), "=r"(r[1]), "=r"(r[2]), "=r"(r[3]) : "r"(addr));
}
__device__ __forceinline__ void mma_f16(float* d, const uint32_t* a, const uint32_t* b) {
    asm volatile(
        "mma.sync.aligned.m16n8k16.row.col.f32.f16.f16.f32 "
        "{%0,%1,%2,%3}, {%4,%5,%6,%7}, {%8,%9}, {%0,%1,%2,%3};"
        : "+f"(d[0]), "+f"(d[1]), "+f"(d[2]), "+f"(d[3])
        : "r"(a[0]), "r"(a[1]), "r"(a[2]), "r"(a[3]), "r"(b[0]), "r"(b[1]));
}
__device__ __forceinline__ uint32_t packh2(float x, float y) {
    __half2 v = __floats2half2_rn(x, y);
    return *reinterpret_cast<uint32_t*>(&v);
}
__device__ __forceinline__ uint32_t packh2s(float x, float y) {
    float hx = __half2float(__float2half(x));
    float hy = __half2float(__float2half(y));
    return packh2(fmaf(SPLIT_S, x - hx, hx), fmaf(SPLIT_S, y - hy, hy));
}

// ---------------- split kernel: fp32 -> (hi, hi + 64*resid) fp16 ------------
__global__ void split_fp16(const float* __restrict__ in,
                           __half* __restrict__ hi,
                           __half* __restrict__ su, int n4)
{
    for (int i = blockIdx.x * blockDim.x + threadIdx.x; i < n4; i += gridDim.x * blockDim.x) {
        float4 x = ((const float4*)in)[i];
        __half h0 = __float2half(x.x), h1 = __float2half(x.y);
        __half h2 = __float2half(x.z), h3 = __float2half(x.w);
        float f0 = __half2float(h0), f1 = __half2float(h1);
        float f2 = __half2float(h2), f3 = __half2float(h3);
        __half s0 = __float2half(fmaf(SPLIT_S, x.x - f0, f0));
        __half s1 = __float2half(fmaf(SPLIT_S, x.y - f1, f1));
        __half s2 = __float2half(fmaf(SPLIT_S, x.z - f2, f2));
        __half s3 = __float2half(fmaf(SPLIT_S, x.w - f3, f3));
        ushort4 hv = make_ushort4(__half_as_ushort(h0), __half_as_ushort(h1),
                                  __half_as_ushort(h2), __half_as_ushort(h3));
        ushort4 sv = make_ushort4(__half_as_ushort(s0), __half_as_ushort(s1),
                                  __half_as_ushort(s2), __half_as_ushort(s3));
        ((ushort4*)hi)[i] = hv;
        ((ushort4*)su)[i] = sv;
    }
}

// ---------------- V transpose + split: [s][kvh*HD+d] -> [bh][d][s] ---------
__global__ void transpose_split_v(const float* __restrict__ v,
                                  __half* __restrict__ vth,
                                  __half* __restrict__ vts)
{
    __shared__ float tile[32][33];
    const int s0 = blockIdx.x * 32, d0 = blockIdx.y * 32;
    const int bh = blockIdx.z;
    const int b = bh / NKV, kvh = bh % NKV;
    const int tx = threadIdx.x, ty = threadIdx.y;   // 32 x 8

    #pragma unroll
    for (int i = 0; i < 4; i++) {
        int s = s0 + ty * 4 + i;
        tile[ty * 4 + i][tx] = v[(size_t)(b * SEQ + s) * KVD + kvh * HD + d0 + tx];
    }
    __syncthreads();
    #pragma unroll
    for (int i = 0; i < 4; i++) {
        int d = d0 + ty * 4 + i;
        float x = tile[tx][ty * 4 + i];
        __half hx = __float2half(x);
        float hf = __half2float(hx);
        __half sx = __float2half(fmaf(SPLIT_S, x - hf, hf));
        size_t o = (size_t)(bh * HD + d) * SEQ + s0 + tx;
        vth[o] = hx;
        vts[o] = sx;
    }
}

// ============================================================================
// fp16 2-MMA corrected GEMM (unchanged from R10 winner)
// ============================================================================
#define LDH 40
#define LDB (LDH * 2)
#define ARR (128 * LDB)
#define BUFB (4 * ARR)
#define GSM (2 * BUFB)

__global__ __launch_bounds__(512) void gemm_fp16x2(
    const __half* __restrict__ Ah_, const __half* __restrict__ As_,
    const __half* __restrict__ Bh_, const __half* __restrict__ Bs_,
    float* __restrict__ C, int N)
{
    extern __shared__ char dsm[];
    const uint32_t base = smem_u32(dsm);

    const int tid  = threadIdx.x;
    const int warp = tid >> 5, lane = tid & 31;
    const int wr = warp & 3, wc = warp >> 2;
    const int row0 = blockIdx.y * 128;
    const int col0 = blockIdx.x * 128;

    const char* src[4] = {
        (const char*)(Ah_ + (size_t)row0 * HIDDEN),
        (const char*)(As_ + (size_t)row0 * HIDDEN),
        (const char*)(Bh_ + (size_t)col0 * HIDDEN),
        (const char*)(Bs_ + (size_t)col0 * HIDDEN)
    };

    const int nChunk = HIDDEN / 32;

    const int lr = tid >> 2;
    const int lc = tid & 3;
    auto loadTile = [&](int t, int buf) {
        #pragma unroll
        for (int a = 0; a < 4; a++) {
            cpa16(base + buf * BUFB + a * ARR + lr * LDB + lc * 16,
                  src[a] + ((size_t)lr * HIDDEN + t * 32) * 2 + lc * 16);
        }
        cpa_commit();
    };

    float acch[2][4][4], accs[2][4][4];
    #pragma unroll
    for (int mi = 0; mi < 2; mi++)
        #pragma unroll
        for (int ni = 0; ni < 4; ni++)
            #pragma unroll
            for (int r = 0; r < 4; r++) { acch[mi][ni][r] = 0.f; accs[mi][ni][r] = 0.f; }

    const uint32_t aoffA = (uint32_t)((wr * 32 + (lane & 15)) * LDB + ((lane >> 4) << 3) * 2);
    const uint32_t aoffB = (uint32_t)((wc * 32 + ((lane >> 4) << 3) + (lane & 7)) * LDB
                                      + (((lane >> 3) & 1) << 3) * 2);

    loadTile(0, 0);

    for (int t = 0; t < nChunk; t++) {
        const int buf = t & 1;
        if (t + 1 < nChunk) { loadTile(t + 1, buf ^ 1); cpa_wait1(); }
        else                { cpa_wait0(); }
        __syncthreads();

        const uint32_t bo = base + buf * BUFB;

        #pragma unroll
        for (int ks = 0; ks < 2; ks++) {
            const uint32_t kb = (uint32_t)(ks * 32);

            uint32_t ah[2][4], as_[2][4];
            ldsm_x4(ah[0],  bo + 0 * ARR + aoffA + kb);
            ldsm_x4(ah[1],  bo + 0 * ARR + aoffA + kb + 16 * LDB);
            ldsm_x4(as_[0], bo + 1 * ARR + aoffA + kb);
            ldsm_x4(as_[1], bo + 1 * ARR + aoffA + kb + 16 * LDB);

            uint32_t bh[4][2], bs[4][2], tmp[4];
            ldsm_x4(tmp, bo + 2 * ARR + aoffB + kb);
            bh[0][0] = tmp[0]; bh[0][1] = tmp[1]; bh[1][0] = tmp[2]; bh[1][1] = tmp[3];
            ldsm_x4(tmp, bo + 2 * ARR + aoffB + kb + 16 * LDB);
            bh[2][0] = tmp[0]; bh[2][1] = tmp[1]; bh[3][0] = tmp[2]; bh[3][1] = tmp[3];
            ldsm_x4(tmp, bo + 3 * ARR + aoffB + kb);
            bs[0][0] = tmp[0]; bs[0][1] = tmp[1]; bs[1][0] = tmp[2]; bs[1][1] = tmp[3];
            ldsm_x4(tmp, bo + 3 * ARR + aoffB + kb + 16 * LDB);
            bs[2][0] = tmp[0]; bs[2][1] = tmp[1]; bs[3][0] = tmp[2]; bs[3][1] = tmp[3];

            #pragma unroll
            for (int mi = 0; mi < 2; mi++)
                #pragma unroll
                for (int ni = 0; ni < 4; ni++) {
                    mma_f16(acch[mi][ni], ah[mi],  bh[ni]);
                    mma_f16(accs[mi][ni], as_[mi], bs[ni]);
                }
        }
        __syncthreads();
    }

    #pragma unroll
    for (int mi = 0; mi < 2; mi++)
        #pragma unroll
        for (int ni = 0; ni < 4; ni++) {
            const int row = row0 + wr * 32 + mi * 16 + (lane >> 2);
            const int col = col0 + wc * 32 + ni * 8 + 2 * (lane & 3);
            float v0 = acch[mi][ni][0] + (accs[mi][ni][0] - acch[mi][ni][0]) * SPLIT_SINV;
            float v1 = acch[mi][ni][1] + (accs[mi][ni][1] - acch[mi][ni][1]) * SPLIT_SINV;
            float v2 = acch[mi][ni][2] + (accs[mi][ni][2] - acch[mi][ni][2]) * SPLIT_SINV;
            float v3 = acch[mi][ni][3] + (accs[mi][ni][3] - acch[mi][ni][3]) * SPLIT_SINV;
            *(float2*)(C + (size_t)row * N + col)       = make_float2(v0, v1);
            *(float2*)(C + (size_t)(row + 8) * N + col) = make_float2(v2, v3);
        }
}

// ---------------- RoPE (in-place on q [MTOT,2048] and k [MTOT,512]) --------
__global__ void rope_kernel(float* __restrict__ q, float* __restrict__ k)
{
    const int bs  = blockIdx.x;
    const int pos = bs % SEQ;
    const int i   = threadIdx.x;       // 0..63
    float inv = powf(10000.0f, -(float)i / 64.0f);
    float ang = (float)pos * inv;
    float s, c;
    sincosf(ang, &s, &c);

    #pragma unroll
    for (int h = 0; h < NH; h++) {
        float* p = q + (size_t)bs * HIDDEN + h * HD;
        float a = p[i], b2 = p[i + 64];
        p[i]      = a * c - b2 * s;
        p[i + 64] = b2 * c + a * s;
    }
    #pragma unroll
    for (int h = 0; h < NKV; h++) {
        float* p = k + (size_t)bs * KVD + h * HD;
        float a = p[i], b2 = p[i + 64];
        p[i]      = a * c - b2 * s;
        p[i + 64] = b2 * c + a * s;
    }
}

// ============================================================================
// MMA flash attention (causal, GQA) — fp16 2-MMA split, FA2 style
// BQ=128 (8 warps x 16 rows), BKV=32, double-buffered K/V
// ============================================================================
#define ATT_BQ 128
#define ATT_BKV 32
#define SQ_LDB 272              // 128 halfs + 16B pad
#define SV_LDB 80               // 32 halfs + 16B pad
#define OFF_QH 0
#define OFF_QS 34816
#define OFF_K  69632            // + (buf*2+split)*8704
#define OFF_VT 104448           // + (buf*2+split)*10240
#define OFF_MSK 145408
#define ATT_SM 153600

__global__ __launch_bounds__(256) void attn_mma(
    const __half* __restrict__ qh,  const __half* __restrict__ qs,
    const __half* __restrict__ kh,  const __half* __restrict__ ks,
    const __half* __restrict__ vth, const __half* __restrict__ vts,
    const int* __restrict__ amask, float* __restrict__ ao)
{
    extern __shared__ char sm[];
    const uint32_t base = smem_u32(sm);
    const int qb = blockIdx.x, h = blockIdx.y, b = blockIdx.z;
    const int kvh = h / (NH / NKV);
    const int bh = b * NKV + kvh;
    const int tid = threadIdx.x, warp = tid >> 5, lane = tid & 31;

    // load Q tile (both splits): 128 rows x 128 halfs
    {
        const size_t qrow0 = (size_t)(b * SEQ + qb * ATT_BQ);
        #pragma unroll
        for (int i = 0; i < 8; i++) {
            int id = tid + i * 256;            // 0..2047
            int r = id >> 4, c = id & 15;
            size_t go = (qrow0 + r) * HIDDEN + (size_t)h * HD + c * 8;
            cpa16(base + OFF_QH + r * SQ_LDB + c * 16, qh + go);
            cpa16(base + OFF_QS + r * SQ_LDB + c * 16, qs + go);
        }
        cpa_commit();
    }
    // mask into smem (plain loads)
    for (int i = tid; i < SEQ; i += 256)
        ((int*)(sm + OFF_MSK))[i] = amask[b * SEQ + i];

    const int nTiles = (qb + 1) * (ATT_BQ / ATT_BKV);   // (qb+1)*4

    auto loadKV = [&](int t, int buf) {
        const int kv0 = t * ATT_BKV;
        #pragma unroll
        for (int i = 0; i < 4; i++) {
            int id = tid + i * 256;            // 0..1023 (K)
            int split = id >> 9, rem = id & 511;
            int r = rem >> 4, c = rem & 15;
            const __half* src = split ? ks : kh;
            cpa16(base + OFF_K + (buf * 2 + split) * 8704 + r * SQ_LDB + c * 16,
                  src + (size_t)(b * SEQ + kv0 + r) * KVD + (size_t)kvh * HD + c * 8);
        }
        #pragma unroll
        for (int i = 0; i < 4; i++) {
            int id = tid + i * 256;            // 0..1023 (V)
            int split = id >> 9, rem = id & 511;
            int r = rem >> 2, c = rem & 3;
            const __half* src = split ? vts : vth;
            cpa16(base + OFF_VT + (buf * 2 + split) * 10240 + r * SV_LDB + c * 16,
                  src + (size_t)(bh * HD + r) * SEQ + kv0 + c * 8);
        }
        cpa_commit();
    };

    float O[16][4];
    #pragma unroll
    for (int i = 0; i < 16; i++)
        #pragma unroll
        for (int r = 0; r < 4; r++) O[i][r] = 0.f;
    float m0 = -1e30f, m1 = -1e30f, l0 = 0.f, l1 = 0.f;

    loadKV(0, 0);
    cpa_wait0();
    __syncthreads();

    const uint32_t aoffQ = (uint32_t)((warp * 16 + (lane & 15)) * SQ_LDB + ((lane >> 4) << 4));
    const uint32_t boffK = (uint32_t)(((lane >> 4) * 8 + (lane & 7)) * SQ_LDB + (((lane >> 3) & 1) << 4));
    const uint32_t boffV = (uint32_t)(((lane >> 4) * 8 + (lane & 7)) * SV_LDB + (((lane >> 3) & 1) << 4));

    const int rowg0 = qb * ATT_BQ + warp * 16 + (lane >> 2);
    const int rowg1 = rowg0 + 8;
    const int* msk = (const int*)(sm + OFF_MSK);
    const float scale = 0.08838834764831845f;

    for (int t = 0; t < nTiles; t++) {
        const int buf = t & 1;
        const int kv0 = t * ATT_BKV;

        __syncthreads();                        // prev compute done, safe to overwrite buf^1
        if (t + 1 < nTiles) { loadKV(t + 1, buf ^ 1); cpa_wait1(); }
        else                { cpa_wait0(); }
        __syncthreads();                        // tile t visible to all

        const uint32_t kb_h = base + OFF_K + (buf * 2 + 0) * 8704;
        const uint32_t kb_s = base + OFF_K + (buf * 2 + 1) * 8704;

        // ---- S = Q K^T (2-MMA split) ----
        float sh[4][4], ss[4][4];
        #pragma unroll
        for (int nt = 0; nt < 4; nt++)
            #pragma unroll
            for (int r = 0; r < 4; r++) { sh[nt][r] = 0.f; ss[nt][r] = 0.f; }

        #pragma unroll
        for (int ksI = 0; ksI < 8; ksI++) {
            uint32_t ah[4], as_[4];
            ldsm_x4(ah,  base + OFF_QH + aoffQ + ksI * 32);
            ldsm_x4(as_, base + OFF_QS + aoffQ + ksI * 32);
            #pragma unroll
            for (int ntp = 0; ntp < 2; ntp++) {
                uint32_t tmp[4];
                ldsm_x4(tmp, kb_h + boffK + ntp * 16 * SQ_LDB + ksI * 32);
                { uint32_t b0[2] = {tmp[0], tmp[1]}, b1[2] = {tmp[2], tmp[3]};
                  mma_f16(sh[ntp * 2],     ah, b0);
                  mma_f16(sh[ntp * 2 + 1], ah, b1); }
                ldsm_x4(tmp, kb_s + boffK + ntp * 16 * SQ_LDB + ksI * 32);
                { uint32_t b0[2] = {tmp[0], tmp[1]}, b1[2] = {tmp[2], tmp[3]};
                  mma_f16(ss[ntp * 2],     as_, b0);
                  mma_f16(ss[ntp * 2 + 1], as_, b1); }
            }
        }

        // fold + scale + mask
        #pragma unroll
        for (int nt = 0; nt < 4; nt++)
            #pragma unroll
            for (int r = 0; r < 4; r++) {
                float s = sh[nt][r] + (ss[nt][r] - sh[nt][r]) * SPLIT_SINV;
                s *= scale;
                int col = kv0 + nt * 8 + 2 * (lane & 3) + (r & 1);
                int row = (r < 2) ? rowg0 : rowg1;
                if (col > row || msk[col] == 0) s = -1e30f;
                sh[nt][r] = s;
            }

        // online softmax (rows: rowg0 for r=0,1; rowg1 for r=2,3)
        float mx0 = m0, mx1 = m1;
        #pragma unroll
        for (int nt = 0; nt < 4; nt++) {
            mx0 = fmaxf(mx0, fmaxf(sh[nt][0], sh[nt][1]));
            mx1 = fmaxf(mx1, fmaxf(sh[nt][2], sh[nt][3]));
        }
        mx0 = fmaxf(mx0, __shfl_xor_sync(0xffffffffu, mx0, 1));
        mx0 = fmaxf(mx0, __shfl_xor_sync(0xffffffffu, mx0, 2));
        mx1 = fmaxf(mx1, __shfl_xor_sync(0xffffffffu, mx1, 1));
        mx1 = fmaxf(mx1, __shfl_xor_sync(0xffffffffu, mx1, 2));

        float sum0 = 0.f, sum1 = 0.f;
        #pragma unroll
        for (int nt = 0; nt < 4; nt++) {
            sh[nt][0] = __expf(sh[nt][0] - mx0);
            sh[nt][1] = __expf(sh[nt][1] - mx0);
            sh[nt][2] = __expf(sh[nt][2] - mx1);
            sh[nt][3] = __expf(sh[nt][3] - mx1);
            sum0 += sh[nt][0] + sh[nt][1];
            sum1 += sh[nt][2] + sh[nt][3];
        }
        sum0 += __shfl_xor_sync(0xffffffffu, sum0, 1);
        sum0 += __shfl_xor_sync(0xffffffffu, sum0, 2);
        sum1 += __shfl_xor_sync(0xffffffffu, sum1, 1);
        sum1 += __shfl_xor_sync(0xffffffffu, sum1, 2);

        float a0 = __expf(m0 - mx0), a1 = __expf(m1 - mx1);
        l0 = l0 * a0 + sum0;
        l1 = l1 * a1 + sum1;
        m0 = mx0; m1 = mx1;

        // rescale O
        #pragma unroll
        for (int i = 0; i < 16; i++) {
            O[i][0] *= a0; O[i][1] *= a0;
            O[i][2] *= a1; O[i][3] *= a1;
        }

        // build P fragments (A-operand layout) hi/sum
        uint32_t pH[2][4], pS[2][4];
        #pragma unroll
        for (int ksI = 0; ksI < 2; ksI++) {
            int t0 = ksI * 2, t1 = t0 + 1;
            pH[ksI][0] = packh2 (sh[t0][0], sh[t0][1]);
            pH[ksI][1] = packh2 (sh[t0][2], sh[t0][3]);
            pH[ksI][2] = packh2 (sh[t1][0], sh[t1][1]);
            pH[ksI][3] = packh2 (sh[t1][2], sh[t1][3]);
            pS[ksI][0] = packh2s(sh[t0][0], sh[t0][1]);
            pS[ksI][1] = packh2s(sh[t0][2], sh[t0][3]);
            pS[ksI][2] = packh2s(sh[t1][0], sh[t1][1]);
            pS[ksI][3] = packh2s(sh[t1][2], sh[t1][3]);
        }

        // ---- O += P V (2-MMA split, fold per n-pair) ----
        const uint32_t vb_h = base + OFF_VT + (buf * 2 + 0) * 10240;
        const uint32_t vb_s = base + OFF_VT + (buf * 2 + 1) * 10240;
        #pragma unroll
        for (int ntp = 0; ntp < 8; ntp++) {
            float th[2][4], ts[2][4];
            #pragma unroll
            for (int j = 0; j < 2; j++)
                #pragma unroll
                for (int r = 0; r < 4; r++) { th[j][r] = 0.f; ts[j][r] = 0.f; }
            #pragma unroll
            for (int ksI = 0; ksI < 2; ksI++) {
                uint32_t tmp[4];
                ldsm_x4(tmp, vb_h + boffV + ntp * 16 * SV_LDB + ksI * 32);
                { uint32_t b0[2] = {tmp[0], tmp[1]}, b1[2] = {tmp[2], tmp[3]};
                  mma_f16(th[0], pH[ksI], b0);
                  mma_f16(th[1], pH[ksI], b1); }
                ldsm_x4(tmp, vb_s + boffV + ntp * 16 * SV_LDB + ksI * 32);
                { uint32_t b0[2] = {tmp[0], tmp[1]}, b1[2] = {tmp[2], tmp[3]};
                  mma_f16(ts[0], pS[ksI], b0);
                  mma_f16(ts[1], pS[ksI], b1); }
            }
            #pragma unroll
            for (int j = 0; j < 2; j++)
                #pragma unroll
                for (int r = 0; r < 4; r++)
                    O[ntp * 2 + j][r] += th[j][r] + (ts[j][r] - th[j][r]) * SPLIT_SINV;
        }
    }

    // epilogue: normalize + store
    const float il0 = 1.f / l0, il1 = 1.f / l1;
    #pragma unroll
    for (int nt = 0; nt < 16; nt++) {
        int col = h * HD + nt * 8 + 2 * (lane & 3);
        size_t o0 = (size_t)(b * SEQ + rowg0) * HIDDEN + col;
        size_t o1 = (size_t)(b * SEQ + rowg1) * HIDDEN + col;
        *(float2*)(ao + o0) = make_float2(O[nt][0] * il0, O[nt][1] * il0);
        *(float2*)(ao + o1) = make_float2(O[nt][2] * il1, O[nt][3] * il1);
    }
}

// ---------------- launch ----------------------------------------------------
extern "C" void kernel_launch(void* const* d_in, const int* in_sizes, int n_in,
                              void* d_out, int out_size)
{
    const float* hs    = (const float*)d_in[0];
    const int*   amask = (const int*)  d_in[1];
    const float* wq    = (const float*)d_in[2];
    const float* wk    = (const float*)d_in[3];
    const float* wv    = (const float*)d_in[4];
    const float* wo    = (const float*)d_in[5];
    float* out = (float*)d_out;

    float *dq, *dk, *dv, *dao;
    cudaGetSymbolAddress((void**)&dq,  g_q);
    cudaGetSymbolAddress((void**)&dk,  g_k);
    cudaGetSymbolAddress((void**)&dv,  g_v);
    cudaGetSymbolAddress((void**)&dao, g_ao);

    __half *hsh, *hss, *wqh, *wqs, *wkh, *wks, *wvh, *wvs, *woh, *wos, *aoh, *aos;
    cudaGetSymbolAddress((void**)&hsh, g_hsh); cudaGetSymbolAddress((void**)&hss, g_hss);
    cudaGetSymbolAddress((void**)&wqh, g_wqh); cudaGetSymbolAddress((void**)&wqs, g_wqs);
    cudaGetSymbolAddress((void**)&wkh, g_wkh); cudaGetSymbolAddress((void**)&wks, g_wks);
    cudaGetSymbolAddress((void**)&wvh, g_wvh); cudaGetSymbolAddress((void**)&wvs, g_wvs);
    cudaGetSymbolAddress((void**)&woh, g_woh); cudaGetSymbolAddress((void**)&wos, g_wos);
    cudaGetSymbolAddress((void**)&aoh, g_aoh); cudaGetSymbolAddress((void**)&aos, g_aos);

    __half *qh, *qs2, *kh, *ks2, *vth, *vts;
    cudaGetSymbolAddress((void**)&qh,  g_qh);  cudaGetSymbolAddress((void**)&qs2, g_qs2);
    cudaGetSymbolAddress((void**)&kh,  g_kh);  cudaGetSymbolAddress((void**)&ks2, g_ks2);
    cudaGetSymbolAddress((void**)&vth, g_vth); cudaGetSymbolAddress((void**)&vts, g_vts);

    cudaFuncSetAttribute(gemm_fp16x2, cudaFuncAttributeMaxDynamicSharedMemorySize, GSM);
    cudaFuncSetAttribute(attn_mma,    cudaFuncAttributeMaxDynamicSharedMemorySize, ATT_SM);

    // split inputs into fp16 (hi, sum)
    split_fp16<<<1024, 256>>>(hs, hsh, hss, MTOT * HIDDEN / 4);
    split_fp16<<<1024, 256>>>(wq, wqh, wqs, HIDDEN * HIDDEN / 4);
    split_fp16<<<512,  256>>>(wk, wkh, wks, KVD * HIDDEN / 4);
    split_fp16<<<512,  256>>>(wv, wvh, wvs, KVD * HIDDEN / 4);
    split_fp16<<<1024, 256>>>(wo, woh, wos, HIDDEN * HIDDEN / 4);

    // projections (2-MMA corrected fp16 tensor cores)
    gemm_fp16x2<<<dim3(HIDDEN / 128, MTOT / 128), 512, GSM>>>(hsh, hss, wqh, wqs, dq, HIDDEN);
    gemm_fp16x2<<<dim3(KVD    / 128, MTOT / 128), 512, GSM>>>(hsh, hss, wkh, wks, dk, KVD);
    gemm_fp16x2<<<dim3(KVD    / 128, MTOT / 128), 512, GSM>>>(hsh, hss, wvh, wvs, dv, KVD);

    // RoPE on q and k
    rope_kernel<<<MTOT, 64>>>(dq, dk);

    // split rope'd Q/K; transpose+split V
    split_fp16<<<1024, 256>>>(dq, qh, qs2, MTOT * HIDDEN / 4);
    split_fp16<<<512,  256>>>(dk, kh, ks2, MTOT * KVD / 4);
    transpose_split_v<<<dim3(SEQ / 32, HD / 32, BATCH * NKV), dim3(32, 8)>>>(dv, vth, vts);

    // MMA flash attention
    attn_mma<<<dim3(SEQ / ATT_BQ, NH, BATCH), 256, ATT_SM>>>(
        qh, qs2, kh, ks2, vth, vts, amask, dao);

    // split attention output, then O-projection
    split_fp16<<<1024, 256>>>(dao, aoh, aos, MTOT * HIDDEN / 4);
    gemm_fp16x2<<<dim3(HIDDEN / 128, MTOT / 128), 512, GSM>>>(aoh, aos, woh, wos, out, HIDDEN);
}

// round 12
// speedup vs baseline: 3.9523x; 1.0935x over previous
#include <cuda_runtime.h>
#include <cuda_fp16.h>
#include <math.h>
#include <stdint.h>

#define HIDDEN 2048
#define NH 16
#define NKV 4
#define HD 128
#define KVD 512
#define BATCH 2
#define SEQ 2048
#define MTOT (BATCH*SEQ)   // 4096
#define KVOUT 1024         // merged K+V projection output width

// ---------------- scratch (static device globals; no allocs allowed) -------
__device__ float g_dq [(size_t)MTOT * HIDDEN];   // Q proj out (fp32, pre-rope)
__device__ float g_dkv[(size_t)MTOT * KVOUT];    // merged K|V proj out (fp32)

// fp16 (hi, sum) operands: hi = fp16(x); sum = fp16(hi + 64*(x - hi))
__device__ __half g_hsh [(size_t)MTOT * HIDDEN];
__device__ __half g_hss [(size_t)MTOT * HIDDEN];
__device__ __half g_wqh [(size_t)HIDDEN * HIDDEN];
__device__ __half g_wqs [(size_t)HIDDEN * HIDDEN];
__device__ __half g_wkvh[(size_t)KVOUT * HIDDEN];
__device__ __half g_wkvs[(size_t)KVOUT * HIDDEN];
__device__ __half g_woh [(size_t)HIDDEN * HIDDEN];
__device__ __half g_wos [(size_t)HIDDEN * HIDDEN];
__device__ __half g_aoh [(size_t)MTOT * HIDDEN];
__device__ __half g_aos [(size_t)MTOT * HIDDEN];

// attention fp16 operands
__device__ __half g_qh [(size_t)MTOT * HIDDEN];
__device__ __half g_qs2[(size_t)MTOT * HIDDEN];
__device__ __half g_kh [(size_t)MTOT * KVD];
__device__ __half g_ks2[(size_t)MTOT * KVD];
__device__ __half g_vth[(size_t)BATCH * NKV * HD * SEQ];
__device__ __half g_vts[(size_t)BATCH * NKV * HD * SEQ];

#define SPLIT_S 64.0f
#define SPLIT_SINV (1.0f / 64.0f)

// ---------------- helpers ---------------------------------------------------
__device__ __forceinline__ uint32_t smem_u32(const void* p) {
    return (uint32_t)__cvta_generic_to_shared(p);
}
__device__ __forceinline__ void cpa16(uint32_t smaddr, const void* g) {
    asm volatile("cp.async.cg.shared.global [%0], [%1], 16;" :: "r"(smaddr), "l"(g));
}
__device__ __forceinline__ void cpa_commit() { asm volatile("cp.async.commit_group;"); }
__device__ __forceinline__ void cpa_wait1()  { asm volatile("cp.async.wait_group 1;"); }
__device__ __forceinline__ void cpa_wait0()  { asm volatile("cp.async.wait_group 0;"); }

__device__ __forceinline__ void ldsm_x4(uint32_t* r, uint32_t addr) {
    asm volatile("ldmatrix.sync.aligned.m8n8.x4.shared.b16 {%0,%1,%2,%3}, [%4];"
                 : "=r"(r[0]), "=r"(r[1]), "=r"(r[2]), "=r"(r[3]) : "r"(addr));
}
__device__ __forceinline__ void mma_f16(float* d, const uint32_t* a, const uint32_t* b) {
    asm volatile(
        "mma.sync.aligned.m16n8k16.row.col.f32.f16.f16.f32 "
        "{%0,%1,%2,%3}, {%4,%5,%6,%7}, {%8,%9}, {%0,%1,%2,%3};"
        : "+f"(d[0]), "+f"(d[1]), "+f"(d[2]), "+f"(d[3])
        : "r"(a[0]), "r"(a[1]), "r"(a[2]), "r"(a[3]), "r"(b[0]), "r"(b[1]));
}
__device__ __forceinline__ uint32_t packh2(float x, float y) {
    __half2 v = __floats2half2_rn(x, y);
    return *reinterpret_cast<uint32_t*>(&v);
}
__device__ __forceinline__ uint32_t packh2s(float x, float y) {
    float hx = __half2float(__float2half(x));
    float hy = __half2float(__float2half(y));
    return packh2(fmaf(SPLIT_S, x - hx, hx), fmaf(SPLIT_S, y - hy, hy));
}
__device__ __forceinline__ void split1(float x, __half& h, __half& s) {
    h = __float2half(x);
    float hf = __half2float(h);
    s = __float2half(fmaf(SPLIT_S, x - hf, hf));
}

// ---------------- split kernel: fp32 -> (hi, hi + 64*resid) fp16 ------------
__global__ void split_fp16(const float* __restrict__ in,
                           __half* __restrict__ hi,
                           __half* __restrict__ su, int n4)
{
    for (int i = blockIdx.x * blockDim.x + threadIdx.x; i < n4; i += gridDim.x * blockDim.x) {
        float4 x = ((const float4*)in)[i];
        __half h0, h1, h2, h3, s0, s1, s2, s3;
        split1(x.x, h0, s0); split1(x.y, h1, s1);
        split1(x.z, h2, s2); split1(x.w, h3, s3);
        ushort4 hv = make_ushort4(__half_as_ushort(h0), __half_as_ushort(h1),
                                  __half_as_ushort(h2), __half_as_ushort(h3));
        ushort4 sv = make_ushort4(__half_as_ushort(s0), __half_as_ushort(s1),
                                  __half_as_ushort(s2), __half_as_ushort(s3));
        ((ushort4*)hi)[i] = hv;
        ((ushort4*)su)[i] = sv;
    }
}

// ---------------- fused RoPE + split: fp32 q/dkv -> fp16 hi/sum -------------
__global__ void rope_split(const float* __restrict__ q, const float* __restrict__ dkv,
                           __half* __restrict__ qh, __half* __restrict__ qs,
                           __half* __restrict__ kh, __half* __restrict__ ks)
{
    const int bs  = blockIdx.x;
    const int pos = bs % SEQ;
    const int i   = threadIdx.x;       // 0..63 (pair index)
    float inv = powf(10000.0f, -(float)i / 64.0f);
    float ang = (float)pos * inv;
    float s, c;
    sincosf(ang, &s, &c);

    #pragma unroll
    for (int h = 0; h < NH; h++) {
        const float* p = q + (size_t)bs * HIDDEN + h * HD;
        float a = p[i], b2 = p[i + 64];
        float r0 = a * c - b2 * s;
        float r1 = b2 * c + a * s;
        __half h0, s0, h1, s1;
        split1(r0, h0, s0); split1(r1, h1, s1);
        size_t o = (size_t)bs * HIDDEN + h * HD + i;
        qh[o] = h0; qs[o] = s0;
        qh[o + 64] = h1; qs[o + 64] = s1;
    }
    #pragma unroll
    for (int h = 0; h < NKV; h++) {
        const float* p = dkv + (size_t)bs * KVOUT + h * HD;   // K part: cols [0,512)
        float a = p[i], b2 = p[i + 64];
        float r0 = a * c - b2 * s;
        float r1 = b2 * c + a * s;
        __half h0, s0, h1, s1;
        split1(r0, h0, s0); split1(r1, h1, s1);
        size_t o = (size_t)bs * KVD + h * HD + i;
        kh[o] = h0; ks[o] = s0;
        kh[o + 64] = h1; ks[o + 64] = s1;
    }
}

// ---------------- V transpose + split: dkv [s][512+kvh*HD+d] -> [bh][d][s] --
__global__ void transpose_split_v(const float* __restrict__ dkv,
                                  __half* __restrict__ vth,
                                  __half* __restrict__ vts)
{
    __shared__ float tile[32][33];
    const int s0 = blockIdx.x * 32, d0 = blockIdx.y * 32;
    const int bh = blockIdx.z;
    const int b = bh / NKV, kvh = bh % NKV;
    const int tx = threadIdx.x, ty = threadIdx.y;   // 32 x 8

    #pragma unroll
    for (int i = 0; i < 4; i++) {
        int s = s0 + ty * 4 + i;
        tile[ty * 4 + i][tx] = dkv[(size_t)(b * SEQ + s) * KVOUT + KVD + kvh * HD + d0 + tx];
    }
    __syncthreads();
    #pragma unroll
    for (int i = 0; i < 4; i++) {
        int d = d0 + ty * 4 + i;
        float x = tile[tx][ty * 4 + i];
        __half hx, sx;
        split1(x, hx, sx);
        size_t o = (size_t)(bh * HD + d) * SEQ + s0 + tx;
        vth[o] = hx;
        vts[o] = sx;
    }
}

// ============================================================================
// fp16 2-MMA corrected GEMM (R10 winner, unchanged)
// ============================================================================
#define LDH 40
#define LDB (LDH * 2)
#define ARR (128 * LDB)
#define BUFB (4 * ARR)
#define GSM (2 * BUFB)

__global__ __launch_bounds__(512) void gemm_fp16x2(
    const __half* __restrict__ Ah_, const __half* __restrict__ As_,
    const __half* __restrict__ Bh_, const __half* __restrict__ Bs_,
    float* __restrict__ C, int N)
{
    extern __shared__ char dsm[];
    const uint32_t base = smem_u32(dsm);

    const int tid  = threadIdx.x;
    const int warp = tid >> 5, lane = tid & 31;
    const int wr = warp & 3, wc = warp >> 2;
    const int row0 = blockIdx.y * 128;
    const int col0 = blockIdx.x * 128;

    const char* src[4] = {
        (const char*)(Ah_ + (size_t)row0 * HIDDEN),
        (const char*)(As_ + (size_t)row0 * HIDDEN),
        (const char*)(Bh_ + (size_t)col0 * HIDDEN),
        (const char*)(Bs_ + (size_t)col0 * HIDDEN)
    };

    const int nChunk = HIDDEN / 32;

    const int lr = tid >> 2;
    const int lc = tid & 3;
    auto loadTile = [&](int t, int buf) {
        #pragma unroll
        for (int a = 0; a < 4; a++) {
            cpa16(base + buf * BUFB + a * ARR + lr * LDB + lc * 16,
                  src[a] + ((size_t)lr * HIDDEN + t * 32) * 2 + lc * 16);
        }
        cpa_commit();
    };

    float acch[2][4][4], accs[2][4][4];
    #pragma unroll
    for (int mi = 0; mi < 2; mi++)
        #pragma unroll
        for (int ni = 0; ni < 4; ni++)
            #pragma unroll
            for (int r = 0; r < 4; r++) { acch[mi][ni][r] = 0.f; accs[mi][ni][r] = 0.f; }

    const uint32_t aoffA = (uint32_t)((wr * 32 + (lane & 15)) * LDB + ((lane >> 4) << 3) * 2);
    const uint32_t aoffB = (uint32_t)((wc * 32 + ((lane >> 4) << 3) + (lane & 7)) * LDB
                                      + (((lane >> 3) & 1) << 3) * 2);

    loadTile(0, 0);

    for (int t = 0; t < nChunk; t++) {
        const int buf = t & 1;
        if (t + 1 < nChunk) { loadTile(t + 1, buf ^ 1); cpa_wait1(); }
        else                { cpa_wait0(); }
        __syncthreads();

        const uint32_t bo = base + buf * BUFB;

        #pragma unroll
        for (int ks = 0; ks < 2; ks++) {
            const uint32_t kb = (uint32_t)(ks * 32);

            uint32_t ah[2][4], as_[2][4];
            ldsm_x4(ah[0],  bo + 0 * ARR + aoffA + kb);
            ldsm_x4(ah[1],  bo + 0 * ARR + aoffA + kb + 16 * LDB);
            ldsm_x4(as_[0], bo + 1 * ARR + aoffA + kb);
            ldsm_x4(as_[1], bo + 1 * ARR + aoffA + kb + 16 * LDB);

            uint32_t bh[4][2], bs[4][2], tmp[4];
            ldsm_x4(tmp, bo + 2 * ARR + aoffB + kb);
            bh[0][0] = tmp[0]; bh[0][1] = tmp[1]; bh[1][0] = tmp[2]; bh[1][1] = tmp[3];
            ldsm_x4(tmp, bo + 2 * ARR + aoffB + kb + 16 * LDB);
            bh[2][0] = tmp[0]; bh[2][1] = tmp[1]; bh[3][0] = tmp[2]; bh[3][1] = tmp[3];
            ldsm_x4(tmp, bo + 3 * ARR + aoffB + kb);
            bs[0][0] = tmp[0]; bs[0][1] = tmp[1]; bs[1][0] = tmp[2]; bs[1][1] = tmp[3];
            ldsm_x4(tmp, bo + 3 * ARR + aoffB + kb + 16 * LDB);
            bs[2][0] = tmp[0]; bs[2][1] = tmp[1]; bs[3][0] = tmp[2]; bs[3][1] = tmp[3];

            #pragma unroll
            for (int mi = 0; mi < 2; mi++)
                #pragma unroll
                for (int ni = 0; ni < 4; ni++) {
                    mma_f16(acch[mi][ni], ah[mi],  bh[ni]);
                    mma_f16(accs[mi][ni], as_[mi], bs[ni]);
                }
        }
        __syncthreads();
    }

    #pragma unroll
    for (int mi = 0; mi < 2; mi++)
        #pragma unroll
        for (int ni = 0; ni < 4; ni++) {
            const int row = row0 + wr * 32 + mi * 16 + (lane >> 2);
            const int col = col0 + wc * 32 + ni * 8 + 2 * (lane & 3);
            float v0 = acch[mi][ni][0] + (accs[mi][ni][0] - acch[mi][ni][0]) * SPLIT_SINV;
            float v1 = acch[mi][ni][1] + (accs[mi][ni][1] - acch[mi][ni][1]) * SPLIT_SINV;
            float v2 = acch[mi][ni][2] + (accs[mi][ni][2] - acch[mi][ni][2]) * SPLIT_SINV;
            float v3 = acch[mi][ni][3] + (accs[mi][ni][3] - acch[mi][ni][3]) * SPLIT_SINV;
            *(float2*)(C + (size_t)row * N + col)       = make_float2(v0, v1);
            *(float2*)(C + (size_t)(row + 8) * N + col) = make_float2(v2, v3);
        }
}

// ============================================================================
// Persistent MMA flash attention (causal, GQA) — fp16 2-MMA split
// 148 persistent CTAs; items (qb,h,b) sorted by descending qb, serpentine.
// Writes fp16 hi/sum output directly (fused split).
// ============================================================================
#define ATT_BQ 128
#define ATT_BKV 32
#define ATT_GRID 148
#define N_ITEMS 512             // 16 qb x 16 h x 2 b
#define SQ_LDB 272              // 128 halfs + 16B pad
#define SV_LDB 80               // 32 halfs + 16B pad
#define OFF_QH 0
#define OFF_QS 34816
#define OFF_K  69632            // + (buf*2+split)*8704
#define OFF_VT 104448           // + (buf*2+split)*10240
#define OFF_MSK 145408
#define ATT_SM 153600

__global__ __launch_bounds__(256) void attn_mma(
    const __half* __restrict__ qh,  const __half* __restrict__ qs,
    const __half* __restrict__ kh,  const __half* __restrict__ ks,
    const __half* __restrict__ vth, const __half* __restrict__ vts,
    const int* __restrict__ amask,
    __half* __restrict__ aoh, __half* __restrict__ aos)
{
    extern __shared__ char sm[];
    const uint32_t base = smem_u32(sm);
    const int cta = blockIdx.x;
    const int tid = threadIdx.x, warp = tid >> 5, lane = tid & 31;
    const float scale = 0.08838834764831845f;

    const uint32_t aoffQ = (uint32_t)((warp * 16 + (lane & 15)) * SQ_LDB + ((lane >> 4) << 4));
    const uint32_t boffK = (uint32_t)(((lane >> 4) * 8 + (lane & 7)) * SQ_LDB + (((lane >> 3) & 1) << 4));
    const uint32_t boffV = (uint32_t)(((lane >> 4) * 8 + (lane & 7)) * SV_LDB + (((lane >> 3) & 1) << 4));
    const int* msk = (const int*)(sm + OFF_MSK);

    for (int p = 0; p < (N_ITEMS + ATT_GRID - 1) / ATT_GRID; p++) {
        const int w = p * ATT_GRID + ((p & 1) ? (ATT_GRID - 1 - cta) : cta);
        if (w >= N_ITEMS) continue;
        const int qb = 15 - (w >> 5);          // descending-qb order
        const int rem = w & 31;
        const int h = rem >> 1;
        const int b = rem & 1;
        const int kvh = h / (NH / NKV);
        const int bh = b * NKV + kvh;

        __syncthreads();   // previous item's smem consumers done

        // load Q tile (both splits): 128 rows x 128 halfs
        {
            const size_t qrow0 = (size_t)(b * SEQ + qb * ATT_BQ);
            #pragma unroll
            for (int i = 0; i < 8; i++) {
                int id = tid + i * 256;
                int r = id >> 4, c = id & 15;
                size_t go = (qrow0 + r) * HIDDEN + (size_t)h * HD + c * 8;
                cpa16(base + OFF_QH + r * SQ_LDB + c * 16, qh + go);
                cpa16(base + OFF_QS + r * SQ_LDB + c * 16, qs + go);
            }
            cpa_commit();
        }
        // mask into smem (only needed prefix)
        const int mlen = (qb + 1) * ATT_BQ;
        for (int i = tid; i < mlen; i += 256)
            ((int*)(sm + OFF_MSK))[i] = amask[b * SEQ + i];

        const int nTiles = (qb + 1) * (ATT_BQ / ATT_BKV);

        auto loadKV = [&](int t, int buf) {
            const int kv0 = t * ATT_BKV;
            #pragma unroll
            for (int i = 0; i < 4; i++) {
                int id = tid + i * 256;
                int split = id >> 9, rem2 = id & 511;
                int r = rem2 >> 4, c = rem2 & 15;
                const __half* src = split ? ks : kh;
                cpa16(base + OFF_K + (buf * 2 + split) * 8704 + r * SQ_LDB + c * 16,
                      src + (size_t)(b * SEQ + kv0 + r) * KVD + (size_t)kvh * HD + c * 8);
            }
            #pragma unroll
            for (int i = 0; i < 4; i++) {
                int id = tid + i * 256;
                int split = id >> 9, rem2 = id & 511;
                int r = rem2 >> 2, c = rem2 & 3;
                const __half* src = split ? vts : vth;
                cpa16(base + OFF_VT + (buf * 2 + split) * 10240 + r * SV_LDB + c * 16,
                      src + (size_t)(bh * HD + r) * SEQ + kv0 + c * 8);
            }
            cpa_commit();
        };

        float O[16][4];
        #pragma unroll
        for (int i = 0; i < 16; i++)
            #pragma unroll
            for (int r = 0; r < 4; r++) O[i][r] = 0.f;
        float m0 = -1e30f, m1 = -1e30f, l0 = 0.f, l1 = 0.f;

        loadKV(0, 0);
        cpa_wait0();
        __syncthreads();

        const int rowg0 = qb * ATT_BQ + warp * 16 + (lane >> 2);
        const int rowg1 = rowg0 + 8;

        for (int t = 0; t < nTiles; t++) {
            const int buf = t & 1;
            const int kv0 = t * ATT_BKV;

            __syncthreads();
            if (t + 1 < nTiles) { loadKV(t + 1, buf ^ 1); cpa_wait1(); }
            else                { cpa_wait0(); }
            __syncthreads();

            const uint32_t kb_h = base + OFF_K + (buf * 2 + 0) * 8704;
            const uint32_t kb_s = base + OFF_K + (buf * 2 + 1) * 8704;

            // ---- S = Q K^T (2-MMA split) ----
            float sh[4][4], ss[4][4];
            #pragma unroll
            for (int nt = 0; nt < 4; nt++)
                #pragma unroll
                for (int r = 0; r < 4; r++) { sh[nt][r] = 0.f; ss[nt][r] = 0.f; }

            #pragma unroll
            for (int ksI = 0; ksI < 8; ksI++) {
                uint32_t ah[4], as_[4];
                ldsm_x4(ah,  base + OFF_QH + aoffQ + ksI * 32);
                ldsm_x4(as_, base + OFF_QS + aoffQ + ksI * 32);
                #pragma unroll
                for (int ntp = 0; ntp < 2; ntp++) {
                    uint32_t tmp[4];
                    ldsm_x4(tmp, kb_h + boffK + ntp * 16 * SQ_LDB + ksI * 32);
                    { uint32_t b0[2] = {tmp[0], tmp[1]}, b1[2] = {tmp[2], tmp[3]};
                      mma_f16(sh[ntp * 2],     ah, b0);
                      mma_f16(sh[ntp * 2 + 1], ah, b1); }
                    ldsm_x4(tmp, kb_s + boffK + ntp * 16 * SQ_LDB + ksI * 32);
                    { uint32_t b0[2] = {tmp[0], tmp[1]}, b1[2] = {tmp[2], tmp[3]};
                      mma_f16(ss[ntp * 2],     as_, b0);
                      mma_f16(ss[ntp * 2 + 1], as_, b1); }
                }
            }

            // fold + scale + mask
            #pragma unroll
            for (int nt = 0; nt < 4; nt++)
                #pragma unroll
                for (int r = 0; r < 4; r++) {
                    float s = sh[nt][r] + (ss[nt][r] - sh[nt][r]) * SPLIT_SINV;
                    s *= scale;
                    int col = kv0 + nt * 8 + 2 * (lane & 3) + (r & 1);
                    int row = (r < 2) ? rowg0 : rowg1;
                    if (col > row || msk[col] == 0) s = -1e30f;
                    sh[nt][r] = s;
                }

            // online softmax
            float mx0 = m0, mx1 = m1;
            #pragma unroll
            for (int nt = 0; nt < 4; nt++) {
                mx0 = fmaxf(mx0, fmaxf(sh[nt][0], sh[nt][1]));
                mx1 = fmaxf(mx1, fmaxf(sh[nt][2], sh[nt][3]));
            }
            mx0 = fmaxf(mx0, __shfl_xor_sync(0xffffffffu, mx0, 1));
            mx0 = fmaxf(mx0, __shfl_xor_sync(0xffffffffu, mx0, 2));
            mx1 = fmaxf(mx1, __shfl_xor_sync(0xffffffffu, mx1, 1));
            mx1 = fmaxf(mx1, __shfl_xor_sync(0xffffffffu, mx1, 2));

            float sum0 = 0.f, sum1 = 0.f;
            #pragma unroll
            for (int nt = 0; nt < 4; nt++) {
                sh[nt][0] = __expf(sh[nt][0] - mx0);
                sh[nt][1] = __expf(sh[nt][1] - mx0);
                sh[nt][2] = __expf(sh[nt][2] - mx1);
                sh[nt][3] = __expf(sh[nt][3] - mx1);
                sum0 += sh[nt][0] + sh[nt][1];
                sum1 += sh[nt][2] + sh[nt][3];
            }
            sum0 += __shfl_xor_sync(0xffffffffu, sum0, 1);
            sum0 += __shfl_xor_sync(0xffffffffu, sum0, 2);
            sum1 += __shfl_xor_sync(0xffffffffu, sum1, 1);
            sum1 += __shfl_xor_sync(0xffffffffu, sum1, 2);

            float a0 = __expf(m0 - mx0), a1 = __expf(m1 - mx1);
            l0 = l0 * a0 + sum0;
            l1 = l1 * a1 + sum1;
            m0 = mx0; m1 = mx1;

            #pragma unroll
            for (int i = 0; i < 16; i++) {
                O[i][0] *= a0; O[i][1] *= a0;
                O[i][2] *= a1; O[i][3] *= a1;
            }

            // P fragments hi/sum
            uint32_t pH[2][4], pS[2][4];
            #pragma unroll
            for (int ksI = 0; ksI < 2; ksI++) {
                int t0 = ksI * 2, t1 = t0 + 1;
                pH[ksI][0] = packh2 (sh[t0][0], sh[t0][1]);
                pH[ksI][1] = packh2 (sh[t0][2], sh[t0][3]);
                pH[ksI][2] = packh2 (sh[t1][0], sh[t1][1]);
                pH[ksI][3] = packh2 (sh[t1][2], sh[t1][3]);
                pS[ksI][0] = packh2s(sh[t0][0], sh[t0][1]);
                pS[ksI][1] = packh2s(sh[t0][2], sh[t0][3]);
                pS[ksI][2] = packh2s(sh[t1][0], sh[t1][1]);
                pS[ksI][3] = packh2s(sh[t1][2], sh[t1][3]);
            }

            // ---- O += P V ----
            const uint32_t vb_h = base + OFF_VT + (buf * 2 + 0) * 10240;
            const uint32_t vb_s = base + OFF_VT + (buf * 2 + 1) * 10240;
            #pragma unroll
            for (int ntp = 0; ntp < 8; ntp++) {
                float th[2][4], ts[2][4];
                #pragma unroll
                for (int j = 0; j < 2; j++)
                    #pragma unroll
                    for (int r = 0; r < 4; r++) { th[j][r] = 0.f; ts[j][r] = 0.f; }
                #pragma unroll
                for (int ksI = 0; ksI < 2; ksI++) {
                    uint32_t tmp[4];
                    ldsm_x4(tmp, vb_h + boffV + ntp * 16 * SV_LDB + ksI * 32);
                    { uint32_t b0[2] = {tmp[0], tmp[1]}, b1[2] = {tmp[2], tmp[3]};
                      mma_f16(th[0], pH[ksI], b0);
                      mma_f16(th[1], pH[ksI], b1); }
                    ldsm_x4(tmp, vb_s + boffV + ntp * 16 * SV_LDB + ksI * 32);
                    { uint32_t b0[2] = {tmp[0], tmp[1]}, b1[2] = {tmp[2], tmp[3]};
                      mma_f16(ts[0], pS[ksI], b0);
                      mma_f16(ts[1], pS[ksI], b1); }
                }
                #pragma unroll
                for (int j = 0; j < 2; j++)
                    #pragma unroll
                    for (int r = 0; r < 4; r++)
                        O[ntp * 2 + j][r] += th[j][r] + (ts[j][r] - th[j][r]) * SPLIT_SINV;
            }
        }

        // epilogue: normalize + fused split to fp16 hi/sum
        const float il0 = 1.f / l0, il1 = 1.f / l1;
        #pragma unroll
        for (int nt = 0; nt < 16; nt++) {
            int col = h * HD + nt * 8 + 2 * (lane & 3);
            size_t o0 = (size_t)(b * SEQ + rowg0) * HIDDEN + col;
            size_t o1 = (size_t)(b * SEQ + rowg1) * HIDDEN + col;
            float x0 = O[nt][0] * il0, x1 = O[nt][1] * il0;
            float x2 = O[nt][2] * il1, x3 = O[nt][3] * il1;
            uint32_t h01 = packh2 (x0, x1), s01 = packh2s(x0, x1);
            uint32_t h23 = packh2 (x2, x3), s23 = packh2s(x2, x3);
            *(uint32_t*)(aoh + o0) = h01;
            *(uint32_t*)(aos + o0) = s01;
            *(uint32_t*)(aoh + o1) = h23;
            *(uint32_t*)(aos + o1) = s23;
        }
    }
}

// ---------------- launch ----------------------------------------------------
extern "C" void kernel_launch(void* const* d_in, const int* in_sizes, int n_in,
                              void* d_out, int out_size)
{
    const float* hs    = (const float*)d_in[0];
    const int*   amask = (const int*)  d_in[1];
    const float* wq    = (const float*)d_in[2];
    const float* wk    = (const float*)d_in[3];
    const float* wv    = (const float*)d_in[4];
    const float* wo    = (const float*)d_in[5];
    float* out = (float*)d_out;

    float *dq, *dkv;
    cudaGetSymbolAddress((void**)&dq,  g_dq);
    cudaGetSymbolAddress((void**)&dkv, g_dkv);

    __half *hsh, *hss, *wqh, *wqs, *wkvh, *wkvs, *woh, *wos, *aoh, *aos;
    cudaGetSymbolAddress((void**)&hsh,  g_hsh);  cudaGetSymbolAddress((void**)&hss,  g_hss);
    cudaGetSymbolAddress((void**)&wqh,  g_wqh);  cudaGetSymbolAddress((void**)&wqs,  g_wqs);
    cudaGetSymbolAddress((void**)&wkvh, g_wkvh); cudaGetSymbolAddress((void**)&wkvs, g_wkvs);
    cudaGetSymbolAddress((void**)&woh,  g_woh);  cudaGetSymbolAddress((void**)&wos,  g_wos);
    cudaGetSymbolAddress((void**)&aoh,  g_aoh);  cudaGetSymbolAddress((void**)&aos,  g_aos);

    __half *qh, *qs2, *kh, *ks2, *vth, *vts;
    cudaGetSymbolAddress((void**)&qh,  g_qh);  cudaGetSymbolAddress((void**)&qs2, g_qs2);
    cudaGetSymbolAddress((void**)&kh,  g_kh);  cudaGetSymbolAddress((void**)&ks2, g_ks2);
    cudaGetSymbolAddress((void**)&vth, g_vth); cudaGetSymbolAddress((void**)&vts, g_vts);

    cudaFuncSetAttribute(gemm_fp16x2, cudaFuncAttributeMaxDynamicSharedMemorySize, GSM);
    cudaFuncSetAttribute(attn_mma,    cudaFuncAttributeMaxDynamicSharedMemorySize, ATT_SM);

    // split inputs into fp16 (hi, sum); wk/wv into merged [1024][2048] buffers
    split_fp16<<<1024, 256>>>(hs, hsh, hss, MTOT * HIDDEN / 4);
    split_fp16<<<1024, 256>>>(wq, wqh, wqs, HIDDEN * HIDDEN / 4);
    split_fp16<<<512,  256>>>(wk, wkvh,                       wkvs,                       KVD * HIDDEN / 4);
    split_fp16<<<512,  256>>>(wv, wkvh + (size_t)KVD * HIDDEN, wkvs + (size_t)KVD * HIDDEN, KVD * HIDDEN / 4);
    split_fp16<<<1024, 256>>>(wo, woh, wos, HIDDEN * HIDDEN / 4);

    // projections: Q, and merged K|V
    gemm_fp16x2<<<dim3(HIDDEN / 128, MTOT / 128), 512, GSM>>>(hsh, hss, wqh,  wqs,  dq,  HIDDEN);
    gemm_fp16x2<<<dim3(KVOUT  / 128, MTOT / 128), 512, GSM>>>(hsh, hss, wkvh, wkvs, dkv, KVOUT);

    // fused RoPE + split (Q, K) and V transpose + split
    rope_split<<<MTOT, 64>>>(dq, dkv, qh, qs2, kh, ks2);
    transpose_split_v<<<dim3(SEQ / 32, HD / 32, BATCH * NKV), dim3(32, 8)>>>(dkv, vth, vts);

    // persistent MMA flash attention (writes fp16 hi/sum directly)
    attn_mma<<<ATT_GRID, 256, ATT_SM>>>(qh, qs2, kh, ks2, vth, vts, amask, aoh, aos);

    // O-projection
    gemm_fp16x2<<<dim3(HIDDEN / 128, MTOT / 128), 512, GSM>>>(aoh, aos, woh, wos, out, HIDDEN);
}

// round 13
// speedup vs baseline: 4.0783x; 1.0319x over previous
#include <cuda_runtime.h>
#include <cuda_fp16.h>
#include <math.h>
#include <stdint.h>

#define HIDDEN 2048
#define NH 16
#define NKV 4
#define HD 128
#define KVD 512
#define BATCH 2
#define SEQ 2048
#define MTOT (BATCH*SEQ)   // 4096
#define QKVOUT 3072        // merged Q|K|V projection output width

// ---------------- scratch (static device globals; no allocs allowed) -------
__device__ float g_qkv[(size_t)MTOT * QKVOUT];   // merged Q|K|V proj out (fp32)

// fp16 (hi, sum) operands: hi = fp16(x); sum = fp16(hi + 64*(x - hi))
__device__ __half g_hsh  [(size_t)MTOT * HIDDEN];
__device__ __half g_hss  [(size_t)MTOT * HIDDEN];
__device__ __half g_wqkvh[(size_t)QKVOUT * HIDDEN];
__device__ __half g_wqkvs[(size_t)QKVOUT * HIDDEN];
__device__ __half g_woh  [(size_t)HIDDEN * HIDDEN];
__device__ __half g_wos  [(size_t)HIDDEN * HIDDEN];
__device__ __half g_aoh  [(size_t)MTOT * HIDDEN];
__device__ __half g_aos  [(size_t)MTOT * HIDDEN];

// attention fp16 operands
__device__ __half g_qh [(size_t)MTOT * HIDDEN];
__device__ __half g_qs2[(size_t)MTOT * HIDDEN];
__device__ __half g_kh [(size_t)MTOT * KVD];
__device__ __half g_ks2[(size_t)MTOT * KVD];
__device__ __half g_vth[(size_t)BATCH * NKV * HD * SEQ];
__device__ __half g_vts[(size_t)BATCH * NKV * HD * SEQ];

#define SPLIT_S 64.0f
#define SPLIT_SINV (1.0f / 64.0f)

// ---------------- helpers ---------------------------------------------------
__device__ __forceinline__ uint32_t smem_u32(const void* p) {
    return (uint32_t)__cvta_generic_to_shared(p);
}
__device__ __forceinline__ void cpa16(uint32_t smaddr, const void* g) {
    asm volatile("cp.async.cg.shared.global [%0], [%1], 16;" :: "r"(smaddr), "l"(g));
}
__device__ __forceinline__ void cpa_commit() { asm volatile("cp.async.commit_group;"); }
__device__ __forceinline__ void cpa_wait1()  { asm volatile("cp.async.wait_group 1;"); }
__device__ __forceinline__ void cpa_wait0()  { asm volatile("cp.async.wait_group 0;"); }

__device__ __forceinline__ void ldsm_x4(uint32_t* r, uint32_t addr) {
    asm volatile("ldmatrix.sync.aligned.m8n8.x4.shared.b16 {%0,%1,%2,%3}, [%4];"
                 : "=r"(r[0]), "=r"(r[1]), "=r"(r[2]), "=r"(r[3]) : "r"(addr));
}
__device__ __forceinline__ void mma_f16(float* d, const uint32_t* a, const uint32_t* b) {
    asm volatile(
        "mma.sync.aligned.m16n8k16.row.col.f32.f16.f16.f32 "
        "{%0,%1,%2,%3}, {%4,%5,%6,%7}, {%8,%9}, {%0,%1,%2,%3};"
        : "+f"(d[0]), "+f"(d[1]), "+f"(d[2]), "+f"(d[3])
        : "r"(a[0]), "r"(a[1]), "r"(a[2]), "r"(a[3]), "r"(b[0]), "r"(b[1]));
}
__device__ __forceinline__ uint32_t packh2(float x, float y) {
    __half2 v = __floats2half2_rn(x, y);
    return *reinterpret_cast<uint32_t*>(&v);
}
__device__ __forceinline__ uint32_t packh2s(float x, float y) {
    float hx = __half2float(__float2half(x));
    float hy = __half2float(__float2half(y));
    return packh2(fmaf(SPLIT_S, x - hx, hx), fmaf(SPLIT_S, y - hy, hy));
}
__device__ __forceinline__ void split1(float x, __half& h, __half& s) {
    h = __float2half(x);
    float hf = __half2float(h);
    s = __float2half(fmaf(SPLIT_S, x - hf, hf));
}

// ---------------- split kernel: fp32 -> (hi, hi + 64*resid) fp16 ------------
__global__ void split_fp16(const float* __restrict__ in,
                           __half* __restrict__ hi,
                           __half* __restrict__ su, int n4)
{
    for (int i = blockIdx.x * blockDim.x + threadIdx.x; i < n4; i += gridDim.x * blockDim.x) {
        float4 x = ((const float4*)in)[i];
        __half h0, h1, h2, h3, s0, s1, s2, s3;
        split1(x.x, h0, s0); split1(x.y, h1, s1);
        split1(x.z, h2, s2); split1(x.w, h3, s3);
        ushort4 hv = make_ushort4(__half_as_ushort(h0), __half_as_ushort(h1),
                                  __half_as_ushort(h2), __half_as_ushort(h3));
        ushort4 sv = make_ushort4(__half_as_ushort(s0), __half_as_ushort(s1),
                                  __half_as_ushort(s2), __half_as_ushort(s3));
        ((ushort4*)hi)[i] = hv;
        ((ushort4*)su)[i] = sv;
    }
}

// ---------------- fused RoPE + split: fp32 qkv -> fp16 hi/sum ---------------
__global__ __launch_bounds__(256) void rope_split(
    const float* __restrict__ qkv,
    __half* __restrict__ qh, __half* __restrict__ qs,
    __half* __restrict__ kh, __half* __restrict__ ks)
{
    const int bs  = blockIdx.x * 4 + (threadIdx.x >> 6);
    const int pos = bs % SEQ;
    const int i   = threadIdx.x & 63;  // pair index
    float inv = powf(10000.0f, -(float)i / 64.0f);
    float ang = (float)pos * inv;
    float s, c;
    sincosf(ang, &s, &c);

    #pragma unroll
    for (int h = 0; h < NH; h++) {
        const float* p = qkv + (size_t)bs * QKVOUT + h * HD;
        float a = p[i], b2 = p[i + 64];
        float r0 = a * c - b2 * s;
        float r1 = b2 * c + a * s;
        __half h0, s0, h1, s1;
        split1(r0, h0, s0); split1(r1, h1, s1);
        size_t o = (size_t)bs * HIDDEN + h * HD + i;
        qh[o] = h0; qs[o] = s0;
        qh[o + 64] = h1; qs[o + 64] = s1;
    }
    #pragma unroll
    for (int h = 0; h < NKV; h++) {
        const float* p = qkv + (size_t)bs * QKVOUT + HIDDEN + h * HD;   // K cols
        float a = p[i], b2 = p[i + 64];
        float r0 = a * c - b2 * s;
        float r1 = b2 * c + a * s;
        __half h0, s0, h1, s1;
        split1(r0, h0, s0); split1(r1, h1, s1);
        size_t o = (size_t)bs * KVD + h * HD + i;
        kh[o] = h0; ks[o] = s0;
        kh[o + 64] = h1; ks[o + 64] = s1;
    }
}

// ---------------- V transpose + split: qkv [s][2560+kvh*HD+d] -> [bh][d][s] -
__global__ void transpose_split_v(const float* __restrict__ qkv,
                                  __half* __restrict__ vth,
                                  __half* __restrict__ vts)
{
    __shared__ float tile[32][33];
    const int s0 = blockIdx.x * 32, d0 = blockIdx.y * 32;
    const int bh = blockIdx.z;
    const int b = bh / NKV, kvh = bh % NKV;
    const int tx = threadIdx.x, ty = threadIdx.y;   // 32 x 8

    #pragma unroll
    for (int i = 0; i < 4; i++) {
        int s = s0 + ty * 4 + i;
        tile[ty * 4 + i][tx] = qkv[(size_t)(b * SEQ + s) * QKVOUT + HIDDEN + KVD + kvh * HD + d0 + tx];
    }
    __syncthreads();
    #pragma unroll
    for (int i = 0; i < 4; i++) {
        int d = d0 + ty * 4 + i;
        float x = tile[tx][ty * 4 + i];
        __half hx, sx;
        split1(x, hx, sx);
        size_t o = (size_t)(bh * HD + d) * SEQ + s0 + tx;
        vth[o] = hx;
        vts[o] = sx;
    }
}

// ============================================================================
// fp16 2-MMA corrected GEMM (R10 winner, unchanged math)
// ============================================================================
#define LDH 40
#define LDB (LDH * 2)
#define ARR (128 * LDB)
#define BUFB (4 * ARR)
#define GSM (2 * BUFB)

__global__ __launch_bounds__(512) void gemm_fp16x2(
    const __half* __restrict__ Ah_, const __half* __restrict__ As_,
    const __half* __restrict__ Bh_, const __half* __restrict__ Bs_,
    float* __restrict__ C, int N)
{
    extern __shared__ char dsm[];
    const uint32_t base = smem_u32(dsm);

    const int tid  = threadIdx.x;
    const int warp = tid >> 5, lane = tid & 31;
    const int wr = warp & 3, wc = warp >> 2;
    const int row0 = blockIdx.y * 128;
    const int col0 = blockIdx.x * 128;

    const char* src[4] = {
        (const char*)(Ah_ + (size_t)row0 * HIDDEN),
        (const char*)(As_ + (size_t)row0 * HIDDEN),
        (const char*)(Bh_ + (size_t)col0 * HIDDEN),
        (const char*)(Bs_ + (size_t)col0 * HIDDEN)
    };

    const int nChunk = HIDDEN / 32;

    const int lr = tid >> 2;
    const int lc = tid & 3;
    auto loadTile = [&](int t, int buf) {
        #pragma unroll
        for (int a = 0; a < 4; a++) {
            cpa16(base + buf * BUFB + a * ARR + lr * LDB + lc * 16,
                  src[a] + ((size_t)lr * HIDDEN + t * 32) * 2 + lc * 16);
        }
        cpa_commit();
    };

    float acch[2][4][4], accs[2][4][4];
    #pragma unroll
    for (int mi = 0; mi < 2; mi++)
        #pragma unroll
        for (int ni = 0; ni < 4; ni++)
            #pragma unroll
            for (int r = 0; r < 4; r++) { acch[mi][ni][r] = 0.f; accs[mi][ni][r] = 0.f; }

    const uint32_t aoffA = (uint32_t)((wr * 32 + (lane & 15)) * LDB + ((lane >> 4) << 3) * 2);
    const uint32_t aoffB = (uint32_t)((wc * 32 + ((lane >> 4) << 3) + (lane & 7)) * LDB
                                      + (((lane >> 3) & 1) << 3) * 2);

    loadTile(0, 0);

    for (int t = 0; t < nChunk; t++) {
        const int buf = t & 1;
        if (t + 1 < nChunk) { loadTile(t + 1, buf ^ 1); cpa_wait1(); }
        else                { cpa_wait0(); }
        __syncthreads();

        const uint32_t bo = base + buf * BUFB;

        #pragma unroll
        for (int ks = 0; ks < 2; ks++) {
            const uint32_t kb = (uint32_t)(ks * 32);

            uint32_t ah[2][4], as_[2][4];
            ldsm_x4(ah[0],  bo + 0 * ARR + aoffA + kb);
            ldsm_x4(ah[1],  bo + 0 * ARR + aoffA + kb + 16 * LDB);
            ldsm_x4(as_[0], bo + 1 * ARR + aoffA + kb);
            ldsm_x4(as_[1], bo + 1 * ARR + aoffA + kb + 16 * LDB);

            uint32_t bh[4][2], bs[4][2], tmp[4];
            ldsm_x4(tmp, bo + 2 * ARR + aoffB + kb);
            bh[0][0] = tmp[0]; bh[0][1] = tmp[1]; bh[1][0] = tmp[2]; bh[1][1] = tmp[3];
            ldsm_x4(tmp, bo + 2 * ARR + aoffB + kb + 16 * LDB);
            bh[2][0] = tmp[0]; bh[2][1] = tmp[1]; bh[3][0] = tmp[2]; bh[3][1] = tmp[3];
            ldsm_x4(tmp, bo + 3 * ARR + aoffB + kb);
            bs[0][0] = tmp[0]; bs[0][1] = tmp[1]; bs[1][0] = tmp[2]; bs[1][1] = tmp[3];
            ldsm_x4(tmp, bo + 3 * ARR + aoffB + kb + 16 * LDB);
            bs[2][0] = tmp[0]; bs[2][1] = tmp[1]; bs[3][0] = tmp[2]; bs[3][1] = tmp[3];

            #pragma unroll
            for (int mi = 0; mi < 2; mi++)
                #pragma unroll
                for (int ni = 0; ni < 4; ni++) {
                    mma_f16(acch[mi][ni], ah[mi],  bh[ni]);
                    mma_f16(accs[mi][ni], as_[mi], bs[ni]);
                }
        }
        __syncthreads();
    }

    #pragma unroll
    for (int mi = 0; mi < 2; mi++)
        #pragma unroll
        for (int ni = 0; ni < 4; ni++) {
            const int row = row0 + wr * 32 + mi * 16 + (lane >> 2);
            const int col = col0 + wc * 32 + ni * 8 + 2 * (lane & 3);
            float v0 = acch[mi][ni][0] + (accs[mi][ni][0] - acch[mi][ni][0]) * SPLIT_SINV;
            float v1 = acch[mi][ni][1] + (accs[mi][ni][1] - acch[mi][ni][1]) * SPLIT_SINV;
            float v2 = acch[mi][ni][2] + (accs[mi][ni][2] - acch[mi][ni][2]) * SPLIT_SINV;
            float v3 = acch[mi][ni][3] + (accs[mi][ni][3] - acch[mi][ni][3]) * SPLIT_SINV;
            *(float2*)(C + (size_t)row * N + col)       = make_float2(v0, v1);
            *(float2*)(C + (size_t)(row + 8) * N + col) = make_float2(v2, v3);
        }
}

// ============================================================================
// Persistent MMA flash attention (causal, GQA) — fp16 2-MMA split, BKV=64
// ============================================================================
#define ATT_BQ 128
#define ATT_BKV 64
#define ATT_GRID 148
#define N_ITEMS 512             // 16 qb x 16 h x 2 b
#define SQ_LDB 272              // 128 halfs + 16B pad
#define SV_LDB 144              // 64 halfs + 16B pad
#define KTILE_B 17408           // 64 * SQ_LDB
#define VTILE_B 18432           // 128 * SV_LDB
#define OFF_QH 0
#define OFF_QS 34816
#define OFF_K  69632            // + (buf*2+split)*KTILE_B
#define OFF_VT 139264           // + (buf*2+split)*VTILE_B
#define OFF_MSK 212992
#define ATT_SM 221184

__global__ __launch_bounds__(256) void attn_mma(
    const __half* __restrict__ qh,  const __half* __restrict__ qs,
    const __half* __restrict__ kh,  const __half* __restrict__ ks,
    const __half* __restrict__ vth, const __half* __restrict__ vts,
    const int* __restrict__ amask,
    __half* __restrict__ aoh, __half* __restrict__ aos)
{
    extern __shared__ char sm[];
    const uint32_t base = smem_u32(sm);
    const int cta = blockIdx.x;
    const int tid = threadIdx.x, warp = tid >> 5, lane = tid & 31;
    const float scale = 0.08838834764831845f;

    const uint32_t aoffQ = (uint32_t)((warp * 16 + (lane & 15)) * SQ_LDB + ((lane >> 4) << 4));
    const uint32_t boffK = (uint32_t)(((lane >> 4) * 8 + (lane & 7)) * SQ_LDB + (((lane >> 3) & 1) << 4));
    const uint32_t boffV = (uint32_t)(((lane >> 4) * 8 + (lane & 7)) * SV_LDB + (((lane >> 3) & 1) << 4));
    const int* msk = (const int*)(sm + OFF_MSK);

    for (int p = 0; p < (N_ITEMS + ATT_GRID - 1) / ATT_GRID; p++) {
        const int w = p * ATT_GRID + ((p & 1) ? (ATT_GRID - 1 - cta) : cta);
        if (w >= N_ITEMS) continue;
        const int qb = 15 - (w >> 5);          // descending-qb order
        const int rem = w & 31;
        const int h = rem >> 1;
        const int b = rem & 1;
        const int kvh = h / (NH / NKV);
        const int bh = b * NKV + kvh;

        __syncthreads();   // previous item's smem consumers done

        // load Q tile (both splits)
        {
            const size_t qrow0 = (size_t)(b * SEQ + qb * ATT_BQ);
            #pragma unroll
            for (int i = 0; i < 8; i++) {
                int id = tid + i * 256;
                int r = id >> 4, c = id & 15;
                size_t go = (qrow0 + r) * HIDDEN + (size_t)h * HD + c * 8;
                cpa16(base + OFF_QH + r * SQ_LDB + c * 16, qh + go);
                cpa16(base + OFF_QS + r * SQ_LDB + c * 16, qs + go);
            }
            cpa_commit();
        }
        const int mlen = (qb + 1) * ATT_BQ;
        for (int i = tid; i < mlen; i += 256)
            ((int*)(sm + OFF_MSK))[i] = amask[b * SEQ + i];

        const int nTiles = (qb + 1) * (ATT_BQ / ATT_BKV);   // (qb+1)*2

        auto loadKV = [&](int t, int buf) {
            const int kv0 = t * ATT_BKV;
            #pragma unroll
            for (int i = 0; i < 8; i++) {       // K: 2 splits x 64 rows x 16 chunks
                int id = tid + i * 256;
                int split = id >> 10, rem2 = id & 1023;
                int r = rem2 >> 4, c = rem2 & 15;
                const __half* src = split ? ks : kh;
                cpa16(base + OFF_K + (buf * 2 + split) * KTILE_B + r * SQ_LDB + c * 16,
                      src + (size_t)(b * SEQ + kv0 + r) * KVD + (size_t)kvh * HD + c * 8);
            }
            #pragma unroll
            for (int i = 0; i < 8; i++) {       // V: 2 splits x 128 rows x 8 chunks
                int id = tid + i * 256;
                int split = id >> 10, rem2 = id & 1023;
                int r = rem2 >> 3, c = rem2 & 7;
                const __half* src = split ? vts : vth;
                cpa16(base + OFF_VT + (buf * 2 + split) * VTILE_B + r * SV_LDB + c * 16,
                      src + (size_t)(bh * HD + r) * SEQ + kv0 + c * 8);
            }
            cpa_commit();
        };

        float O[16][4];
        #pragma unroll
        for (int i = 0; i < 16; i++)
            #pragma unroll
            for (int r = 0; r < 4; r++) O[i][r] = 0.f;
        float m0 = -1e30f, m1 = -1e30f, l0 = 0.f, l1 = 0.f;

        loadKV(0, 0);
        cpa_wait0();
        __syncthreads();

        const int rowg0 = qb * ATT_BQ + warp * 16 + (lane >> 2);
        const int rowg1 = rowg0 + 8;

        for (int t = 0; t < nTiles; t++) {
            const int buf = t & 1;
            const int kv0 = t * ATT_BKV;

            __syncthreads();
            if (t + 1 < nTiles) { loadKV(t + 1, buf ^ 1); cpa_wait1(); }
            else                { cpa_wait0(); }
            __syncthreads();

            const uint32_t kb_h = base + OFF_K + (buf * 2 + 0) * KTILE_B;
            const uint32_t kb_s = base + OFF_K + (buf * 2 + 1) * KTILE_B;

            // ---- S = Q K^T in two 32-col halves (caps live registers) ----
            float sf[8][4];
            #pragma unroll
            for (int h32 = 0; h32 < 2; h32++) {
                float sh[4][4], ss[4][4];
                #pragma unroll
                for (int nt = 0; nt < 4; nt++)
                    #pragma unroll
                    for (int r = 0; r < 4; r++) { sh[nt][r] = 0.f; ss[nt][r] = 0.f; }

                #pragma unroll
                for (int ksI = 0; ksI < 8; ksI++) {
                    uint32_t ah[4], as_[4];
                    ldsm_x4(ah,  base + OFF_QH + aoffQ + ksI * 32);
                    ldsm_x4(as_, base + OFF_QS + aoffQ + ksI * 32);
                    #pragma unroll
                    for (int ntp = 0; ntp < 2; ntp++) {
                        const uint32_t roff = (uint32_t)((h32 * 2 + ntp) * 16 * SQ_LDB) + ksI * 32;
                        uint32_t tmp[4];
                        ldsm_x4(tmp, kb_h + boffK + roff);
                        { uint32_t b0[2] = {tmp[0], tmp[1]}, b1[2] = {tmp[2], tmp[3]};
                          mma_f16(sh[ntp * 2],     ah, b0);
                          mma_f16(sh[ntp * 2 + 1], ah, b1); }
                        ldsm_x4(tmp, kb_s + boffK + roff);
                        { uint32_t b0[2] = {tmp[0], tmp[1]}, b1[2] = {tmp[2], tmp[3]};
                          mma_f16(ss[ntp * 2],     as_, b0);
                          mma_f16(ss[ntp * 2 + 1], as_, b1); }
                    }
                }

                // fold + scale + mask into sf
                #pragma unroll
                for (int nt = 0; nt < 4; nt++)
                    #pragma unroll
                    for (int r = 0; r < 4; r++) {
                        float s = sh[nt][r] + (ss[nt][r] - sh[nt][r]) * SPLIT_SINV;
                        s *= scale;
                        int col = kv0 + h32 * 32 + nt * 8 + 2 * (lane & 3) + (r & 1);
                        int row = (r < 2) ? rowg0 : rowg1;
                        if (col > row || msk[col] == 0) s = -1e30f;
                        sf[h32 * 4 + nt][r] = s;
                    }
            }

            // online softmax over 64 columns
            float mx0 = m0, mx1 = m1;
            #pragma unroll
            for (int nt = 0; nt < 8; nt++) {
                mx0 = fmaxf(mx0, fmaxf(sf[nt][0], sf[nt][1]));
                mx1 = fmaxf(mx1, fmaxf(sf[nt][2], sf[nt][3]));
            }
            mx0 = fmaxf(mx0, __shfl_xor_sync(0xffffffffu, mx0, 1));
            mx0 = fmaxf(mx0, __shfl_xor_sync(0xffffffffu, mx0, 2));
            mx1 = fmaxf(mx1, __shfl_xor_sync(0xffffffffu, mx1, 1));
            mx1 = fmaxf(mx1, __shfl_xor_sync(0xffffffffu, mx1, 2));

            float sum0 = 0.f, sum1 = 0.f;
            #pragma unroll
            for (int nt = 0; nt < 8; nt++) {
                sf[nt][0] = __expf(sf[nt][0] - mx0);
                sf[nt][1] = __expf(sf[nt][1] - mx0);
                sf[nt][2] = __expf(sf[nt][2] - mx1);
                sf[nt][3] = __expf(sf[nt][3] - mx1);
                sum0 += sf[nt][0] + sf[nt][1];
                sum1 += sf[nt][2] + sf[nt][3];
            }
            sum0 += __shfl_xor_sync(0xffffffffu, sum0, 1);
            sum0 += __shfl_xor_sync(0xffffffffu, sum0, 2);
            sum1 += __shfl_xor_sync(0xffffffffu, sum1, 1);
            sum1 += __shfl_xor_sync(0xffffffffu, sum1, 2);

            float a0 = __expf(m0 - mx0), a1 = __expf(m1 - mx1);
            l0 = l0 * a0 + sum0;
            l1 = l1 * a1 + sum1;
            m0 = mx0; m1 = mx1;

            #pragma unroll
            for (int i = 0; i < 16; i++) {
                O[i][0] *= a0; O[i][1] *= a0;
                O[i][2] *= a1; O[i][3] *= a1;
            }

            // P fragments hi/sum: 4 k16 groups over 64 columns
            uint32_t pH[4][4], pS[4][4];
            #pragma unroll
            for (int g = 0; g < 4; g++) {
                int t0 = g * 2, t1 = t0 + 1;
                pH[g][0] = packh2 (sf[t0][0], sf[t0][1]);
                pH[g][1] = packh2 (sf[t0][2], sf[t0][3]);
                pH[g][2] = packh2 (sf[t1][0], sf[t1][1]);
                pH[g][3] = packh2 (sf[t1][2], sf[t1][3]);
                pS[g][0] = packh2s(sf[t0][0], sf[t0][1]);
                pS[g][1] = packh2s(sf[t0][2], sf[t0][3]);
                pS[g][2] = packh2s(sf[t1][0], sf[t1][1]);
                pS[g][3] = packh2s(sf[t1][2], sf[t1][3]);
            }

            // ---- O += P V ----
            const uint32_t vb_h = base + OFF_VT + (buf * 2 + 0) * VTILE_B;
            const uint32_t vb_s = base + OFF_VT + (buf * 2 + 1) * VTILE_B;
            #pragma unroll
            for (int ntp = 0; ntp < 8; ntp++) {
                float th[2][4], ts[2][4];
                #pragma unroll
                for (int j = 0; j < 2; j++)
                    #pragma unroll
                    for (int r = 0; r < 4; r++) { th[j][r] = 0.f; ts[j][r] = 0.f; }
                #pragma unroll
                for (int g = 0; g < 4; g++) {
                    uint32_t tmp[4];
                    ldsm_x4(tmp, vb_h + boffV + ntp * 16 * SV_LDB + g * 32);
                    { uint32_t b0[2] = {tmp[0], tmp[1]}, b1[2] = {tmp[2], tmp[3]};
                      mma_f16(th[0], pH[g], b0);
                      mma_f16(th[1], pH[g], b1); }
                    ldsm_x4(tmp, vb_s + boffV + ntp * 16 * SV_LDB + g * 32);
                    { uint32_t b0[2] = {tmp[0], tmp[1]}, b1[2] = {tmp[2], tmp[3]};
                      mma_f16(ts[0], pS[g], b0);
                      mma_f16(ts[1], pS[g], b1); }
                }
                #pragma unroll
                for (int j = 0; j < 2; j++)
                    #pragma unroll
                    for (int r = 0; r < 4; r++)
                        O[ntp * 2 + j][r] += th[j][r] + (ts[j][r] - th[j][r]) * SPLIT_SINV;
            }
        }

        // epilogue: normalize + fused split to fp16 hi/sum
        const float il0 = 1.f / l0, il1 = 1.f / l1;
        #pragma unroll
        for (int nt = 0; nt < 16; nt++) {
            int col = h * HD + nt * 8 + 2 * (lane & 3);
            size_t o0 = (size_t)(b * SEQ + rowg0) * HIDDEN + col;
            size_t o1 = (size_t)(b * SEQ + rowg1) * HIDDEN + col;
            float x0 = O[nt][0] * il0, x1 = O[nt][1] * il0;
            float x2 = O[nt][2] * il1, x3 = O[nt][3] * il1;
            *(uint32_t*)(aoh + o0) = packh2 (x0, x1);
            *(uint32_t*)(aos + o0) = packh2s(x0, x1);
            *(uint32_t*)(aoh + o1) = packh2 (x2, x3);
            *(uint32_t*)(aos + o1) = packh2s(x2, x3);
        }
    }
}

// ---------------- launch ----------------------------------------------------
extern "C" void kernel_launch(void* const* d_in, const int* in_sizes, int n_in,
                              void* d_out, int out_size)
{
    const float* hs    = (const float*)d_in[0];
    const int*   amask = (const int*)  d_in[1];
    const float* wq    = (const float*)d_in[2];
    const float* wk    = (const float*)d_in[3];
    const float* wv    = (const float*)d_in[4];
    const float* wo    = (const float*)d_in[5];
    float* out = (float*)d_out;

    float* qkv;
    cudaGetSymbolAddress((void**)&qkv, g_qkv);

    __half *hsh, *hss, *wqkvh, *wqkvs, *woh, *wos, *aoh, *aos;
    cudaGetSymbolAddress((void**)&hsh,   g_hsh);   cudaGetSymbolAddress((void**)&hss,   g_hss);
    cudaGetSymbolAddress((void**)&wqkvh, g_wqkvh); cudaGetSymbolAddress((void**)&wqkvs, g_wqkvs);
    cudaGetSymbolAddress((void**)&woh,   g_woh);   cudaGetSymbolAddress((void**)&wos,   g_wos);
    cudaGetSymbolAddress((void**)&aoh,   g_aoh);   cudaGetSymbolAddress((void**)&aos,   g_aos);

    __half *qh, *qs2, *kh, *ks2, *vth, *vts;
    cudaGetSymbolAddress((void**)&qh,  g_qh);  cudaGetSymbolAddress((void**)&qs2, g_qs2);
    cudaGetSymbolAddress((void**)&kh,  g_kh);  cudaGetSymbolAddress((void**)&ks2, g_ks2);
    cudaGetSymbolAddress((void**)&vth, g_vth); cudaGetSymbolAddress((void**)&vts, g_vts);

    cudaFuncSetAttribute(gemm_fp16x2, cudaFuncAttributeMaxDynamicSharedMemorySize, GSM);
    cudaFuncSetAttribute(attn_mma,    cudaFuncAttributeMaxDynamicSharedMemorySize, ATT_SM);

    // split inputs; weights packed [wq | wk | wv] rows into merged buffers
    split_fp16<<<1024, 256>>>(hs, hsh, hss, MTOT * HIDDEN / 4);
    split_fp16<<<1024, 256>>>(wq, wqkvh, wqkvs, HIDDEN * HIDDEN / 4);
    split_fp16<<<512,  256>>>(wk, wqkvh + (size_t)HIDDEN * HIDDEN,
                                  wqkvs + (size_t)HIDDEN * HIDDEN, KVD * HIDDEN / 4);
    split_fp16<<<512,  256>>>(wv, wqkvh + (size_t)(HIDDEN + KVD) * HIDDEN,
                                  wqkvs + (size_t)(HIDDEN + KVD) * HIDDEN, KVD * HIDDEN / 4);
    split_fp16<<<1024, 256>>>(wo, woh, wos, HIDDEN * HIDDEN / 4);

    // single merged Q|K|V projection
    gemm_fp16x2<<<dim3(QKVOUT / 128, MTOT / 128), 512, GSM>>>(hsh, hss, wqkvh, wqkvs, qkv, QKVOUT);

    // fused RoPE + split (Q, K) and V transpose + split
    rope_split<<<MTOT / 4, 256>>>(qkv, qh, qs2, kh, ks2);
    transpose_split_v<<<dim3(SEQ / 32, HD / 32, BATCH * NKV), dim3(32, 8)>>>(qkv, vth, vts);

    // persistent MMA flash attention (BKV=64, writes fp16 hi/sum directly)
    attn_mma<<<ATT_GRID, 256, ATT_SM>>>(qh, qs2, kh, ks2, vth, vts, amask, aoh, aos);

    // O-projection
    gemm_fp16x2<<<dim3(HIDDEN / 128, MTOT / 128), 512, GSM>>>(aoh, aos, woh, wos, out, HIDDEN);
}

// round 14
// speedup vs baseline: 4.8319x; 1.1848x over previous
#include <cuda_runtime.h>
#include <cuda_fp16.h>
#include <math.h>
#include <stdint.h>

#define HIDDEN 2048
#define NH 16
#define NKV 4
#define HD 128
#define KVD 512
#define BATCH 2
#define SEQ 2048
#define MTOT (BATCH*SEQ)   // 4096
#define QKVOUT 3072        // merged Q|K|V projection output width

// ---------------- scratch (static device globals; no allocs allowed) -------
__device__ float g_qkv[(size_t)MTOT * QKVOUT];   // merged Q|K|V proj out (fp32)

// fp16 (hi, sum) operands: hi = fp16(x); sum = fp16(hi + 64*(x - hi))
__device__ __half g_hsh  [(size_t)MTOT * HIDDEN];
__device__ __half g_hss  [(size_t)MTOT * HIDDEN];
__device__ __half g_wqkvh[(size_t)QKVOUT * HIDDEN];
__device__ __half g_wqkvs[(size_t)QKVOUT * HIDDEN];
__device__ __half g_woh  [(size_t)HIDDEN * HIDDEN];   // plain fp16 (O-proj)
__device__ __half g_aoh  [(size_t)MTOT * HIDDEN];     // plain fp16 (O-proj)

// attention fp16 operands
__device__ __half g_qh [(size_t)MTOT * HIDDEN];
__device__ __half g_qs2[(size_t)MTOT * HIDDEN];
__device__ __half g_kh [(size_t)MTOT * KVD];
__device__ __half g_ks2[(size_t)MTOT * KVD];
__device__ __half g_vth[(size_t)BATCH * NKV * HD * SEQ];
__device__ __half g_vts[(size_t)BATCH * NKV * HD * SEQ];

#define SPLIT_S 64.0f
#define SPLIT_SINV (1.0f / 64.0f)

// ---------------- helpers ---------------------------------------------------
__device__ __forceinline__ uint32_t smem_u32(const void* p) {
    return (uint32_t)__cvta_generic_to_shared(p);
}
__device__ __forceinline__ void cpa16(uint32_t smaddr, const void* g) {
    asm volatile("cp.async.cg.shared.global [%0], [%1], 16;" :: "r"(smaddr), "l"(g));
}
__device__ __forceinline__ void cpa_commit() { asm volatile("cp.async.commit_group;"); }
__device__ __forceinline__ void cpa_wait1()  { asm volatile("cp.async.wait_group 1;"); }
__device__ __forceinline__ void cpa_wait0()  { asm volatile("cp.async.wait_group 0;"); }

__device__ __forceinline__ void ldsm_x4(uint32_t* r, uint32_t addr) {
    asm volatile("ldmatrix.sync.aligned.m8n8.x4.shared.b16 {%0,%1,%2,%3}, [%4];"
                 : "=r"(r[0]), "=r"(r[1]), "=r"(r[2]), "=r"(r[3]) : "r"(addr));
}
__device__ __forceinline__ void mma_f16(float* d, const uint32_t* a, const uint32_t* b) {
    asm volatile(
        "mma.sync.aligned.m16n8k16.row.col.f32.f16.f16.f32 "
        "{%0,%1,%2,%3}, {%4,%5,%6,%7}, {%8,%9}, {%0,%1,%2,%3};"
        : "+f"(d[0]), "+f"(d[1]), "+f"(d[2]), "+f"(d[3])
        : "r"(a[0]), "r"(a[1]), "r"(a[2]), "r"(a[3]), "r"(b[0]), "r"(b[1]));
}
__device__ __forceinline__ uint32_t packh2(float x, float y) {
    __half2 v = __floats2half2_rn(x, y);
    return *reinterpret_cast<uint32_t*>(&v);
}
__device__ __forceinline__ uint32_t packh2s(float x, float y) {
    float hx = __half2float(__float2half(x));
    float hy = __half2float(__float2half(y));
    return packh2(fmaf(SPLIT_S, x - hx, hx), fmaf(SPLIT_S, y - hy, hy));
}
__device__ __forceinline__ void split1(float x, __half& h, __half& s) {
    h = __float2half(x);
    float hf = __half2float(h);
    s = __float2half(fmaf(SPLIT_S, x - hf, hf));
}

// ---------------- fused split kernel: all inputs in one launch --------------
__global__ __launch_bounds__(256) void split_all(
    const float* __restrict__ hs, const float* __restrict__ wq,
    const float* __restrict__ wk, const float* __restrict__ wv,
    const float* __restrict__ wo,
    __half* __restrict__ hsh, __half* __restrict__ hss,
    __half* __restrict__ wqkvh, __half* __restrict__ wqkvs,
    __half* __restrict__ woh)
{
    const int N_HS = MTOT * HIDDEN / 4;
    const int N_WQ = HIDDEN * HIDDEN / 4;
    const int N_WK = KVD * HIDDEN / 4;
    const int B1 = N_HS, B2 = B1 + N_WQ, B3 = B2 + N_WK, B4 = B3 + N_WK;
    const int total = B4 + N_WQ;

    for (int i = blockIdx.x * blockDim.x + threadIdx.x; i < total; i += gridDim.x * blockDim.x) {
        const float* src;
        __half *dh, *ds;
        int j;
        if (i < B1)      { j = i;      src = hs; dh = hsh;   ds = hss; }
        else if (i < B2) { j = i - B1; src = wq; dh = wqkvh; ds = wqkvs; }
        else if (i < B3) { j = i - B2; src = wk; dh = wqkvh + (size_t)HIDDEN * HIDDEN;
                                                 ds = wqkvs + (size_t)HIDDEN * HIDDEN; }
        else if (i < B4) { j = i - B3; src = wv; dh = wqkvh + (size_t)(HIDDEN + KVD) * HIDDEN;
                                                 ds = wqkvs + (size_t)(HIDDEN + KVD) * HIDDEN; }
        else             { j = i - B4; src = wo; dh = woh;   ds = 0; }

        float4 x = ((const float4*)src)[j];
        __half h0, h1, h2, h3, s0, s1, s2, s3;
        split1(x.x, h0, s0); split1(x.y, h1, s1);
        split1(x.z, h2, s2); split1(x.w, h3, s3);
        ((ushort4*)dh)[j] = make_ushort4(__half_as_ushort(h0), __half_as_ushort(h1),
                                         __half_as_ushort(h2), __half_as_ushort(h3));
        if (ds)
            ((ushort4*)ds)[j] = make_ushort4(__half_as_ushort(s0), __half_as_ushort(s1),
                                             __half_as_ushort(s2), __half_as_ushort(s3));
    }
}

// ---------------- fused RoPE + split: fp32 qkv -> fp16 hi/sum ---------------
__global__ __launch_bounds__(256) void rope_split(
    const float* __restrict__ qkv,
    __half* __restrict__ qh, __half* __restrict__ qs,
    __half* __restrict__ kh, __half* __restrict__ ks)
{
    const int bs  = blockIdx.x * 4 + (threadIdx.x >> 6);
    const int pos = bs % SEQ;
    const int i   = threadIdx.x & 63;  // pair index
    float inv = powf(10000.0f, -(float)i / 64.0f);
    float ang = (float)pos * inv;
    float s, c;
    sincosf(ang, &s, &c);

    #pragma unroll
    for (int h = 0; h < NH; h++) {
        const float* p = qkv + (size_t)bs * QKVOUT + h * HD;
        float a = p[i], b2 = p[i + 64];
        float r0 = a * c - b2 * s;
        float r1 = b2 * c + a * s;
        __half h0, s0, h1, s1;
        split1(r0, h0, s0); split1(r1, h1, s1);
        size_t o = (size_t)bs * HIDDEN + h * HD + i;
        qh[o] = h0; qs[o] = s0;
        qh[o + 64] = h1; qs[o + 64] = s1;
    }
    #pragma unroll
    for (int h = 0; h < NKV; h++) {
        const float* p = qkv + (size_t)bs * QKVOUT + HIDDEN + h * HD;   // K cols
        float a = p[i], b2 = p[i + 64];
        float r0 = a * c - b2 * s;
        float r1 = b2 * c + a * s;
        __half h0, s0, h1, s1;
        split1(r0, h0, s0); split1(r1, h1, s1);
        size_t o = (size_t)bs * KVD + h * HD + i;
        kh[o] = h0; ks[o] = s0;
        kh[o + 64] = h1; ks[o + 64] = s1;
    }
}

// ---------------- V transpose + split: qkv [s][2560+kvh*HD+d] -> [bh][d][s] -
__global__ void transpose_split_v(const float* __restrict__ qkv,
                                  __half* __restrict__ vth,
                                  __half* __restrict__ vts)
{
    __shared__ float tile[32][33];
    const int s0 = blockIdx.x * 32, d0 = blockIdx.y * 32;
    const int bh = blockIdx.z;
    const int b = bh / NKV, kvh = bh % NKV;
    const int tx = threadIdx.x, ty = threadIdx.y;   // 32 x 8

    #pragma unroll
    for (int i = 0; i < 4; i++) {
        int s = s0 + ty * 4 + i;
        tile[ty * 4 + i][tx] = qkv[(size_t)(b * SEQ + s) * QKVOUT + HIDDEN + KVD + kvh * HD + d0 + tx];
    }
    __syncthreads();
    #pragma unroll
    for (int i = 0; i < 4; i++) {
        int d = d0 + ty * 4 + i;
        float x = tile[tx][ty * 4 + i];
        __half hx, sx;
        split1(x, hx, sx);
        size_t o = (size_t)(bh * HD + d) * SEQ + s0 + tx;
        vth[o] = hx;
        vts[o] = sx;
    }
}

// ============================================================================
// fp16 2-MMA corrected GEMM (R10 winner, used for QKV projection)
// ============================================================================
#define LDH 40
#define LDB (LDH * 2)
#define ARR (128 * LDB)
#define BUFB (4 * ARR)
#define GSM (2 * BUFB)

__global__ __launch_bounds__(512) void gemm_fp16x2(
    const __half* __restrict__ Ah_, const __half* __restrict__ As_,
    const __half* __restrict__ Bh_, const __half* __restrict__ Bs_,
    float* __restrict__ C, int N)
{
    extern __shared__ char dsm[];
    const uint32_t base = smem_u32(dsm);

    const int tid  = threadIdx.x;
    const int warp = tid >> 5, lane = tid & 31;
    const int wr = warp & 3, wc = warp >> 2;
    const int row0 = blockIdx.y * 128;
    const int col0 = blockIdx.x * 128;

    const char* src[4] = {
        (const char*)(Ah_ + (size_t)row0 * HIDDEN),
        (const char*)(As_ + (size_t)row0 * HIDDEN),
        (const char*)(Bh_ + (size_t)col0 * HIDDEN),
        (const char*)(Bs_ + (size_t)col0 * HIDDEN)
    };

    const int nChunk = HIDDEN / 32;

    const int lr = tid >> 2;
    const int lc = tid & 3;
    auto loadTile = [&](int t, int buf) {
        #pragma unroll
        for (int a = 0; a < 4; a++) {
            cpa16(base + buf * BUFB + a * ARR + lr * LDB + lc * 16,
                  src[a] + ((size_t)lr * HIDDEN + t * 32) * 2 + lc * 16);
        }
        cpa_commit();
    };

    float acch[2][4][4], accs[2][4][4];
    #pragma unroll
    for (int mi = 0; mi < 2; mi++)
        #pragma unroll
        for (int ni = 0; ni < 4; ni++)
            #pragma unroll
            for (int r = 0; r < 4; r++) { acch[mi][ni][r] = 0.f; accs[mi][ni][r] = 0.f; }

    const uint32_t aoffA = (uint32_t)((wr * 32 + (lane & 15)) * LDB + ((lane >> 4) << 3) * 2);
    const uint32_t aoffB = (uint32_t)((wc * 32 + ((lane >> 4) << 3) + (lane & 7)) * LDB
                                      + (((lane >> 3) & 1) << 3) * 2);

    loadTile(0, 0);

    for (int t = 0; t < nChunk; t++) {
        const int buf = t & 1;
        if (t + 1 < nChunk) { loadTile(t + 1, buf ^ 1); cpa_wait1(); }
        else                { cpa_wait0(); }
        __syncthreads();

        const uint32_t bo = base + buf * BUFB;

        #pragma unroll
        for (int ks = 0; ks < 2; ks++) {
            const uint32_t kb = (uint32_t)(ks * 32);

            uint32_t ah[2][4], as_[2][4];
            ldsm_x4(ah[0],  bo + 0 * ARR + aoffA + kb);
            ldsm_x4(ah[1],  bo + 0 * ARR + aoffA + kb + 16 * LDB);
            ldsm_x4(as_[0], bo + 1 * ARR + aoffA + kb);
            ldsm_x4(as_[1], bo + 1 * ARR + aoffA + kb + 16 * LDB);

            uint32_t bh[4][2], bs[4][2], tmp[4];
            ldsm_x4(tmp, bo + 2 * ARR + aoffB + kb);
            bh[0][0] = tmp[0]; bh[0][1] = tmp[1]; bh[1][0] = tmp[2]; bh[1][1] = tmp[3];
            ldsm_x4(tmp, bo + 2 * ARR + aoffB + kb + 16 * LDB);
            bh[2][0] = tmp[0]; bh[2][1] = tmp[1]; bh[3][0] = tmp[2]; bh[3][1] = tmp[3];
            ldsm_x4(tmp, bo + 3 * ARR + aoffB + kb);
            bs[0][0] = tmp[0]; bs[0][1] = tmp[1]; bs[1][0] = tmp[2]; bs[1][1] = tmp[3];
            ldsm_x4(tmp, bo + 3 * ARR + aoffB + kb + 16 * LDB);
            bs[2][0] = tmp[0]; bs[2][1] = tmp[1]; bs[3][0] = tmp[2]; bs[3][1] = tmp[3];

            #pragma unroll
            for (int mi = 0; mi < 2; mi++)
                #pragma unroll
                for (int ni = 0; ni < 4; ni++) {
                    mma_f16(acch[mi][ni], ah[mi],  bh[ni]);
                    mma_f16(accs[mi][ni], as_[mi], bs[ni]);
                }
        }
        __syncthreads();
    }

    #pragma unroll
    for (int mi = 0; mi < 2; mi++)
        #pragma unroll
        for (int ni = 0; ni < 4; ni++) {
            const int row = row0 + wr * 32 + mi * 16 + (lane >> 2);
            const int col = col0 + wc * 32 + ni * 8 + 2 * (lane & 3);
            float v0 = acch[mi][ni][0] + (accs[mi][ni][0] - acch[mi][ni][0]) * SPLIT_SINV;
            float v1 = acch[mi][ni][1] + (accs[mi][ni][1] - acch[mi][ni][1]) * SPLIT_SINV;
            float v2 = acch[mi][ni][2] + (accs[mi][ni][2] - acch[mi][ni][2]) * SPLIT_SINV;
            float v3 = acch[mi][ni][3] + (accs[mi][ni][3] - acch[mi][ni][3]) * SPLIT_SINV;
            *(float2*)(C + (size_t)row * N + col)       = make_float2(v0, v1);
            *(float2*)(C + (size_t)(row + 8) * N + col) = make_float2(v2, v3);
        }
}

// ============================================================================
// Plain fp16 GEMM (single MMA, no correction) — O-projection (final stage)
// 128x128 block, 512 threads, warp 32x32, k-chunk 64, double-buffered
// ============================================================================
#define PLDB 144                 // 64 halfs + 16B pad
#define PARR (128 * PLDB)        // 18432
#define PBUF (2 * PARR)          // 36864
#define PGSM (2 * PBUF)          // 73728

__global__ __launch_bounds__(512) void gemm_plain(
    const __half* __restrict__ Ah_, const __half* __restrict__ Bh_,
    float* __restrict__ C, int N)
{
    extern __shared__ char dsm[];
    const uint32_t base = smem_u32(dsm);

    const int tid  = threadIdx.x;
    const int warp = tid >> 5, lane = tid & 31;
    const int wr = warp & 3, wc = warp >> 2;
    const int row0 = blockIdx.y * 128;
    const int col0 = blockIdx.x * 128;

    const char* srcA = (const char*)(Ah_ + (size_t)row0 * HIDDEN);
    const char* srcB = (const char*)(Bh_ + (size_t)col0 * HIDDEN);

    const int nChunk = HIDDEN / 64;    // 32

    auto loadTile = [&](int t, int buf) {
        #pragma unroll
        for (int i = 0; i < 2; i++) {
            int idx = tid + i * 512;        // 0..1023
            int r = idx >> 3, c = idx & 7;
            size_t go = ((size_t)r * HIDDEN + t * 64) * 2 + c * 16;
            cpa16(base + buf * PBUF + 0 * PARR + r * PLDB + c * 16, srcA + go);
            cpa16(base + buf * PBUF + 1 * PARR + r * PLDB + c * 16, srcB + go);
        }
        cpa_commit();
    };

    float acc[2][4][4];
    #pragma unroll
    for (int mi = 0; mi < 2; mi++)
        #pragma unroll
        for (int ni = 0; ni < 4; ni++)
            #pragma unroll
            for (int r = 0; r < 4; r++) acc[mi][ni][r] = 0.f;

    const uint32_t aoffA = (uint32_t)((wr * 32 + (lane & 15)) * PLDB + ((lane >> 4) << 4));
    const uint32_t aoffB = (uint32_t)((wc * 32 + ((lane >> 4) << 3) + (lane & 7)) * PLDB
                                      + (((lane >> 3) & 1) << 4));

    loadTile(0, 0);

    for (int t = 0; t < nChunk; t++) {
        const int buf = t & 1;
        if (t + 1 < nChunk) { loadTile(t + 1, buf ^ 1); cpa_wait1(); }
        else                { cpa_wait0(); }
        __syncthreads();

        const uint32_t bo = base + buf * PBUF;

        #pragma unroll
        for (int ks = 0; ks < 4; ks++) {
            const uint32_t kb = (uint32_t)(ks * 32);

            uint32_t ah[2][4];
            ldsm_x4(ah[0], bo + 0 * PARR + aoffA + kb);
            ldsm_x4(ah[1], bo + 0 * PARR + aoffA + kb + 16 * PLDB);

            uint32_t bh[4][2], tmp[4];
            ldsm_x4(tmp, bo + 1 * PARR + aoffB + kb);
            bh[0][0] = tmp[0]; bh[0][1] = tmp[1]; bh[1][0] = tmp[2]; bh[1][1] = tmp[3];
            ldsm_x4(tmp, bo + 1 * PARR + aoffB + kb + 16 * PLDB);
            bh[2][0] = tmp[0]; bh[2][1] = tmp[1]; bh[3][0] = tmp[2]; bh[3][1] = tmp[3];

            #pragma unroll
            for (int mi = 0; mi < 2; mi++)
                #pragma unroll
                for (int ni = 0; ni < 4; ni++)
                    mma_f16(acc[mi][ni], ah[mi], bh[ni]);
        }
        __syncthreads();
    }

    #pragma unroll
    for (int mi = 0; mi < 2; mi++)
        #pragma unroll
        for (int ni = 0; ni < 4; ni++) {
            const int row = row0 + wr * 32 + mi * 16 + (lane >> 2);
            const int col = col0 + wc * 32 + ni * 8 + 2 * (lane & 3);
            *(float2*)(C + (size_t)row * N + col)       = make_float2(acc[mi][ni][0], acc[mi][ni][1]);
            *(float2*)(C + (size_t)(row + 8) * N + col) = make_float2(acc[mi][ni][2], acc[mi][ni][3]);
        }
}

// ============================================================================
// Persistent MMA flash attention (causal, GQA) — fp16 2-MMA split, BKV=64
// Output written as plain fp16 (aoh only) for the plain O-projection.
// ============================================================================
#define ATT_BQ 128
#define ATT_BKV 64
#define ATT_GRID 148
#define N_ITEMS 512             // 16 qb x 16 h x 2 b
#define SQ_LDB 272              // 128 halfs + 16B pad
#define SV_LDB 144              // 64 halfs + 16B pad
#define KTILE_B 17408           // 64 * SQ_LDB
#define VTILE_B 18432           // 128 * SV_LDB
#define OFF_QH 0
#define OFF_QS 34816
#define OFF_K  69632            // + (buf*2+split)*KTILE_B
#define OFF_VT 139264           // + (buf*2+split)*VTILE_B
#define OFF_MSK 212992
#define ATT_SM 221184

__global__ __launch_bounds__(256) void attn_mma(
    const __half* __restrict__ qh,  const __half* __restrict__ qs,
    const __half* __restrict__ kh,  const __half* __restrict__ ks,
    const __half* __restrict__ vth, const __half* __restrict__ vts,
    const int* __restrict__ amask,
    __half* __restrict__ aoh)
{
    extern __shared__ char sm[];
    const uint32_t base = smem_u32(sm);
    const int cta = blockIdx.x;
    const int tid = threadIdx.x, warp = tid >> 5, lane = tid & 31;
    const float scale = 0.08838834764831845f;

    const uint32_t aoffQ = (uint32_t)((warp * 16 + (lane & 15)) * SQ_LDB + ((lane >> 4) << 4));
    const uint32_t boffK = (uint32_t)(((lane >> 4) * 8 + (lane & 7)) * SQ_LDB + (((lane >> 3) & 1) << 4));
    const uint32_t boffV = (uint32_t)(((lane >> 4) * 8 + (lane & 7)) * SV_LDB + (((lane >> 3) & 1) << 4));
    const int* msk = (const int*)(sm + OFF_MSK);

    for (int p = 0; p < (N_ITEMS + ATT_GRID - 1) / ATT_GRID; p++) {
        const int w = p * ATT_GRID + ((p & 1) ? (ATT_GRID - 1 - cta) : cta);
        if (w >= N_ITEMS) continue;
        const int qb = 15 - (w >> 5);          // descending-qb order
        const int rem = w & 31;
        const int h = rem >> 1;
        const int b = rem & 1;
        const int kvh = h / (NH / NKV);
        const int bh = b * NKV + kvh;

        __syncthreads();   // previous item's smem consumers done

        // load Q tile (both splits)
        {
            const size_t qrow0 = (size_t)(b * SEQ + qb * ATT_BQ);
            #pragma unroll
            for (int i = 0; i < 8; i++) {
                int id = tid + i * 256;
                int r = id >> 4, c = id & 15;
                size_t go = (qrow0 + r) * HIDDEN + (size_t)h * HD + c * 8;
                cpa16(base + OFF_QH + r * SQ_LDB + c * 16, qh + go);
                cpa16(base + OFF_QS + r * SQ_LDB + c * 16, qs + go);
            }
            cpa_commit();
        }
        const int mlen = (qb + 1) * ATT_BQ;
        for (int i = tid; i < mlen; i += 256)
            ((int*)(sm + OFF_MSK))[i] = amask[b * SEQ + i];

        const int nTiles = (qb + 1) * (ATT_BQ / ATT_BKV);   // (qb+1)*2

        auto loadKV = [&](int t, int buf) {
            const int kv0 = t * ATT_BKV;
            #pragma unroll
            for (int i = 0; i < 8; i++) {       // K: 2 splits x 64 rows x 16 chunks
                int id = tid + i * 256;
                int split = id >> 10, rem2 = id & 1023;
                int r = rem2 >> 4, c = rem2 & 15;
                const __half* src = split ? ks : kh;
                cpa16(base + OFF_K + (buf * 2 + split) * KTILE_B + r * SQ_LDB + c * 16,
                      src + (size_t)(b * SEQ + kv0 + r) * KVD + (size_t)kvh * HD + c * 8);
            }
            #pragma unroll
            for (int i = 0; i < 8; i++) {       // V: 2 splits x 128 rows x 8 chunks
                int id = tid + i * 256;
                int split = id >> 10, rem2 = id & 1023;
                int r = rem2 >> 3, c = rem2 & 7;
                const __half* src = split ? vts : vth;
                cpa16(base + OFF_VT + (buf * 2 + split) * VTILE_B + r * SV_LDB + c * 16,
                      src + (size_t)(bh * HD + r) * SEQ + kv0 + c * 8);
            }
            cpa_commit();
        };

        float O[16][4];
        #pragma unroll
        for (int i = 0; i < 16; i++)
            #pragma unroll
            for (int r = 0; r < 4; r++) O[i][r] = 0.f;
        float m0 = -1e30f, m1 = -1e30f, l0 = 0.f, l1 = 0.f;

        loadKV(0, 0);
        cpa_wait0();
        __syncthreads();

        const int rowg0 = qb * ATT_BQ + warp * 16 + (lane >> 2);
        const int rowg1 = rowg0 + 8;

        for (int t = 0; t < nTiles; t++) {
            const int buf = t & 1;
            const int kv0 = t * ATT_BKV;

            __syncthreads();
            if (t + 1 < nTiles) { loadKV(t + 1, buf ^ 1); cpa_wait1(); }
            else                { cpa_wait0(); }
            __syncthreads();

            const uint32_t kb_h = base + OFF_K + (buf * 2 + 0) * KTILE_B;
            const uint32_t kb_s = base + OFF_K + (buf * 2 + 1) * KTILE_B;

            // ---- S = Q K^T in two 32-col halves ----
            float sf[8][4];
            #pragma unroll
            for (int h32 = 0; h32 < 2; h32++) {
                float sh[4][4], ss[4][4];
                #pragma unroll
                for (int nt = 0; nt < 4; nt++)
                    #pragma unroll
                    for (int r = 0; r < 4; r++) { sh[nt][r] = 0.f; ss[nt][r] = 0.f; }

                #pragma unroll
                for (int ksI = 0; ksI < 8; ksI++) {
                    uint32_t ah[4], as_[4];
                    ldsm_x4(ah,  base + OFF_QH + aoffQ + ksI * 32);
                    ldsm_x4(as_, base + OFF_QS + aoffQ + ksI * 32);
                    #pragma unroll
                    for (int ntp = 0; ntp < 2; ntp++) {
                        const uint32_t roff = (uint32_t)((h32 * 2 + ntp) * 16 * SQ_LDB) + ksI * 32;
                        uint32_t tmp[4];
                        ldsm_x4(tmp, kb_h + boffK + roff);
                        { uint32_t b0[2] = {tmp[0], tmp[1]}, b1[2] = {tmp[2], tmp[3]};
                          mma_f16(sh[ntp * 2],     ah, b0);
                          mma_f16(sh[ntp * 2 + 1], ah, b1); }
                        ldsm_x4(tmp, kb_s + boffK + roff);
                        { uint32_t b0[2] = {tmp[0], tmp[1]}, b1[2] = {tmp[2], tmp[3]};
                          mma_f16(ss[ntp * 2],     as_, b0);
                          mma_f16(ss[ntp * 2 + 1], as_, b1); }
                    }
                }

                #pragma unroll
                for (int nt = 0; nt < 4; nt++)
                    #pragma unroll
                    for (int r = 0; r < 4; r++) {
                        float s = sh[nt][r] + (ss[nt][r] - sh[nt][r]) * SPLIT_SINV;
                        s *= scale;
                        int col = kv0 + h32 * 32 + nt * 8 + 2 * (lane & 3) + (r & 1);
                        int row = (r < 2) ? rowg0 : rowg1;
                        if (col > row || msk[col] == 0) s = -1e30f;
                        sf[h32 * 4 + nt][r] = s;
                    }
            }

            // online softmax over 64 columns
            float mx0 = m0, mx1 = m1;
            #pragma unroll
            for (int nt = 0; nt < 8; nt++) {
                mx0 = fmaxf(mx0, fmaxf(sf[nt][0], sf[nt][1]));
                mx1 = fmaxf(mx1, fmaxf(sf[nt][2], sf[nt][3]));
            }
            mx0 = fmaxf(mx0, __shfl_xor_sync(0xffffffffu, mx0, 1));
            mx0 = fmaxf(mx0, __shfl_xor_sync(0xffffffffu, mx0, 2));
            mx1 = fmaxf(mx1, __shfl_xor_sync(0xffffffffu, mx1, 1));
            mx1 = fmaxf(mx1, __shfl_xor_sync(0xffffffffu, mx1, 2));

            float sum0 = 0.f, sum1 = 0.f;
            #pragma unroll
            for (int nt = 0; nt < 8; nt++) {
                sf[nt][0] = __expf(sf[nt][0] - mx0);
                sf[nt][1] = __expf(sf[nt][1] - mx0);
                sf[nt][2] = __expf(sf[nt][2] - mx1);
                sf[nt][3] = __expf(sf[nt][3] - mx1);
                sum0 += sf[nt][0] + sf[nt][1];
                sum1 += sf[nt][2] + sf[nt][3];
            }
            sum0 += __shfl_xor_sync(0xffffffffu, sum0, 1);
            sum0 += __shfl_xor_sync(0xffffffffu, sum0, 2);
            sum1 += __shfl_xor_sync(0xffffffffu, sum1, 1);
            sum1 += __shfl_xor_sync(0xffffffffu, sum1, 2);

            float a0 = __expf(m0 - mx0), a1 = __expf(m1 - mx1);
            l0 = l0 * a0 + sum0;
            l1 = l1 * a1 + sum1;
            m0 = mx0; m1 = mx1;

            #pragma unroll
            for (int i = 0; i < 16; i++) {
                O[i][0] *= a0; O[i][1] *= a0;
                O[i][2] *= a1; O[i][3] *= a1;
            }

            // P fragments hi/sum: 4 k16 groups over 64 columns
            uint32_t pH[4][4], pS[4][4];
            #pragma unroll
            for (int g = 0; g < 4; g++) {
                int t0 = g * 2, t1 = t0 + 1;
                pH[g][0] = packh2 (sf[t0][0], sf[t0][1]);
                pH[g][1] = packh2 (sf[t0][2], sf[t0][3]);
                pH[g][2] = packh2 (sf[t1][0], sf[t1][1]);
                pH[g][3] = packh2 (sf[t1][2], sf[t1][3]);
                pS[g][0] = packh2s(sf[t0][0], sf[t0][1]);
                pS[g][1] = packh2s(sf[t0][2], sf[t0][3]);
                pS[g][2] = packh2s(sf[t1][0], sf[t1][1]);
                pS[g][3] = packh2s(sf[t1][2], sf[t1][3]);
            }

            // ---- O += P V ----
            const uint32_t vb_h = base + OFF_VT + (buf * 2 + 0) * VTILE_B;
            const uint32_t vb_s = base + OFF_VT + (buf * 2 + 1) * VTILE_B;
            #pragma unroll
            for (int ntp = 0; ntp < 8; ntp++) {
                float th[2][4], ts[2][4];
                #pragma unroll
                for (int j = 0; j < 2; j++)
                    #pragma unroll
                    for (int r = 0; r < 4; r++) { th[j][r] = 0.f; ts[j][r] = 0.f; }
                #pragma unroll
                for (int g = 0; g < 4; g++) {
                    uint32_t tmp[4];
                    ldsm_x4(tmp, vb_h + boffV + ntp * 16 * SV_LDB + g * 32);
                    { uint32_t b0[2] = {tmp[0], tmp[1]}, b1[2] = {tmp[2], tmp[3]};
                      mma_f16(th[0], pH[g], b0);
                      mma_f16(th[1], pH[g], b1); }
                    ldsm_x4(tmp, vb_s + boffV + ntp * 16 * SV_LDB + g * 32);
                    { uint32_t b0[2] = {tmp[0], tmp[1]}, b1[2] = {tmp[2], tmp[3]};
                      mma_f16(ts[0], pS[g], b0);
                      mma_f16(ts[1], pS[g], b1); }
                }
                #pragma unroll
                for (int j = 0; j < 2; j++)
                    #pragma unroll
                    for (int r = 0; r < 4; r++)
                        O[ntp * 2 + j][r] += th[j][r] + (ts[j][r] - th[j][r]) * SPLIT_SINV;
            }
        }

        // epilogue: normalize + plain fp16 output
        const float il0 = 1.f / l0, il1 = 1.f / l1;
        #pragma unroll
        for (int nt = 0; nt < 16; nt++) {
            int col = h * HD + nt * 8 + 2 * (lane & 3);
            size_t o0 = (size_t)(b * SEQ + rowg0) * HIDDEN + col;
            size_t o1 = (size_t)(b * SEQ + rowg1) * HIDDEN + col;
            *(uint32_t*)(aoh + o0) = packh2(O[nt][0] * il0, O[nt][1] * il0);
            *(uint32_t*)(aoh + o1) = packh2(O[nt][2] * il1, O[nt][3] * il1);
        }
    }
}

// ---------------- launch ----------------------------------------------------
extern "C" void kernel_launch(void* const* d_in, const int* in_sizes, int n_in,
                              void* d_out, int out_size)
{
    const float* hs    = (const float*)d_in[0];
    const int*   amask = (const int*)  d_in[1];
    const float* wq    = (const float*)d_in[2];
    const float* wk    = (const float*)d_in[3];
    const float* wv    = (const float*)d_in[4];
    const float* wo    = (const float*)d_in[5];
    float* out = (float*)d_out;

    float* qkv;
    cudaGetSymbolAddress((void**)&qkv, g_qkv);

    __half *hsh, *hss, *wqkvh, *wqkvs, *woh, *aoh;
    cudaGetSymbolAddress((void**)&hsh,   g_hsh);   cudaGetSymbolAddress((void**)&hss,   g_hss);
    cudaGetSymbolAddress((void**)&wqkvh, g_wqkvh); cudaGetSymbolAddress((void**)&wqkvs, g_wqkvs);
    cudaGetSymbolAddress((void**)&woh,   g_woh);
    cudaGetSymbolAddress((void**)&aoh,   g_aoh);

    __half *qh, *qs2, *kh, *ks2, *vth, *vts;
    cudaGetSymbolAddress((void**)&qh,  g_qh);  cudaGetSymbolAddress((void**)&qs2, g_qs2);
    cudaGetSymbolAddress((void**)&kh,  g_kh);  cudaGetSymbolAddress((void**)&ks2, g_ks2);
    cudaGetSymbolAddress((void**)&vth, g_vth); cudaGetSymbolAddress((void**)&vts, g_vts);

    cudaFuncSetAttribute(gemm_fp16x2, cudaFuncAttributeMaxDynamicSharedMemorySize, GSM);
    cudaFuncSetAttribute(gemm_plain,  cudaFuncAttributeMaxDynamicSharedMemorySize, PGSM);
    cudaFuncSetAttribute(attn_mma,    cudaFuncAttributeMaxDynamicSharedMemorySize, ATT_SM);

    // one fused split for all inputs (wo -> plain fp16 hi only)
    split_all<<<2048, 256>>>(hs, wq, wk, wv, wo, hsh, hss, wqkvh, wqkvs, woh);

    // single merged Q|K|V projection (2-MMA corrected)
    gemm_fp16x2<<<dim3(QKVOUT / 128, MTOT / 128), 512, GSM>>>(hsh, hss, wqkvh, wqkvs, qkv, QKVOUT);

    // fused RoPE + split (Q, K) and V transpose + split
    rope_split<<<MTOT / 4, 256>>>(qkv, qh, qs2, kh, ks2);
    transpose_split_v<<<dim3(SEQ / 32, HD / 32, BATCH * NKV), dim3(32, 8)>>>(qkv, vth, vts);

    // persistent MMA flash attention (writes plain fp16 output)
    attn_mma<<<ATT_GRID, 256, ATT_SM>>>(qh, qs2, kh, ks2, vth, vts, amask, aoh);

    // O-projection: plain fp16 single-MMA (final stage, unamplified error)
    gemm_plain<<<dim3(HIDDEN / 128, MTOT / 128), 512, PGSM>>>(aoh, woh, out, HIDDEN);
}

// round 15
// speedup vs baseline: 5.2194x; 1.0802x over previous
#include <cuda_runtime.h>
#include <cuda_fp16.h>
#include <math.h>
#include <stdint.h>

#define HIDDEN 2048
#define NH 16
#define NKV 4
#define HD 128
#define KVD 512
#define BATCH 2
#define SEQ 2048
#define MTOT (BATCH*SEQ)   // 4096
#define QKVOUT 3072        // merged Q|K|V projection output width

// ---------------- scratch (static device globals; no allocs allowed) -------
__device__ float g_qkv[(size_t)MTOT * QKVOUT];   // merged Q|K|V proj out (fp32)

// fp16 (hi, sum) operands: hi = fp16(x); sum = fp16(hi + 64*(x - hi))
__device__ __half g_hsh  [(size_t)MTOT * HIDDEN];
__device__ __half g_hss  [(size_t)MTOT * HIDDEN];
__device__ __half g_wqkvh[(size_t)QKVOUT * HIDDEN];
__device__ __half g_wqkvs[(size_t)QKVOUT * HIDDEN];
__device__ __half g_woh  [(size_t)HIDDEN * HIDDEN];   // plain fp16 (O-proj)
__device__ __half g_aoh  [(size_t)MTOT * HIDDEN];     // plain fp16 (O-proj)

// attention fp16 operands
__device__ __half g_qh [(size_t)MTOT * HIDDEN];
__device__ __half g_qs2[(size_t)MTOT * HIDDEN];
__device__ __half g_kh [(size_t)MTOT * KVD];
__device__ __half g_ks2[(size_t)MTOT * KVD];
__device__ __half g_vth[(size_t)BATCH * NKV * HD * SEQ];   // plain fp16 V^T

#define SPLIT_S 64.0f
#define SPLIT_SINV (1.0f / 64.0f)

// ---------------- helpers ---------------------------------------------------
__device__ __forceinline__ uint32_t smem_u32(const void* p) {
    return (uint32_t)__cvta_generic_to_shared(p);
}
__device__ __forceinline__ void cpa16(uint32_t smaddr, const void* g) {
    asm volatile("cp.async.cg.shared.global [%0], [%1], 16;" :: "r"(smaddr), "l"(g));
}
__device__ __forceinline__ void cpa_commit() { asm volatile("cp.async.commit_group;"); }
__device__ __forceinline__ void cpa_wait1()  { asm volatile("cp.async.wait_group 1;"); }
__device__ __forceinline__ void cpa_wait0()  { asm volatile("cp.async.wait_group 0;"); }

__device__ __forceinline__ void ldsm_x4(uint32_t* r, uint32_t addr) {
    asm volatile("ldmatrix.sync.aligned.m8n8.x4.shared.b16 {%0,%1,%2,%3}, [%4];"
                 : "=r"(r[0]), "=r"(r[1]), "=r"(r[2]), "=r"(r[3]) : "r"(addr));
}
__device__ __forceinline__ void mma_f16(float* d, const uint32_t* a, const uint32_t* b) {
    asm volatile(
        "mma.sync.aligned.m16n8k16.row.col.f32.f16.f16.f32 "
        "{%0,%1,%2,%3}, {%4,%5,%6,%7}, {%8,%9}, {%0,%1,%2,%3};"
        : "+f"(d[0]), "+f"(d[1]), "+f"(d[2]), "+f"(d[3])
        : "r"(a[0]), "r"(a[1]), "r"(a[2]), "r"(a[3]), "r"(b[0]), "r"(b[1]));
}
__device__ __forceinline__ uint32_t packh2(float x, float y) {
    __half2 v = __floats2half2_rn(x, y);
    return *reinterpret_cast<uint32_t*>(&v);
}
__device__ __forceinline__ void split1(float x, __half& h, __half& s) {
    h = __float2half(x);
    float hf = __half2float(h);
    s = __float2half(fmaf(SPLIT_S, x - hf, hf));
}

// ---------------- fused split kernel: all inputs in one launch --------------
__global__ __launch_bounds__(256) void split_all(
    const float* __restrict__ hs, const float* __restrict__ wq,
    const float* __restrict__ wk, const float* __restrict__ wv,
    const float* __restrict__ wo,
    __half* __restrict__ hsh, __half* __restrict__ hss,
    __half* __restrict__ wqkvh, __half* __restrict__ wqkvs,
    __half* __restrict__ woh)
{
    const int N_HS = MTOT * HIDDEN / 4;
    const int N_WQ = HIDDEN * HIDDEN / 4;
    const int N_WK = KVD * HIDDEN / 4;
    const int B1 = N_HS, B2 = B1 + N_WQ, B3 = B2 + N_WK, B4 = B3 + N_WK;
    const int total = B4 + N_WQ;

    for (int i = blockIdx.x * blockDim.x + threadIdx.x; i < total; i += gridDim.x * blockDim.x) {
        const float* src;
        __half *dh, *ds;
        int j;
        if (i < B1)      { j = i;      src = hs; dh = hsh;   ds = hss; }
        else if (i < B2) { j = i - B1; src = wq; dh = wqkvh; ds = wqkvs; }
        else if (i < B3) { j = i - B2; src = wk; dh = wqkvh + (size_t)HIDDEN * HIDDEN;
                                                 ds = wqkvs + (size_t)HIDDEN * HIDDEN; }
        else if (i < B4) { j = i - B3; src = wv; dh = wqkvh + (size_t)(HIDDEN + KVD) * HIDDEN;
                                                 ds = wqkvs + (size_t)(HIDDEN + KVD) * HIDDEN; }
        else             { j = i - B4; src = wo; dh = woh;   ds = 0; }

        float4 x = ((const float4*)src)[j];
        __half h0, h1, h2, h3, s0, s1, s2, s3;
        split1(x.x, h0, s0); split1(x.y, h1, s1);
        split1(x.z, h2, s2); split1(x.w, h3, s3);
        ((ushort4*)dh)[j] = make_ushort4(__half_as_ushort(h0), __half_as_ushort(h1),
                                         __half_as_ushort(h2), __half_as_ushort(h3));
        if (ds)
            ((ushort4*)ds)[j] = make_ushort4(__half_as_ushort(s0), __half_as_ushort(s1),
                                             __half_as_ushort(s2), __half_as_ushort(s3));
    }
}

// ---------------- fused RoPE + split: fp32 qkv -> fp16 hi/sum ---------------
__global__ __launch_bounds__(256) void rope_split(
    const float* __restrict__ qkv,
    __half* __restrict__ qh, __half* __restrict__ qs,
    __half* __restrict__ kh, __half* __restrict__ ks)
{
    const int bs  = blockIdx.x * 4 + (threadIdx.x >> 6);
    const int pos = bs % SEQ;
    const int i   = threadIdx.x & 63;  // pair index
    float inv = powf(10000.0f, -(float)i / 64.0f);
    float ang = (float)pos * inv;
    float s, c;
    sincosf(ang, &s, &c);

    #pragma unroll
    for (int h = 0; h < NH; h++) {
        const float* p = qkv + (size_t)bs * QKVOUT + h * HD;
        float a = p[i], b2 = p[i + 64];
        float r0 = a * c - b2 * s;
        float r1 = b2 * c + a * s;
        __half h0, s0, h1, s1;
        split1(r0, h0, s0); split1(r1, h1, s1);
        size_t o = (size_t)bs * HIDDEN + h * HD + i;
        qh[o] = h0; qs[o] = s0;
        qh[o + 64] = h1; qs[o + 64] = s1;
    }
    #pragma unroll
    for (int h = 0; h < NKV; h++) {
        const float* p = qkv + (size_t)bs * QKVOUT + HIDDEN + h * HD;   // K cols
        float a = p[i], b2 = p[i + 64];
        float r0 = a * c - b2 * s;
        float r1 = b2 * c + a * s;
        __half h0, s0, h1, s1;
        split1(r0, h0, s0); split1(r1, h1, s1);
        size_t o = (size_t)bs * KVD + h * HD + i;
        kh[o] = h0; ks[o] = s0;
        kh[o + 64] = h1; ks[o + 64] = s1;
    }
}

// ---------------- V transpose: qkv [s][2560+kvh*HD+d] -> fp16 [bh][d][s] ----
__global__ void transpose_v(const float* __restrict__ qkv,
                            __half* __restrict__ vth)
{
    __shared__ float tile[32][33];
    const int s0 = blockIdx.x * 32, d0 = blockIdx.y * 32;
    const int bh = blockIdx.z;
    const int b = bh / NKV, kvh = bh % NKV;
    const int tx = threadIdx.x, ty = threadIdx.y;   // 32 x 8

    #pragma unroll
    for (int i = 0; i < 4; i++) {
        int s = s0 + ty * 4 + i;
        tile[ty * 4 + i][tx] = qkv[(size_t)(b * SEQ + s) * QKVOUT + HIDDEN + KVD + kvh * HD + d0 + tx];
    }
    __syncthreads();
    #pragma unroll
    for (int i = 0; i < 4; i++) {
        int d = d0 + ty * 4 + i;
        vth[(size_t)(bh * HD + d) * SEQ + s0 + tx] = __float2half(tile[tx][ty * 4 + i]);
    }
}

// ============================================================================
// fp16 2-MMA corrected GEMM (R10 winner, used for QKV projection)
// ============================================================================
#define LDH 40
#define LDB (LDH * 2)
#define ARR (128 * LDB)
#define BUFB (4 * ARR)
#define GSM (2 * BUFB)

__global__ __launch_bounds__(512) void gemm_fp16x2(
    const __half* __restrict__ Ah_, const __half* __restrict__ As_,
    const __half* __restrict__ Bh_, const __half* __restrict__ Bs_,
    float* __restrict__ C, int N)
{
    extern __shared__ char dsm[];
    const uint32_t base = smem_u32(dsm);

    const int tid  = threadIdx.x;
    const int warp = tid >> 5, lane = tid & 31;
    const int wr = warp & 3, wc = warp >> 2;
    const int row0 = blockIdx.y * 128;
    const int col0 = blockIdx.x * 128;

    const char* src[4] = {
        (const char*)(Ah_ + (size_t)row0 * HIDDEN),
        (const char*)(As_ + (size_t)row0 * HIDDEN),
        (const char*)(Bh_ + (size_t)col0 * HIDDEN),
        (const char*)(Bs_ + (size_t)col0 * HIDDEN)
    };

    const int nChunk = HIDDEN / 32;

    const int lr = tid >> 2;
    const int lc = tid & 3;
    auto loadTile = [&](int t, int buf) {
        #pragma unroll
        for (int a = 0; a < 4; a++) {
            cpa16(base + buf * BUFB + a * ARR + lr * LDB + lc * 16,
                  src[a] + ((size_t)lr * HIDDEN + t * 32) * 2 + lc * 16);
        }
        cpa_commit();
    };

    float acch[2][4][4], accs[2][4][4];
    #pragma unroll
    for (int mi = 0; mi < 2; mi++)
        #pragma unroll
        for (int ni = 0; ni < 4; ni++)
            #pragma unroll
            for (int r = 0; r < 4; r++) { acch[mi][ni][r] = 0.f; accs[mi][ni][r] = 0.f; }

    const uint32_t aoffA = (uint32_t)((wr * 32 + (lane & 15)) * LDB + ((lane >> 4) << 3) * 2);
    const uint32_t aoffB = (uint32_t)((wc * 32 + ((lane >> 4) << 3) + (lane & 7)) * LDB
                                      + (((lane >> 3) & 1) << 3) * 2);

    loadTile(0, 0);

    for (int t = 0; t < nChunk; t++) {
        const int buf = t & 1;
        if (t + 1 < nChunk) { loadTile(t + 1, buf ^ 1); cpa_wait1(); }
        else                { cpa_wait0(); }
        __syncthreads();

        const uint32_t bo = base + buf * BUFB;

        #pragma unroll
        for (int ks = 0; ks < 2; ks++) {
            const uint32_t kb = (uint32_t)(ks * 32);

            uint32_t ah[2][4], as_[2][4];
            ldsm_x4(ah[0],  bo + 0 * ARR + aoffA + kb);
            ldsm_x4(ah[1],  bo + 0 * ARR + aoffA + kb + 16 * LDB);
            ldsm_x4(as_[0], bo + 1 * ARR + aoffA + kb);
            ldsm_x4(as_[1], bo + 1 * ARR + aoffA + kb + 16 * LDB);

            uint32_t bh[4][2], bs[4][2], tmp[4];
            ldsm_x4(tmp, bo + 2 * ARR + aoffB + kb);
            bh[0][0] = tmp[0]; bh[0][1] = tmp[1]; bh[1][0] = tmp[2]; bh[1][1] = tmp[3];
            ldsm_x4(tmp, bo + 2 * ARR + aoffB + kb + 16 * LDB);
            bh[2][0] = tmp[0]; bh[2][1] = tmp[1]; bh[3][0] = tmp[2]; bh[3][1] = tmp[3];
            ldsm_x4(tmp, bo + 3 * ARR + aoffB + kb);
            bs[0][0] = tmp[0]; bs[0][1] = tmp[1]; bs[1][0] = tmp[2]; bs[1][1] = tmp[3];
            ldsm_x4(tmp, bo + 3 * ARR + aoffB + kb + 16 * LDB);
            bs[2][0] = tmp[0]; bs[2][1] = tmp[1]; bs[3][0] = tmp[2]; bs[3][1] = tmp[3];

            #pragma unroll
            for (int mi = 0; mi < 2; mi++)
                #pragma unroll
                for (int ni = 0; ni < 4; ni++) {
                    mma_f16(acch[mi][ni], ah[mi],  bh[ni]);
                    mma_f16(accs[mi][ni], as_[mi], bs[ni]);
                }
        }
        __syncthreads();
    }

    #pragma unroll
    for (int mi = 0; mi < 2; mi++)
        #pragma unroll
        for (int ni = 0; ni < 4; ni++) {
            const int row = row0 + wr * 32 + mi * 16 + (lane >> 2);
            const int col = col0 + wc * 32 + ni * 8 + 2 * (lane & 3);
            float v0 = acch[mi][ni][0] + (accs[mi][ni][0] - acch[mi][ni][0]) * SPLIT_SINV;
            float v1 = acch[mi][ni][1] + (accs[mi][ni][1] - acch[mi][ni][1]) * SPLIT_SINV;
            float v2 = acch[mi][ni][2] + (accs[mi][ni][2] - acch[mi][ni][2]) * SPLIT_SINV;
            float v3 = acch[mi][ni][3] + (accs[mi][ni][3] - acch[mi][ni][3]) * SPLIT_SINV;
            *(float2*)(C + (size_t)row * N + col)       = make_float2(v0, v1);
            *(float2*)(C + (size_t)(row + 8) * N + col) = make_float2(v2, v3);
        }
}

// ============================================================================
// Plain fp16 GEMM (single MMA, no correction) — O-projection (final stage)
// ============================================================================
#define PLDB 144                 // 64 halfs + 16B pad
#define PARR (128 * PLDB)        // 18432
#define PBUF (2 * PARR)          // 36864
#define PGSM (2 * PBUF)          // 73728

__global__ __launch_bounds__(512) void gemm_plain(
    const __half* __restrict__ Ah_, const __half* __restrict__ Bh_,
    float* __restrict__ C, int N)
{
    extern __shared__ char dsm[];
    const uint32_t base = smem_u32(dsm);

    const int tid  = threadIdx.x;
    const int warp = tid >> 5, lane = tid & 31;
    const int wr = warp & 3, wc = warp >> 2;
    const int row0 = blockIdx.y * 128;
    const int col0 = blockIdx.x * 128;

    const char* srcA = (const char*)(Ah_ + (size_t)row0 * HIDDEN);
    const char* srcB = (const char*)(Bh_ + (size_t)col0 * HIDDEN);

    const int nChunk = HIDDEN / 64;    // 32

    auto loadTile = [&](int t, int buf) {
        #pragma unroll
        for (int i = 0; i < 2; i++) {
            int idx = tid + i * 512;        // 0..1023
            int r = idx >> 3, c = idx & 7;
            size_t go = ((size_t)r * HIDDEN + t * 64) * 2 + c * 16;
            cpa16(base + buf * PBUF + 0 * PARR + r * PLDB + c * 16, srcA + go);
            cpa16(base + buf * PBUF + 1 * PARR + r * PLDB + c * 16, srcB + go);
        }
        cpa_commit();
    };

    float acc[2][4][4];
    #pragma unroll
    for (int mi = 0; mi < 2; mi++)
        #pragma unroll
        for (int ni = 0; ni < 4; ni++)
            #pragma unroll
            for (int r = 0; r < 4; r++) acc[mi][ni][r] = 0.f;

    const uint32_t aoffA = (uint32_t)((wr * 32 + (lane & 15)) * PLDB + ((lane >> 4) << 4));
    const uint32_t aoffB = (uint32_t)((wc * 32 + ((lane >> 4) << 3) + (lane & 7)) * PLDB
                                      + (((lane >> 3) & 1) << 4));

    loadTile(0, 0);

    for (int t = 0; t < nChunk; t++) {
        const int buf = t & 1;
        if (t + 1 < nChunk) { loadTile(t + 1, buf ^ 1); cpa_wait1(); }
        else                { cpa_wait0(); }
        __syncthreads();

        const uint32_t bo = base + buf * PBUF;

        #pragma unroll
        for (int ks = 0; ks < 4; ks++) {
            const uint32_t kb = (uint32_t)(ks * 32);

            uint32_t ah[2][4];
            ldsm_x4(ah[0], bo + 0 * PARR + aoffA + kb);
            ldsm_x4(ah[1], bo + 0 * PARR + aoffA + kb + 16 * PLDB);

            uint32_t bh[4][2], tmp[4];
            ldsm_x4(tmp, bo + 1 * PARR + aoffB + kb);
            bh[0][0] = tmp[0]; bh[0][1] = tmp[1]; bh[1][0] = tmp[2]; bh[1][1] = tmp[3];
            ldsm_x4(tmp, bo + 1 * PARR + aoffB + kb + 16 * PLDB);
            bh[2][0] = tmp[0]; bh[2][1] = tmp[1]; bh[3][0] = tmp[2]; bh[3][1] = tmp[3];

            #pragma unroll
            for (int mi = 0; mi < 2; mi++)
                #pragma unroll
                for (int ni = 0; ni < 4; ni++)
                    mma_f16(acc[mi][ni], ah[mi], bh[ni]);
        }
        __syncthreads();
    }

    #pragma unroll
    for (int mi = 0; mi < 2; mi++)
        #pragma unroll
        for (int ni = 0; ni < 4; ni++) {
            const int row = row0 + wr * 32 + mi * 16 + (lane >> 2);
            const int col = col0 + wc * 32 + ni * 8 + 2 * (lane & 3);
            *(float2*)(C + (size_t)row * N + col)       = make_float2(acc[mi][ni][0], acc[mi][ni][1]);
            *(float2*)(C + (size_t)(row + 8) * N + col) = make_float2(acc[mi][ni][2], acc[mi][ni][3]);
        }
}

// ============================================================================
// Persistent MMA flash attention (causal, GQA)
// QK^T: fp16 2-MMA split. PV: plain fp16 (P>=0 convex combination, unamplified).
// ============================================================================
#define ATT_BQ 128
#define ATT_BKV 64
#define ATT_GRID 148
#define N_ITEMS 512             // 16 qb x 16 h x 2 b
#define SQ_LDB 272              // 128 halfs + 16B pad
#define SV_LDB 144              // 64 halfs + 16B pad
#define KTILE_B 17408           // 64 * SQ_LDB
#define VTILE_B 18432           // 128 * SV_LDB
#define OFF_QH 0
#define OFF_QS 34816
#define OFF_K  69632            // + (buf*2+split)*KTILE_B  -> 4 tiles
#define OFF_VT 139264           // + buf*VTILE_B            -> 2 tiles
#define OFF_MSK 176128
#define ATT_SM 184320

__global__ __launch_bounds__(256) void attn_mma(
    const __half* __restrict__ qh,  const __half* __restrict__ qs,
    const __half* __restrict__ kh,  const __half* __restrict__ ks,
    const __half* __restrict__ vth,
    const int* __restrict__ amask,
    __half* __restrict__ aoh)
{
    extern __shared__ char sm[];
    const uint32_t base = smem_u32(sm);
    const int cta = blockIdx.x;
    const int tid = threadIdx.x, warp = tid >> 5, lane = tid & 31;
    const float scale = 0.08838834764831845f;

    const uint32_t aoffQ = (uint32_t)((warp * 16 + (lane & 15)) * SQ_LDB + ((lane >> 4) << 4));
    const uint32_t boffK = (uint32_t)(((lane >> 4) * 8 + (lane & 7)) * SQ_LDB + (((lane >> 3) & 1) << 4));
    const uint32_t boffV = (uint32_t)(((lane >> 4) * 8 + (lane & 7)) * SV_LDB + (((lane >> 3) & 1) << 4));
    const int* msk = (const int*)(sm + OFF_MSK);

    for (int p = 0; p < (N_ITEMS + ATT_GRID - 1) / ATT_GRID; p++) {
        const int w = p * ATT_GRID + ((p & 1) ? (ATT_GRID - 1 - cta) : cta);
        if (w >= N_ITEMS) continue;
        const int qb = 15 - (w >> 5);          // descending-qb order
        const int rem = w & 31;
        const int h = rem >> 1;
        const int b = rem & 1;
        const int kvh = h / (NH / NKV);
        const int bh = b * NKV + kvh;

        __syncthreads();   // previous item's smem consumers done

        // load Q tile (both splits)
        {
            const size_t qrow0 = (size_t)(b * SEQ + qb * ATT_BQ);
            #pragma unroll
            for (int i = 0; i < 8; i++) {
                int id = tid + i * 256;
                int r = id >> 4, c = id & 15;
                size_t go = (qrow0 + r) * HIDDEN + (size_t)h * HD + c * 8;
                cpa16(base + OFF_QH + r * SQ_LDB + c * 16, qh + go);
                cpa16(base + OFF_QS + r * SQ_LDB + c * 16, qs + go);
            }
            cpa_commit();
        }
        const int mlen = (qb + 1) * ATT_BQ;
        for (int i = tid; i < mlen; i += 256)
            ((int*)(sm + OFF_MSK))[i] = amask[b * SEQ + i];

        const int nTiles = (qb + 1) * (ATT_BQ / ATT_BKV);   // (qb+1)*2

        auto loadKV = [&](int t, int buf) {
            const int kv0 = t * ATT_BKV;
            #pragma unroll
            for (int i = 0; i < 8; i++) {       // K: 2 splits x 64 rows x 16 chunks
                int id = tid + i * 256;
                int split = id >> 10, rem2 = id & 1023;
                int r = rem2 >> 4, c = rem2 & 15;
                const __half* src = split ? ks : kh;
                cpa16(base + OFF_K + (buf * 2 + split) * KTILE_B + r * SQ_LDB + c * 16,
                      src + (size_t)(b * SEQ + kv0 + r) * KVD + (size_t)kvh * HD + c * 8);
            }
            #pragma unroll
            for (int i = 0; i < 4; i++) {       // V: 128 rows x 8 chunks (plain)
                int id = tid + i * 256;
                int r = id >> 3, c = id & 7;
                cpa16(base + OFF_VT + buf * VTILE_B + r * SV_LDB + c * 16,
                      vth + (size_t)(bh * HD + r) * SEQ + kv0 + c * 8);
            }
            cpa_commit();
        };

        float O[16][4];
        #pragma unroll
        for (int i = 0; i < 16; i++)
            #pragma unroll
            for (int r = 0; r < 4; r++) O[i][r] = 0.f;
        float m0 = -1e30f, m1 = -1e30f, l0 = 0.f, l1 = 0.f;

        loadKV(0, 0);
        cpa_wait0();
        __syncthreads();

        const int rowg0 = qb * ATT_BQ + warp * 16 + (lane >> 2);
        const int rowg1 = rowg0 + 8;

        for (int t = 0; t < nTiles; t++) {
            const int buf = t & 1;
            const int kv0 = t * ATT_BKV;

            __syncthreads();
            if (t + 1 < nTiles) { loadKV(t + 1, buf ^ 1); cpa_wait1(); }
            else                { cpa_wait0(); }
            __syncthreads();

            const uint32_t kb_h = base + OFF_K + (buf * 2 + 0) * KTILE_B;
            const uint32_t kb_s = base + OFF_K + (buf * 2 + 1) * KTILE_B;

            // ---- S = Q K^T in two 32-col halves (2-MMA split) ----
            float sf[8][4];
            #pragma unroll
            for (int h32 = 0; h32 < 2; h32++) {
                float sh[4][4], ss[4][4];
                #pragma unroll
                for (int nt = 0; nt < 4; nt++)
                    #pragma unroll
                    for (int r = 0; r < 4; r++) { sh[nt][r] = 0.f; ss[nt][r] = 0.f; }

                #pragma unroll
                for (int ksI = 0; ksI < 8; ksI++) {
                    uint32_t ah[4], as_[4];
                    ldsm_x4(ah,  base + OFF_QH + aoffQ + ksI * 32);
                    ldsm_x4(as_, base + OFF_QS + aoffQ + ksI * 32);
                    #pragma unroll
                    for (int ntp = 0; ntp < 2; ntp++) {
                        const uint32_t roff = (uint32_t)((h32 * 2 + ntp) * 16 * SQ_LDB) + ksI * 32;
                        uint32_t tmp[4];
                        ldsm_x4(tmp, kb_h + boffK + roff);
                        { uint32_t b0[2] = {tmp[0], tmp[1]}, b1[2] = {tmp[2], tmp[3]};
                          mma_f16(sh[ntp * 2],     ah, b0);
                          mma_f16(sh[ntp * 2 + 1], ah, b1); }
                        ldsm_x4(tmp, kb_s + boffK + roff);
                        { uint32_t b0[2] = {tmp[0], tmp[1]}, b1[2] = {tmp[2], tmp[3]};
                          mma_f16(ss[ntp * 2],     as_, b0);
                          mma_f16(ss[ntp * 2 + 1], as_, b1); }
                    }
                }

                #pragma unroll
                for (int nt = 0; nt < 4; nt++)
                    #pragma unroll
                    for (int r = 0; r < 4; r++) {
                        float s = sh[nt][r] + (ss[nt][r] - sh[nt][r]) * SPLIT_SINV;
                        s *= scale;
                        int col = kv0 + h32 * 32 + nt * 8 + 2 * (lane & 3) + (r & 1);
                        int row = (r < 2) ? rowg0 : rowg1;
                        if (col > row || msk[col] == 0) s = -1e30f;
                        sf[h32 * 4 + nt][r] = s;
                    }
            }

            // online softmax over 64 columns
            float mx0 = m0, mx1 = m1;
            #pragma unroll
            for (int nt = 0; nt < 8; nt++) {
                mx0 = fmaxf(mx0, fmaxf(sf[nt][0], sf[nt][1]));
                mx1 = fmaxf(mx1, fmaxf(sf[nt][2], sf[nt][3]));
            }
            mx0 = fmaxf(mx0, __shfl_xor_sync(0xffffffffu, mx0, 1));
            mx0 = fmaxf(mx0, __shfl_xor_sync(0xffffffffu, mx0, 2));
            mx1 = fmaxf(mx1, __shfl_xor_sync(0xffffffffu, mx1, 1));
            mx1 = fmaxf(mx1, __shfl_xor_sync(0xffffffffu, mx1, 2));

            float sum0 = 0.f, sum1 = 0.f;
            #pragma unroll
            for (int nt = 0; nt < 8; nt++) {
                sf[nt][0] = __expf(sf[nt][0] - mx0);
                sf[nt][1] = __expf(sf[nt][1] - mx0);
                sf[nt][2] = __expf(sf[nt][2] - mx1);
                sf[nt][3] = __expf(sf[nt][3] - mx1);
                sum0 += sf[nt][0] + sf[nt][1];
                sum1 += sf[nt][2] + sf[nt][3];
            }
            sum0 += __shfl_xor_sync(0xffffffffu, sum0, 1);
            sum0 += __shfl_xor_sync(0xffffffffu, sum0, 2);
            sum1 += __shfl_xor_sync(0xffffffffu, sum1, 1);
            sum1 += __shfl_xor_sync(0xffffffffu, sum1, 2);

            float a0 = __expf(m0 - mx0), a1 = __expf(m1 - mx1);
            l0 = l0 * a0 + sum0;
            l1 = l1 * a1 + sum1;
            m0 = mx0; m1 = mx1;

            #pragma unroll
            for (int i = 0; i < 16; i++) {
                O[i][0] *= a0; O[i][1] *= a0;
                O[i][2] *= a1; O[i][3] *= a1;
            }

            // P fragments (plain fp16): 4 k16 groups over 64 columns
            uint32_t pH[4][4];
            #pragma unroll
            for (int g = 0; g < 4; g++) {
                int t0 = g * 2, t1 = t0 + 1;
                pH[g][0] = packh2(sf[t0][0], sf[t0][1]);
                pH[g][1] = packh2(sf[t0][2], sf[t0][3]);
                pH[g][2] = packh2(sf[t1][0], sf[t1][1]);
                pH[g][3] = packh2(sf[t1][2], sf[t1][3]);
            }

            // ---- O += P V (plain fp16, direct accumulate) ----
            const uint32_t vb = base + OFF_VT + buf * VTILE_B;
            #pragma unroll
            for (int ntp = 0; ntp < 8; ntp++) {
                #pragma unroll
                for (int g = 0; g < 4; g++) {
                    uint32_t tmp[4];
                    ldsm_x4(tmp, vb + boffV + ntp * 16 * SV_LDB + g * 32);
                    uint32_t b0[2] = {tmp[0], tmp[1]}, b1[2] = {tmp[2], tmp[3]};
                    mma_f16(O[ntp * 2],     pH[g], b0);
                    mma_f16(O[ntp * 2 + 1], pH[g], b1);
                }
            }
        }

        // epilogue: normalize + plain fp16 output
        const float il0 = 1.f / l0, il1 = 1.f / l1;
        #pragma unroll
        for (int nt = 0; nt < 16; nt++) {
            int col = h * HD + nt * 8 + 2 * (lane & 3);
            size_t o0 = (size_t)(b * SEQ + rowg0) * HIDDEN + col;
            size_t o1 = (size_t)(b * SEQ + rowg1) * HIDDEN + col;
            *(uint32_t*)(aoh + o0) = packh2(O[nt][0] * il0, O[nt][1] * il0);
            *(uint32_t*)(aoh + o1) = packh2(O[nt][2] * il1, O[nt][3] * il1);
        }
    }
}

// ---------------- launch ----------------------------------------------------
extern "C" void kernel_launch(void* const* d_in, const int* in_sizes, int n_in,
                              void* d_out, int out_size)
{
    const float* hs    = (const float*)d_in[0];
    const int*   amask = (const int*)  d_in[1];
    const float* wq    = (const float*)d_in[2];
    const float* wk    = (const float*)d_in[3];
    const float* wv    = (const float*)d_in[4];
    const float* wo    = (const float*)d_in[5];
    float* out = (float*)d_out;

    float* qkv;
    cudaGetSymbolAddress((void**)&qkv, g_qkv);

    __half *hsh, *hss, *wqkvh, *wqkvs, *woh, *aoh;
    cudaGetSymbolAddress((void**)&hsh,   g_hsh);   cudaGetSymbolAddress((void**)&hss,   g_hss);
    cudaGetSymbolAddress((void**)&wqkvh, g_wqkvh); cudaGetSymbolAddress((void**)&wqkvs, g_wqkvs);
    cudaGetSymbolAddress((void**)&woh,   g_woh);
    cudaGetSymbolAddress((void**)&aoh,   g_aoh);

    __half *qh, *qs2, *kh, *ks2, *vth;
    cudaGetSymbolAddress((void**)&qh,  g_qh);  cudaGetSymbolAddress((void**)&qs2, g_qs2);
    cudaGetSymbolAddress((void**)&kh,  g_kh);  cudaGetSymbolAddress((void**)&ks2, g_ks2);
    cudaGetSymbolAddress((void**)&vth, g_vth);

    cudaFuncSetAttribute(gemm_fp16x2, cudaFuncAttributeMaxDynamicSharedMemorySize, GSM);
    cudaFuncSetAttribute(gemm_plain,  cudaFuncAttributeMaxDynamicSharedMemorySize, PGSM);
    cudaFuncSetAttribute(attn_mma,    cudaFuncAttributeMaxDynamicSharedMemorySize, ATT_SM);

    // one fused split for all inputs (wo -> plain fp16 hi only)
    split_all<<<2048, 256>>>(hs, wq, wk, wv, wo, hsh, hss, wqkvh, wqkvs, woh);

    // single merged Q|K|V projection (2-MMA corrected)
    gemm_fp16x2<<<dim3(QKVOUT / 128, MTOT / 128), 512, GSM>>>(hsh, hss, wqkvh, wqkvs, qkv, QKVOUT);

    // fused RoPE + split (Q, K) and V transpose (plain fp16)
    rope_split<<<MTOT / 4, 256>>>(qkv, qh, qs2, kh, ks2);
    transpose_v<<<dim3(SEQ / 32, HD / 32, BATCH * NKV), dim3(32, 8)>>>(qkv, vth);

    // persistent MMA flash attention (QK split, PV plain; writes plain fp16)
    attn_mma<<<ATT_GRID, 256, ATT_SM>>>(qh, qs2, kh, ks2, vth, amask, aoh);

    // O-projection: plain fp16 single-MMA (final stage)
    gemm_plain<<<dim3(HIDDEN / 128, MTOT / 128), 512, PGSM>>>(aoh, woh, out, HIDDEN);
}

// round 16
// speedup vs baseline: 5.9063x; 1.1316x over previous
#include <cuda_runtime.h>
#include <cuda_fp16.h>
#include <math.h>
#include <stdint.h>

#define HIDDEN 2048
#define NH 16
#define NKV 4
#define HD 128
#define KVD 512
#define BATCH 2
#define SEQ 2048
#define MTOT (BATCH*SEQ)   // 4096
#define QKOUT 2560         // merged Q|K projection output width

// ---------------- scratch (static device globals; no allocs allowed) -------
__device__ float g_qk[(size_t)MTOT * QKOUT];     // merged Q|K proj out (fp32)
__device__ float g_v [(size_t)MTOT * KVD];       // V proj out (fp32)

// fp16 (hi, sum) operands: hi = fp16(x); sum = fp16(hi + 64*(x - hi))
__device__ __half g_hsh [(size_t)MTOT * HIDDEN];
__device__ __half g_hss [(size_t)MTOT * HIDDEN];
__device__ __half g_wqkh[(size_t)QKOUT * HIDDEN];
__device__ __half g_wqks[(size_t)QKOUT * HIDDEN];
__device__ __half g_wvh [(size_t)KVD * HIDDEN];       // plain fp16 (V-proj)
__device__ __half g_woh [(size_t)HIDDEN * HIDDEN];    // plain fp16 (O-proj)
__device__ __half g_aoh [(size_t)MTOT * HIDDEN];      // plain fp16 (O-proj in)

// attention fp16 operands (all plain)
__device__ __half g_qh [(size_t)MTOT * HIDDEN];
__device__ __half g_kh [(size_t)MTOT * KVD];
__device__ __half g_vth[(size_t)BATCH * NKV * HD * SEQ];

#define SPLIT_S 64.0f
#define SPLIT_SINV (1.0f / 64.0f)

// ---------------- helpers ---------------------------------------------------
__device__ __forceinline__ uint32_t smem_u32(const void* p) {
    return (uint32_t)__cvta_generic_to_shared(p);
}
__device__ __forceinline__ void cpa16(uint32_t smaddr, const void* g) {
    asm volatile("cp.async.cg.shared.global [%0], [%1], 16;" :: "r"(smaddr), "l"(g));
}
__device__ __forceinline__ void cpa_commit() { asm volatile("cp.async.commit_group;"); }
__device__ __forceinline__ void cpa_wait1()  { asm volatile("cp.async.wait_group 1;"); }
__device__ __forceinline__ void cpa_wait0()  { asm volatile("cp.async.wait_group 0;"); }

__device__ __forceinline__ void ldsm_x4(uint32_t* r, uint32_t addr) {
    asm volatile("ldmatrix.sync.aligned.m8n8.x4.shared.b16 {%0,%1,%2,%3}, [%4];"
                 : "=r"(r[0]), "=r"(r[1]), "=r"(r[2]), "=r"(r[3]) : "r"(addr));
}
__device__ __forceinline__ void mma_f16(float* d, const uint32_t* a, const uint32_t* b) {
    asm volatile(
        "mma.sync.aligned.m16n8k16.row.col.f32.f16.f16.f32 "
        "{%0,%1,%2,%3}, {%4,%5,%6,%7}, {%8,%9}, {%0,%1,%2,%3};"
        : "+f"(d[0]), "+f"(d[1]), "+f"(d[2]), "+f"(d[3])
        : "r"(a[0]), "r"(a[1]), "r"(a[2]), "r"(a[3]), "r"(b[0]), "r"(b[1]));
}
__device__ __forceinline__ uint32_t packh2(float x, float y) {
    __half2 v = __floats2half2_rn(x, y);
    return *reinterpret_cast<uint32_t*>(&v);
}
__device__ __forceinline__ void split1(float x, __half& h, __half& s) {
    h = __float2half(x);
    float hf = __half2float(h);
    s = __float2half(fmaf(SPLIT_S, x - hf, hf));
}

// ---------------- fused split kernel: all inputs in one launch --------------
// hs -> split; [wq|wk] -> split merged; wv -> plain; wo -> plain
__global__ __launch_bounds__(256) void split_all(
    const float* __restrict__ hs, const float* __restrict__ wq,
    const float* __restrict__ wk, const float* __restrict__ wv,
    const float* __restrict__ wo,
    __half* __restrict__ hsh, __half* __restrict__ hss,
    __half* __restrict__ wqkh, __half* __restrict__ wqks,
    __half* __restrict__ wvh, __half* __restrict__ woh)
{
    const int N_HS = MTOT * HIDDEN / 4;
    const int N_WQ = HIDDEN * HIDDEN / 4;
    const int N_WK = KVD * HIDDEN / 4;
    const int B1 = N_HS, B2 = B1 + N_WQ, B3 = B2 + N_WK, B4 = B3 + N_WK;
    const int total = B4 + N_WQ;

    for (int i = blockIdx.x * blockDim.x + threadIdx.x; i < total; i += gridDim.x * blockDim.x) {
        const float* src;
        __half *dh, *ds;
        int j;
        if (i < B1)      { j = i;      src = hs; dh = hsh;  ds = hss; }
        else if (i < B2) { j = i - B1; src = wq; dh = wqkh; ds = wqks; }
        else if (i < B3) { j = i - B2; src = wk; dh = wqkh + (size_t)HIDDEN * HIDDEN;
                                                 ds = wqks + (size_t)HIDDEN * HIDDEN; }
        else if (i < B4) { j = i - B3; src = wv; dh = wvh;  ds = 0; }
        else             { j = i - B4; src = wo; dh = woh;  ds = 0; }

        float4 x = ((const float4*)src)[j];
        __half h0, h1, h2, h3, s0, s1, s2, s3;
        split1(x.x, h0, s0); split1(x.y, h1, s1);
        split1(x.z, h2, s2); split1(x.w, h3, s3);
        ((ushort4*)dh)[j] = make_ushort4(__half_as_ushort(h0), __half_as_ushort(h1),
                                         __half_as_ushort(h2), __half_as_ushort(h3));
        if (ds)
            ((ushort4*)ds)[j] = make_ushort4(__half_as_ushort(s0), __half_as_ushort(s1),
                                             __half_as_ushort(s2), __half_as_ushort(s3));
    }
}

// ---------------- fused RoPE: fp32 qk -> plain fp16 q/k ---------------------
__global__ __launch_bounds__(256) void rope_plain(
    const float* __restrict__ qk,
    __half* __restrict__ qh, __half* __restrict__ kh)
{
    const int bs  = blockIdx.x * 4 + (threadIdx.x >> 6);
    const int pos = bs % SEQ;
    const int i   = threadIdx.x & 63;  // pair index
    float inv = powf(10000.0f, -(float)i / 64.0f);
    float ang = (float)pos * inv;
    float s, c;
    sincosf(ang, &s, &c);

    #pragma unroll
    for (int h = 0; h < NH; h++) {
        const float* p = qk + (size_t)bs * QKOUT + h * HD;
        float a = p[i], b2 = p[i + 64];
        size_t o = (size_t)bs * HIDDEN + h * HD + i;
        qh[o]      = __float2half(a * c - b2 * s);
        qh[o + 64] = __float2half(b2 * c + a * s);
    }
    #pragma unroll
    for (int h = 0; h < NKV; h++) {
        const float* p = qk + (size_t)bs * QKOUT + HIDDEN + h * HD;   // K cols
        float a = p[i], b2 = p[i + 64];
        size_t o = (size_t)bs * KVD + h * HD + i;
        kh[o]      = __float2half(a * c - b2 * s);
        kh[o + 64] = __float2half(b2 * c + a * s);
    }
}

// ---------------- V transpose: v [s][kvh*HD+d] -> fp16 [bh][d][s] -----------
__global__ void transpose_v(const float* __restrict__ v,
                            __half* __restrict__ vth)
{
    __shared__ float tile[32][33];
    const int s0 = blockIdx.x * 32, d0 = blockIdx.y * 32;
    const int bh = blockIdx.z;
    const int b = bh / NKV, kvh = bh % NKV;
    const int tx = threadIdx.x, ty = threadIdx.y;   // 32 x 8

    #pragma unroll
    for (int i = 0; i < 4; i++) {
        int s = s0 + ty * 4 + i;
        tile[ty * 4 + i][tx] = v[(size_t)(b * SEQ + s) * KVD + kvh * HD + d0 + tx];
    }
    __syncthreads();
    #pragma unroll
    for (int i = 0; i < 4; i++) {
        int d = d0 + ty * 4 + i;
        vth[(size_t)(bh * HD + d) * SEQ + s0 + tx] = __float2half(tile[tx][ty * 4 + i]);
    }
}

// ============================================================================
// fp16 2-MMA corrected GEMM (QK projection)
// ============================================================================
#define LDH 40
#define LDB (LDH * 2)
#define ARR (128 * LDB)
#define BUFB (4 * ARR)
#define GSM (2 * BUFB)

__global__ __launch_bounds__(512) void gemm_fp16x2(
    const __half* __restrict__ Ah_, const __half* __restrict__ As_,
    const __half* __restrict__ Bh_, const __half* __restrict__ Bs_,
    float* __restrict__ C, int N)
{
    extern __shared__ char dsm[];
    const uint32_t base = smem_u32(dsm);

    const int tid  = threadIdx.x;
    const int warp = tid >> 5, lane = tid & 31;
    const int wr = warp & 3, wc = warp >> 2;
    const int row0 = blockIdx.y * 128;
    const int col0 = blockIdx.x * 128;

    const char* src[4] = {
        (const char*)(Ah_ + (size_t)row0 * HIDDEN),
        (const char*)(As_ + (size_t)row0 * HIDDEN),
        (const char*)(Bh_ + (size_t)col0 * HIDDEN),
        (const char*)(Bs_ + (size_t)col0 * HIDDEN)
    };

    const int nChunk = HIDDEN / 32;

    const int lr = tid >> 2;
    const int lc = tid & 3;
    auto loadTile = [&](int t, int buf) {
        #pragma unroll
        for (int a = 0; a < 4; a++) {
            cpa16(base + buf * BUFB + a * ARR + lr * LDB + lc * 16,
                  src[a] + ((size_t)lr * HIDDEN + t * 32) * 2 + lc * 16);
        }
        cpa_commit();
    };

    float acch[2][4][4], accs[2][4][4];
    #pragma unroll
    for (int mi = 0; mi < 2; mi++)
        #pragma unroll
        for (int ni = 0; ni < 4; ni++)
            #pragma unroll
            for (int r = 0; r < 4; r++) { acch[mi][ni][r] = 0.f; accs[mi][ni][r] = 0.f; }

    const uint32_t aoffA = (uint32_t)((wr * 32 + (lane & 15)) * LDB + ((lane >> 4) << 3) * 2);
    const uint32_t aoffB = (uint32_t)((wc * 32 + ((lane >> 4) << 3) + (lane & 7)) * LDB
                                      + (((lane >> 3) & 1) << 3) * 2);

    loadTile(0, 0);

    for (int t = 0; t < nChunk; t++) {
        const int buf = t & 1;
        if (t + 1 < nChunk) { loadTile(t + 1, buf ^ 1); cpa_wait1(); }
        else                { cpa_wait0(); }
        __syncthreads();

        const uint32_t bo = base + buf * BUFB;

        #pragma unroll
        for (int ks = 0; ks < 2; ks++) {
            const uint32_t kb = (uint32_t)(ks * 32);

            uint32_t ah[2][4], as_[2][4];
            ldsm_x4(ah[0],  bo + 0 * ARR + aoffA + kb);
            ldsm_x4(ah[1],  bo + 0 * ARR + aoffA + kb + 16 * LDB);
            ldsm_x4(as_[0], bo + 1 * ARR + aoffA + kb);
            ldsm_x4(as_[1], bo + 1 * ARR + aoffA + kb + 16 * LDB);

            uint32_t bh[4][2], bs[4][2], tmp[4];
            ldsm_x4(tmp, bo + 2 * ARR + aoffB + kb);
            bh[0][0] = tmp[0]; bh[0][1] = tmp[1]; bh[1][0] = tmp[2]; bh[1][1] = tmp[3];
            ldsm_x4(tmp, bo + 2 * ARR + aoffB + kb + 16 * LDB);
            bh[2][0] = tmp[0]; bh[2][1] = tmp[1]; bh[3][0] = tmp[2]; bh[3][1] = tmp[3];
            ldsm_x4(tmp, bo + 3 * ARR + aoffB + kb);
            bs[0][0] = tmp[0]; bs[0][1] = tmp[1]; bs[1][0] = tmp[2]; bs[1][1] = tmp[3];
            ldsm_x4(tmp, bo + 3 * ARR + aoffB + kb + 16 * LDB);
            bs[2][0] = tmp[0]; bs[2][1] = tmp[1]; bs[3][0] = tmp[2]; bs[3][1] = tmp[3];

            #pragma unroll
            for (int mi = 0; mi < 2; mi++)
                #pragma unroll
                for (int ni = 0; ni < 4; ni++) {
                    mma_f16(acch[mi][ni], ah[mi],  bh[ni]);
                    mma_f16(accs[mi][ni], as_[mi], bs[ni]);
                }
        }
        __syncthreads();
    }

    #pragma unroll
    for (int mi = 0; mi < 2; mi++)
        #pragma unroll
        for (int ni = 0; ni < 4; ni++) {
            const int row = row0 + wr * 32 + mi * 16 + (lane >> 2);
            const int col = col0 + wc * 32 + ni * 8 + 2 * (lane & 3);
            float v0 = acch[mi][ni][0] + (accs[mi][ni][0] - acch[mi][ni][0]) * SPLIT_SINV;
            float v1 = acch[mi][ni][1] + (accs[mi][ni][1] - acch[mi][ni][1]) * SPLIT_SINV;
            float v2 = acch[mi][ni][2] + (accs[mi][ni][2] - acch[mi][ni][2]) * SPLIT_SINV;
            float v3 = acch[mi][ni][3] + (accs[mi][ni][3] - acch[mi][ni][3]) * SPLIT_SINV;
            *(float2*)(C + (size_t)row * N + col)       = make_float2(v0, v1);
            *(float2*)(C + (size_t)(row + 8) * N + col) = make_float2(v2, v3);
        }
}

// ============================================================================
// Plain fp16 GEMM (single MMA) — V-projection and O-projection
// ============================================================================
#define PLDB 144                 // 64 halfs + 16B pad
#define PARR (128 * PLDB)        // 18432
#define PBUF (2 * PARR)          // 36864
#define PGSM (2 * PBUF)          // 73728

__global__ __launch_bounds__(512) void gemm_plain(
    const __half* __restrict__ Ah_, const __half* __restrict__ Bh_,
    float* __restrict__ C, int N)
{
    extern __shared__ char dsm[];
    const uint32_t base = smem_u32(dsm);

    const int tid  = threadIdx.x;
    const int warp = tid >> 5, lane = tid & 31;
    const int wr = warp & 3, wc = warp >> 2;
    const int row0 = blockIdx.y * 128;
    const int col0 = blockIdx.x * 128;

    const char* srcA = (const char*)(Ah_ + (size_t)row0 * HIDDEN);
    const char* srcB = (const char*)(Bh_ + (size_t)col0 * HIDDEN);

    const int nChunk = HIDDEN / 64;    // 32

    auto loadTile = [&](int t, int buf) {
        #pragma unroll
        for (int i = 0; i < 2; i++) {
            int idx = tid + i * 512;        // 0..1023
            int r = idx >> 3, c = idx & 7;
            size_t go = ((size_t)r * HIDDEN + t * 64) * 2 + c * 16;
            cpa16(base + buf * PBUF + 0 * PARR + r * PLDB + c * 16, srcA + go);
            cpa16(base + buf * PBUF + 1 * PARR + r * PLDB + c * 16, srcB + go);
        }
        cpa_commit();
    };

    float acc[2][4][4];
    #pragma unroll
    for (int mi = 0; mi < 2; mi++)
        #pragma unroll
        for (int ni = 0; ni < 4; ni++)
            #pragma unroll
            for (int r = 0; r < 4; r++) acc[mi][ni][r] = 0.f;

    const uint32_t aoffA = (uint32_t)((wr * 32 + (lane & 15)) * PLDB + ((lane >> 4) << 4));
    const uint32_t aoffB = (uint32_t)((wc * 32 + ((lane >> 4) << 3) + (lane & 7)) * PLDB
                                      + (((lane >> 3) & 1) << 4));

    loadTile(0, 0);

    for (int t = 0; t < nChunk; t++) {
        const int buf = t & 1;
        if (t + 1 < nChunk) { loadTile(t + 1, buf ^ 1); cpa_wait1(); }
        else                { cpa_wait0(); }
        __syncthreads();

        const uint32_t bo = base + buf * PBUF;

        #pragma unroll
        for (int ks = 0; ks < 4; ks++) {
            const uint32_t kb = (uint32_t)(ks * 32);

            uint32_t ah[2][4];
            ldsm_x4(ah[0], bo + 0 * PARR + aoffA + kb);
            ldsm_x4(ah[1], bo + 0 * PARR + aoffA + kb + 16 * PLDB);

            uint32_t bh[4][2], tmp[4];
            ldsm_x4(tmp, bo + 1 * PARR + aoffB + kb);
            bh[0][0] = tmp[0]; bh[0][1] = tmp[1]; bh[1][0] = tmp[2]; bh[1][1] = tmp[3];
            ldsm_x4(tmp, bo + 1 * PARR + aoffB + kb + 16 * PLDB);
            bh[2][0] = tmp[0]; bh[2][1] = tmp[1]; bh[3][0] = tmp[2]; bh[3][1] = tmp[3];

            #pragma unroll
            for (int mi = 0; mi < 2; mi++)
                #pragma unroll
                for (int ni = 0; ni < 4; ni++)
                    mma_f16(acc[mi][ni], ah[mi], bh[ni]);
        }
        __syncthreads();
    }

    #pragma unroll
    for (int mi = 0; mi < 2; mi++)
        #pragma unroll
        for (int ni = 0; ni < 4; ni++) {
            const int row = row0 + wr * 32 + mi * 16 + (lane >> 2);
            const int col = col0 + wc * 32 + ni * 8 + 2 * (lane & 3);
            *(float2*)(C + (size_t)row * N + col)       = make_float2(acc[mi][ni][0], acc[mi][ni][1]);
            *(float2*)(C + (size_t)(row + 8) * N + col) = make_float2(acc[mi][ni][2], acc[mi][ni][3]);
        }
}

// ============================================================================
// Persistent MMA flash attention (causal, GQA) — all plain fp16 operands
// ============================================================================
#define ATT_BQ 128
#define ATT_BKV 64
#define ATT_GRID 148
#define N_ITEMS 512             // 16 qb x 16 h x 2 b
#define SQ_LDB 272              // 128 halfs + 16B pad
#define SV_LDB 144              // 64 halfs + 16B pad
#define KTILE_B 17408           // 64 * SQ_LDB
#define VTILE_B 18432           // 128 * SV_LDB
#define OFF_QH 0
#define OFF_K  34816            // + buf*KTILE_B
#define OFF_VT 69632            // + buf*VTILE_B
#define OFF_MSK 106496
#define ATT_SM 114688

__global__ __launch_bounds__(256) void attn_mma(
    const __half* __restrict__ qh, const __half* __restrict__ kh,
    const __half* __restrict__ vth,
    const int* __restrict__ amask,
    __half* __restrict__ aoh)
{
    extern __shared__ char sm[];
    const uint32_t base = smem_u32(sm);
    const int cta = blockIdx.x;
    const int tid = threadIdx.x, warp = tid >> 5, lane = tid & 31;
    const float scale = 0.08838834764831845f;

    const uint32_t aoffQ = (uint32_t)((warp * 16 + (lane & 15)) * SQ_LDB + ((lane >> 4) << 4));
    const uint32_t boffK = (uint32_t)(((lane >> 4) * 8 + (lane & 7)) * SQ_LDB + (((lane >> 3) & 1) << 4));
    const uint32_t boffV = (uint32_t)(((lane >> 4) * 8 + (lane & 7)) * SV_LDB + (((lane >> 3) & 1) << 4));
    const int* msk = (const int*)(sm + OFF_MSK);

    for (int p = 0; p < (N_ITEMS + ATT_GRID - 1) / ATT_GRID; p++) {
        const int w = p * ATT_GRID + ((p & 1) ? (ATT_GRID - 1 - cta) : cta);
        if (w >= N_ITEMS) continue;
        const int qb = 15 - (w >> 5);          // descending-qb order
        const int rem = w & 31;
        const int h = rem >> 1;
        const int b = rem & 1;
        const int kvh = h / (NH / NKV);
        const int bh = b * NKV + kvh;

        __syncthreads();   // previous item's smem consumers done

        // load Q tile
        {
            const size_t qrow0 = (size_t)(b * SEQ + qb * ATT_BQ);
            #pragma unroll
            for (int i = 0; i < 8; i++) {
                int id = tid + i * 256;
                int r = id >> 4, c = id & 15;
                cpa16(base + OFF_QH + r * SQ_LDB + c * 16,
                      qh + (qrow0 + r) * HIDDEN + (size_t)h * HD + c * 8);
            }
            cpa_commit();
        }
        const int mlen = (qb + 1) * ATT_BQ;
        for (int i = tid; i < mlen; i += 256)
            ((int*)(sm + OFF_MSK))[i] = amask[b * SEQ + i];

        const int nTiles = (qb + 1) * (ATT_BQ / ATT_BKV);   // (qb+1)*2

        auto loadKV = [&](int t, int buf) {
            const int kv0 = t * ATT_BKV;
            #pragma unroll
            for (int i = 0; i < 4; i++) {       // K: 64 rows x 16 chunks
                int id = tid + i * 256;
                int r = id >> 4, c = id & 15;
                cpa16(base + OFF_K + buf * KTILE_B + r * SQ_LDB + c * 16,
                      kh + (size_t)(b * SEQ + kv0 + r) * KVD + (size_t)kvh * HD + c * 8);
            }
            #pragma unroll
            for (int i = 0; i < 4; i++) {       // V: 128 rows x 8 chunks
                int id = tid + i * 256;
                int r = id >> 3, c = id & 7;
                cpa16(base + OFF_VT + buf * VTILE_B + r * SV_LDB + c * 16,
                      vth + (size_t)(bh * HD + r) * SEQ + kv0 + c * 8);
            }
            cpa_commit();
        };

        float O[16][4];
        #pragma unroll
        for (int i = 0; i < 16; i++)
            #pragma unroll
            for (int r = 0; r < 4; r++) O[i][r] = 0.f;
        float m0 = -1e30f, m1 = -1e30f, l0 = 0.f, l1 = 0.f;

        loadKV(0, 0);
        cpa_wait0();
        __syncthreads();

        const int rowg0 = qb * ATT_BQ + warp * 16 + (lane >> 2);
        const int rowg1 = rowg0 + 8;

        for (int t = 0; t < nTiles; t++) {
            const int buf = t & 1;
            const int kv0 = t * ATT_BKV;

            __syncthreads();
            if (t + 1 < nTiles) { loadKV(t + 1, buf ^ 1); cpa_wait1(); }
            else                { cpa_wait0(); }
            __syncthreads();

            const uint32_t kb_h = base + OFF_K + buf * KTILE_B;

            // ---- S = Q K^T (plain fp16) ----
            float sf[8][4];
            #pragma unroll
            for (int nt = 0; nt < 8; nt++)
                #pragma unroll
                for (int r = 0; r < 4; r++) sf[nt][r] = 0.f;

            #pragma unroll
            for (int ksI = 0; ksI < 8; ksI++) {
                uint32_t ah[4];
                ldsm_x4(ah, base + OFF_QH + aoffQ + ksI * 32);
                #pragma unroll
                for (int ntp = 0; ntp < 4; ntp++) {
                    uint32_t tmp[4];
                    ldsm_x4(tmp, kb_h + boffK + (uint32_t)(ntp * 16 * SQ_LDB) + ksI * 32);
                    uint32_t b0[2] = {tmp[0], tmp[1]}, b1[2] = {tmp[2], tmp[3]};
                    mma_f16(sf[ntp * 2],     ah, b0);
                    mma_f16(sf[ntp * 2 + 1], ah, b1);
                }
            }

            // scale + mask
            #pragma unroll
            for (int nt = 0; nt < 8; nt++)
                #pragma unroll
                for (int r = 0; r < 4; r++) {
                    float s = sf[nt][r] * scale;
                    int col = kv0 + nt * 8 + 2 * (lane & 3) + (r & 1);
                    int row = (r < 2) ? rowg0 : rowg1;
                    if (col > row || msk[col] == 0) s = -1e30f;
                    sf[nt][r] = s;
                }

            // online softmax over 64 columns
            float mx0 = m0, mx1 = m1;
            #pragma unroll
            for (int nt = 0; nt < 8; nt++) {
                mx0 = fmaxf(mx0, fmaxf(sf[nt][0], sf[nt][1]));
                mx1 = fmaxf(mx1, fmaxf(sf[nt][2], sf[nt][3]));
            }
            mx0 = fmaxf(mx0, __shfl_xor_sync(0xffffffffu, mx0, 1));
            mx0 = fmaxf(mx0, __shfl_xor_sync(0xffffffffu, mx0, 2));
            mx1 = fmaxf(mx1, __shfl_xor_sync(0xffffffffu, mx1, 1));
            mx1 = fmaxf(mx1, __shfl_xor_sync(0xffffffffu, mx1, 2));

            float sum0 = 0.f, sum1 = 0.f;
            #pragma unroll
            for (int nt = 0; nt < 8; nt++) {
                sf[nt][0] = __expf(sf[nt][0] - mx0);
                sf[nt][1] = __expf(sf[nt][1] - mx0);
                sf[nt][2] = __expf(sf[nt][2] - mx1);
                sf[nt][3] = __expf(sf[nt][3] - mx1);
                sum0 += sf[nt][0] + sf[nt][1];
                sum1 += sf[nt][2] + sf[nt][3];
            }
            sum0 += __shfl_xor_sync(0xffffffffu, sum0, 1);
            sum0 += __shfl_xor_sync(0xffffffffu, sum0, 2);
            sum1 += __shfl_xor_sync(0xffffffffu, sum1, 1);
            sum1 += __shfl_xor_sync(0xffffffffu, sum1, 2);

            float a0 = __expf(m0 - mx0), a1 = __expf(m1 - mx1);
            l0 = l0 * a0 + sum0;
            l1 = l1 * a1 + sum1;
            m0 = mx0; m1 = mx1;

            #pragma unroll
            for (int i = 0; i < 16; i++) {
                O[i][0] *= a0; O[i][1] *= a0;
                O[i][2] *= a1; O[i][3] *= a1;
            }

            // P fragments (plain fp16): 4 k16 groups over 64 columns
            uint32_t pH[4][4];
            #pragma unroll
            for (int g = 0; g < 4; g++) {
                int t0 = g * 2, t1 = t0 + 1;
                pH[g][0] = packh2(sf[t0][0], sf[t0][1]);
                pH[g][1] = packh2(sf[t0][2], sf[t0][3]);
                pH[g][2] = packh2(sf[t1][0], sf[t1][1]);
                pH[g][3] = packh2(sf[t1][2], sf[t1][3]);
            }

            // ---- O += P V (plain fp16, direct accumulate) ----
            const uint32_t vb = base + OFF_VT + buf * VTILE_B;
            #pragma unroll
            for (int ntp = 0; ntp < 8; ntp++) {
                #pragma unroll
                for (int g = 0; g < 4; g++) {
                    uint32_t tmp[4];
                    ldsm_x4(tmp, vb + boffV + ntp * 16 * SV_LDB + g * 32);
                    uint32_t b0[2] = {tmp[0], tmp[1]}, b1[2] = {tmp[2], tmp[3]};
                    mma_f16(O[ntp * 2],     pH[g], b0);
                    mma_f16(O[ntp * 2 + 1], pH[g], b1);
                }
            }
        }

        // epilogue: normalize + plain fp16 output
        const float il0 = 1.f / l0, il1 = 1.f / l1;
        #pragma unroll
        for (int nt = 0; nt < 16; nt++) {
            int col = h * HD + nt * 8 + 2 * (lane & 3);
            size_t o0 = (size_t)(b * SEQ + rowg0) * HIDDEN + col;
            size_t o1 = (size_t)(b * SEQ + rowg1) * HIDDEN + col;
            *(uint32_t*)(aoh + o0) = packh2(O[nt][0] * il0, O[nt][1] * il0);
            *(uint32_t*)(aoh + o1) = packh2(O[nt][2] * il1, O[nt][3] * il1);
        }
    }
}

// ---------------- launch ----------------------------------------------------
extern "C" void kernel_launch(void* const* d_in, const int* in_sizes, int n_in,
                              void* d_out, int out_size)
{
    const float* hs    = (const float*)d_in[0];
    const int*   amask = (const int*)  d_in[1];
    const float* wq    = (const float*)d_in[2];
    const float* wk    = (const float*)d_in[3];
    const float* wv    = (const float*)d_in[4];
    const float* wo    = (const float*)d_in[5];
    float* out = (float*)d_out;

    float *qk, *dv;
    cudaGetSymbolAddress((void**)&qk, g_qk);
    cudaGetSymbolAddress((void**)&dv, g_v);

    __half *hsh, *hss, *wqkh, *wqks, *wvh, *woh, *aoh;
    cudaGetSymbolAddress((void**)&hsh,  g_hsh);  cudaGetSymbolAddress((void**)&hss,  g_hss);
    cudaGetSymbolAddress((void**)&wqkh, g_wqkh); cudaGetSymbolAddress((void**)&wqks, g_wqks);
    cudaGetSymbolAddress((void**)&wvh,  g_wvh);
    cudaGetSymbolAddress((void**)&woh,  g_woh);
    cudaGetSymbolAddress((void**)&aoh,  g_aoh);

    __half *qh, *kh, *vth;
    cudaGetSymbolAddress((void**)&qh,  g_qh);
    cudaGetSymbolAddress((void**)&kh,  g_kh);
    cudaGetSymbolAddress((void**)&vth, g_vth);

    cudaFuncSetAttribute(gemm_fp16x2, cudaFuncAttributeMaxDynamicSharedMemorySize, GSM);
    cudaFuncSetAttribute(gemm_plain,  cudaFuncAttributeMaxDynamicSharedMemorySize, PGSM);
    cudaFuncSetAttribute(attn_mma,    cudaFuncAttributeMaxDynamicSharedMemorySize, ATT_SM);

    // one fused split for all inputs
    split_all<<<2048, 256>>>(hs, wq, wk, wv, wo, hsh, hss, wqkh, wqks, wvh, woh);

    // merged Q|K projection (2-MMA corrected) + V projection (plain fp16)
    gemm_fp16x2<<<dim3(QKOUT / 128, MTOT / 128), 512, GSM>>>(hsh, hss, wqkh, wqks, qk, QKOUT);
    gemm_plain <<<dim3(KVD   / 128, MTOT / 128), 512, PGSM>>>(hsh, wvh, dv, KVD);

    // fused RoPE (plain fp16 q/k) and V transpose (plain fp16)
    rope_plain<<<MTOT / 4, 256>>>(qk, qh, kh);
    transpose_v<<<dim3(SEQ / 32, HD / 32, BATCH * NKV), dim3(32, 8)>>>(dv, vth);

    // persistent MMA flash attention (all plain fp16; writes plain fp16)
    attn_mma<<<ATT_GRID, 256, ATT_SM>>>(qh, kh, vth, amask, aoh);

    // O-projection: plain fp16 single-MMA (final stage)
    gemm_plain<<<dim3(HIDDEN / 128, MTOT / 128), 512, PGSM>>>(aoh, woh, out, HIDDEN);
}